// round 10
// baseline (speedup 1.0000x reference)
#include <cuda_runtime.h>
#include <cuda_bf16.h>
#include <cstdint>

#define Bb 16
#define Cc 128
#define Nn 2048
#define CO 256
#define KK 20
#define KL 12
#define CNT ((double)(Bb) * (double)(Nn) * (double)(KK))
#define BIGF 1e30f

// ---------------- scratch -----------------------------------------------------
__device__ float          g_sq[Bb * Nn];
__device__ int            g_knn[Bb * Nn * KK];
__device__ __nv_bfloat16  g_xh[(size_t)Bb * Nn * Cc];          // x transposed [b][n][c], hi
__device__ __nv_bfloat16  g_xl[(size_t)Bb * Nn * Cc];          // lo
__device__ __nv_bfloat16  g_Wch[(size_t)2 * CO * Cc];          // Wc [j][c] hi (j<256: W1-W2, else W2)
__device__ __nv_bfloat16  g_Wcl[(size_t)2 * CO * Cc];          // lo
__device__ float          g_uv[(size_t)Bb * Nn * 2 * CO];      // [b][n][0..255]=u, [256..511]=v
__device__ float          g_ymax[(size_t)Bb * Nn * CO];
__device__ float          g_ymin[(size_t)Bb * Nn * CO];
__device__ double         g_sum[CO];
__device__ double         g_sumsq[CO];
__device__ float          g_scale[CO];
__device__ float          g_shift[CO];
__device__ int            g_nfb;
__device__ int            g_fbrow[Bb * Nn];

// ---------------- helpers -----------------------------------------------------
__device__ __forceinline__ uint32_t smem_u32(const void* p) {
    uint32_t a;
    asm("{ .reg .u64 t; cvta.to.shared.u64 t, %1; cvt.u32.u64 %0, t; }" : "=r"(a) : "l"(p));
    return a;
}
__device__ __forceinline__ void ldsm4(uint32_t* r, uint32_t addr) {
    asm volatile("ldmatrix.sync.aligned.m8n8.x4.shared.b16 {%0,%1,%2,%3}, [%4];"
        : "=r"(r[0]), "=r"(r[1]), "=r"(r[2]), "=r"(r[3]) : "r"(addr));
}
__device__ __forceinline__ void mma16816(float* d, const uint32_t* a, uint32_t b0, uint32_t b1) {
    asm volatile("mma.sync.aligned.m16n8k16.row.col.f32.bf16.bf16.f32 "
        "{%0,%1,%2,%3}, {%4,%5,%6,%7}, {%8,%9}, {%0,%1,%2,%3};"
        : "+f"(d[0]), "+f"(d[1]), "+f"(d[2]), "+f"(d[3])
        : "r"(a[0]), "r"(a[1]), "r"(a[2]), "r"(a[3]), "r"(b0), "r"(b1));
}
#define CP16(dst, src) asm volatile("cp.async.cg.shared.global [%0], [%1], 16;" :: "r"(dst), "l"(src))
#define CP_COMMIT()    asm volatile("cp.async.commit_group;" ::: "memory")
#define CP_WAIT0()     asm volatile("cp.async.wait_group 0;" ::: "memory")

// padded smem tile: rows x 128 bf16, row stride 272 bytes (conflict-free ldmatrix)
#define LDB   272
#define TILEB (128 * LDB)          // 34816
#define TILEB64 (64 * LDB)         // 17408

// ---- uv kernel smem layout ----
#define SM_AH 0
#define SM_AL TILEB
#define SM_BH (2 * TILEB)
#define SM_BL (3 * TILEB)
#define SM_DYN (4 * TILEB + 1024)  // 140288

// ---- fused dist+knn smem layout (2 CTAs/SM) ----
#define F2_AH 0
#define F2_AL TILEB
#define F2_BH (2 * TILEB)                 // 69632
#define F2_BL (2 * TILEB + TILEB64)       // 87040
#define F2_SQ (2 * TILEB + 2 * TILEB64)   // 104448
#define F2_DYN (F2_SQ + 8192)             // 112640

// ---- gather smem: v slice + staged knn indices (128-n tile) ----
#define GCH 16
#define GNT 128
#define G_SV   0
#define G_SIDX (Nn * GCH * 4)             // 131072
#define G_DYN  (G_SIDX + GNT * KK * 4)    // 141312

__device__ __forceinline__ void load_tile_pad(const __nv_bfloat16* __restrict__ src,
                                              char* sm, int tid) {
#pragma unroll
    for (int it = 0; it < 8; it++) {
        int idx = it * 256 + tid;
        int row = idx >> 4, seg = idx & 15;
        uint4 v = *(const uint4*)(src + (size_t)row * 128 + seg * 8);
        *(uint4*)(sm + row * LDB + seg * 16) = v;
    }
}
__device__ __forceinline__ void tile_async(const __nv_bfloat16* __restrict__ src,
                                           uint32_t smbase, int tid) {
#pragma unroll
    for (int it = 0; it < 8; it++) {
        int idx = it * 256 + tid;
        int row = idx >> 4, seg = idx & 15;
        CP16(smbase + row * LDB + seg * 16, src + (size_t)row * 128 + seg * 8);
    }
}
__device__ __forceinline__ void tile_async64(const __nv_bfloat16* __restrict__ src,
                                             uint32_t smbase, int tid) {
#pragma unroll
    for (int it = 0; it < 4; it++) {
        int idx = it * 256 + tid;          // 1024 = 64 rows x 16 segs
        int row = idx >> 4, seg = idx & 15;
        CP16(smbase + row * LDB + seg * 16, src + (size_t)row * 128 + seg * 8);
    }
}

// key = (monotone-uint(dist) << 32) | index: lexicographic (dist, idx)
__device__ __forceinline__ uint64_t pd_key(float d, int m) {
    uint32_t b = __float_as_uint(d);
    b ^= ((uint32_t)((int32_t)b >> 31)) | 0x80000000u;
    return ((uint64_t)b << 32) | (uint32_t)m;
}

// paired insert: insert (da,ia),(db,ib) into sorted KL-list in ONE chain pass.
// Values > T are skippable (row-20th <= T proven by quad bound); keep == T.
__device__ __forceinline__ void insert2(float (&bd)[KL], int (&bi)[KL],
                                        float da, int ia, float db, int ib, float T) {
    {
        bool sw = db < da;
        float td = sw ? db : da;  int ti = sw ? ib : ia;
        db = sw ? da : db;        ib = sw ? ia : ib;
        da = td;                  ia = ti;
    }
    if (da < bd[KL - 1] && da <= T) {
#pragma unroll
        for (int i = 0; i < KL; i++) {
            bool lt = da < bd[i];
            float sv = lt ? da : bd[i];
            int   si = lt ? ia : bi[i];
            float c1 = lt ? bd[i] : da;       // displaced candidate
            int   ci = lt ? bi[i] : ia;
            bd[i] = sv; bi[i] = si;
            bool sw = db < c1;                // keep carried pair ordered
            da = sw ? db : c1;  ia = sw ? ib : ci;
            db = sw ? c1 : db;  ib = sw ? ci : ib;
        }
    }
}

// merge one row's 4 per-thread sorted lists (quad of lanes) -> top-20 to g_knn
__device__ __forceinline__ int quad_merge(float (&bd)[KL], int (&bi)[KL],
                                          int lane, int nglob) {
    uint64_t cur = pd_key(bd[0], bi[0]);
    int p = 0;
#pragma unroll 1
    for (int s = 0; s < KK; s++) {
        uint64_t v = cur;
        uint64_t o2 = __shfl_down_sync(0xffffffffu, v, 2, 4); v = o2 < v ? o2 : v;
        uint64_t o1 = __shfl_down_sync(0xffffffffu, v, 1, 4); v = o1 < v ? o1 : v;
        v = __shfl_sync(0xffffffffu, v, 0, 4);
        if ((lane & 3) == 0) g_knn[nglob * KK + s] = (int)(uint32_t)v;
        if (cur == v) {
            p++;
#pragma unroll
            for (int i = 0; i < KL - 1; i++) { bd[i] = bd[i + 1]; bi[i] = bi[i + 1]; }
            bd[KL - 1] = BIGF; bi[KL - 1] = 0x7fffffff;
            cur = pd_key(bd[0], bi[0]);
        }
    }
    return p >= KL ? 1 : 0;
}

// ---------------- prep: weights (folded + split) + zero accumulators ----------
__global__ void k_prep(const float* __restrict__ W) {
    int tid = blockIdx.x * blockDim.x + threadIdx.x;     // 65536
    int j = tid >> 7, c = tid & 127;
    float w;
    if (j < CO) w = W[j * (2 * Cc) + c] - W[j * (2 * Cc) + Cc + c];
    else        w = W[(j - CO) * (2 * Cc) + Cc + c];
    __nv_bfloat16 hi = __float2bfloat16(w);
    g_Wch[tid] = hi;
    g_Wcl[tid] = __float2bfloat16(w - __bfloat162float(hi));
    if (tid < CO) { g_sum[tid] = 0.0; g_sumsq[tid] = 0.0; }
    if (tid == 0) g_nfb = 0;
}

// ---------------- squared norms ------------------------------------------------
__global__ void k_sq(const float* __restrict__ x) {
    int i = blockIdx.x * 256 + threadIdx.x;
    int b = i >> 11, n = i & (Nn - 1);
    const float* xb = x + (size_t)b * Cc * Nn;
    float s = 0.f;
#pragma unroll 8
    for (int c = 0; c < Cc; c++) {
        float v = xb[(size_t)c * Nn + n];
        s = fmaf(v, v, s);
    }
    g_sq[i] = s;
}

// ---------------- transpose x -> [b][n][c] + bf16 hi/lo split -------------------
__global__ void k_split(const float* __restrict__ x) {
    __shared__ float t[32][33];
    int b = blockIdx.z, c0 = blockIdx.y * 32, n0 = blockIdx.x * 32;
    int tx = threadIdx.x, ty = threadIdx.y;
    const float* xb = x + ((size_t)b * Cc + c0) * Nn + n0;
    for (int i = ty; i < 32; i += 8)
        t[i][tx] = xb[(size_t)i * Nn + tx];
    __syncthreads();
    for (int i = ty; i < 32; i += 8) {
        float v = t[tx][i];
        __nv_bfloat16 hi = __float2bfloat16(v);
        float lo = v - __bfloat162float(hi);
        size_t o = ((size_t)b * Nn + n0 + i) * Cc + c0 + tx;
        g_xh[o] = hi;
        g_xl[o] = __float2bfloat16(lo);
    }
}

// ---------------- fused distance GEMM + top-k (2 CTAs/SM, 64-row B tiles) -------
__global__ __launch_bounds__(256, 2) void k_distknn() {
    extern __shared__ char sm[];
    uint32_t sb = smem_u32(sm);
    int tid = threadIdx.x, wid = tid >> 5, lane = tid & 31;
    int strip = blockIdx.x, b = blockIdx.y;
    int n0 = strip * 128;
    const __nv_bfloat16* xh = g_xh + ((size_t)b << 11) * Cc;
    const __nv_bfloat16* xl = g_xl + ((size_t)b << 11) * Cc;
    float* s_sqm = (float*)(sm + F2_SQ);

    {
        const float4* src = (const float4*)(g_sq + (b << 11));
        float4* dst = (float4*)s_sqm;
        for (int i = tid; i < 512; i += 256) dst[i] = src[i];
    }
    tile_async(xh + (size_t)n0 * Cc, sb + F2_AH, tid);
    tile_async(xl + (size_t)n0 * Cc, sb + F2_AL, tid);
    tile_async64(xh, sb + F2_BH, tid);
    tile_async64(xl, sb + F2_BL, tid);
    CP_COMMIT();
    CP_WAIT0();
    __syncthreads();

    int rw = wid * 16, r0 = lane >> 2, q = (lane & 3) * 2;
    float acc[8][4];
#pragma unroll
    for (int g = 0; g < 8; g++)
#pragma unroll
        for (int i = 0; i < 4; i++) acc[g][i] = 0.f;

    float bd0[KL], bd1[KL];
    int   bi0[KL], bi1[KL];
#pragma unroll
    for (int i = 0; i < KL; i++) { bd0[i] = BIGF; bd1[i] = BIGF; bi0[i] = 0x7fffffff; bi1[i] = 0x7fffffff; }
    float T0 = BIGF, T1 = BIGF;

    float sn0 = s_sqm[n0 + rw + r0];
    float sn1 = s_sqm[n0 + rw + r0 + 8];
    uint32_t aoff = (uint32_t)((rw + (lane & 15)) * LDB + (lane >> 4) * 16);
    uint32_t boff = (uint32_t)(((lane & 7) + ((lane >> 4) << 3)) * LDB + ((lane >> 3) & 1) * 16);
    uint32_t a_hi = sb + F2_AH, a_lo = sb + F2_AL;
    uint32_t b_hi = sb + F2_BH, b_lo = sb + F2_BL;

#pragma unroll 1
    for (int t = 0; t < 32; t++) {
#pragma unroll
        for (int ks = 0; ks < 8; ks++) {
            uint32_t kb = ks * 32;
            uint32_t ah[4], al[4];
            ldsm4(ah, a_hi + aoff + kb);
            ldsm4(al, a_lo + aoff + kb);
#pragma unroll
            for (int g = 0; g < 4; g++) {
                uint32_t bo = boff + g * (16 * LDB) + kb;
                uint32_t bhx[4], blx[4];
                ldsm4(bhx, b_hi + bo);
                ldsm4(blx, b_lo + bo);
                mma16816(acc[2 * g],     ah, bhx[0], bhx[1]);
                mma16816(acc[2 * g],     ah, blx[0], blx[1]);
                mma16816(acc[2 * g],     al, bhx[0], bhx[1]);
                mma16816(acc[2 * g + 1], ah, bhx[2], bhx[3]);
                mma16816(acc[2 * g + 1], ah, blx[2], blx[3]);
                mma16816(acc[2 * g + 1], al, bhx[2], bhx[3]);
            }
        }
        __syncthreads();                    // all warps done reading B tile t
        if (t < 31) {                       // overwrite B with tile t+1 (async)
            tile_async64(xh + (size_t)(t + 1) * 64 * Cc, b_hi, tid);
            tile_async64(xl + (size_t)(t + 1) * 64 * Cc, b_lo, tid);
            CP_COMMIT();
        }

        // epilogue (overlaps the async loads): d = sqn + sqm - 2*acc; inserts
        int m0 = t * 64;
#pragma unroll
        for (int g = 0; g < 8; g++) {
            int mm = m0 + g * 8 + q;
            float sm0v = s_sqm[mm], sm1v = s_sqm[mm + 1];
            float d00 = fmaf(-2.f, acc[g][0], sn0 + sm0v);
            float d01 = fmaf(-2.f, acc[g][1], sn0 + sm1v);
            float d10 = fmaf(-2.f, acc[g][2], sn1 + sm0v);
            float d11 = fmaf(-2.f, acc[g][3], sn1 + sm1v);
            insert2(bd0, bi0, d00, mm, d01, mm + 1, T0);
            insert2(bd1, bi1, d10, mm, d11, mm + 1, T1);
            acc[g][0] = acc[g][1] = acc[g][2] = acc[g][3] = 0.f;
        }
        // quad threshold: T = max over quad of bd[4]; >=20 union values <= T
        {
            float t0 = bd0[4];
            t0 = fmaxf(t0, __shfl_xor_sync(0xffffffffu, t0, 1, 4));
            t0 = fmaxf(t0, __shfl_xor_sync(0xffffffffu, t0, 2, 4));
            T0 = t0;
            float t1 = bd1[4];
            t1 = fmaxf(t1, __shfl_xor_sync(0xffffffffu, t1, 1, 4));
            t1 = fmaxf(t1, __shfl_xor_sync(0xffffffffu, t1, 2, 4));
            T1 = t1;
        }
        if (t < 31) {
            CP_WAIT0();
            __syncthreads();
        }
    }

    // merge quads -> g_knn; flag exhausted rows for exact redo
    int nbase = (b << 11) + n0 + rw;
    int bad0 = quad_merge(bd0, bi0, lane, nbase + r0);
    int bad1 = quad_merge(bd1, bi1, lane, nbase + r0 + 8);
    unsigned bm0 = __ballot_sync(0xffffffffu, bad0 != 0);
    unsigned bm1 = __ballot_sync(0xffffffffu, bad1 != 0);
    if ((lane & 3) == 0) {
        if ((bm0 >> lane) & 0xFu) { int s = atomicAdd(&g_nfb, 1); g_fbrow[s] = nbase + r0; }
        if ((bm1 >> lane) & 0xFu) { int s = atomicAdd(&g_nfb, 1); g_fbrow[s] = nbase + r0 + 8; }
    }
}

// ---------------- cleanup: exact fp32 top-20 for flagged rows (coalesced) -------
__global__ __launch_bounds__(256) void k_fix() {
    __shared__ float xn[Cc];
    __shared__ float sd[Nn];
    int nfb = g_nfb;
    int wid = threadIdx.x >> 5, lane = threadIdx.x & 31;
    for (int i = blockIdx.x; i < nfb; i += gridDim.x) {
        int rowid = g_fbrow[i];
        int b = rowid >> 11, n = rowid & (Nn - 1);
        const __nv_bfloat16* xh = g_xh + ((size_t)b << 11) * Cc;
        const __nv_bfloat16* xl = g_xl + ((size_t)b << 11) * Cc;
        if (threadIdx.x < Cc)
            xn[threadIdx.x] = __bfloat162float(xh[(size_t)n * Cc + threadIdx.x])
                            + __bfloat162float(xl[(size_t)n * Cc + threadIdx.x]);
        __syncthreads();
        float sqn = g_sq[(b << 11) + n];
        for (int m = wid; m < Nn; m += 8) {
            const __nv_bfloat162* rh = (const __nv_bfloat162*)(xh + (size_t)m * Cc);
            const __nv_bfloat162* rl = (const __nv_bfloat162*)(xl + (size_t)m * Cc);
            __nv_bfloat162 h0 = rh[lane * 2], h1 = rh[lane * 2 + 1];
            __nv_bfloat162 l0 = rl[lane * 2], l1 = rl[lane * 2 + 1];
            int c0 = lane * 4;
            float dot = xn[c0]     * (__bfloat162float(h0.x) + __bfloat162float(l0.x));
            dot = fmaf(xn[c0 + 1], (__bfloat162float(h0.y) + __bfloat162float(l0.y)), dot);
            dot = fmaf(xn[c0 + 2], (__bfloat162float(h1.x) + __bfloat162float(l1.x)), dot);
            dot = fmaf(xn[c0 + 3], (__bfloat162float(h1.y) + __bfloat162float(l1.y)), dot);
#pragma unroll
            for (int off = 16; off; off >>= 1)
                dot += __shfl_down_sync(0xffffffffu, dot, off);
            if (lane == 0)
                sd[m] = fmaf(-2.f, dot, sqn + g_sq[(b << 11) + m]);
        }
        __syncthreads();
        if (threadIdx.x < 32) {
            uint64_t best[KK];
#pragma unroll
            for (int ii = 0; ii < KK; ii++) best[ii] = ~0ull;
#pragma unroll 1
            for (int t = 0; t < Nn / 32; t++) {
                int m = t * 32 + lane;
                uint64_t key = pd_key(sd[m], m);
                if (key < best[KK - 1]) {
#pragma unroll
                    for (int ii = 0; ii < KK; ii++) {
                        uint64_t bv = best[ii];
                        uint64_t lo = (key < bv) ? key : bv;
                        key          = (key < bv) ? bv : key;
                        best[ii] = lo;
                    }
                }
            }
            int p = 0;
            uint64_t cur = best[0];
#pragma unroll 1
            for (int s = 0; s < KK; s++) {
                uint64_t v = cur;
#pragma unroll
                for (int off = 16; off; off >>= 1) {
                    uint64_t ov = __shfl_down_sync(0xffffffffu, v, off);
                    v = (ov < v) ? ov : v;
                }
                v = __shfl_sync(0xffffffffu, v, 0);
                if (lane == 0) g_knn[((b << 11) + n) * KK + s] = (int)(uint32_t)v;
                if (cur == v) { p++; cur = (p < KK) ? best[p] : ~0ull; }
            }
        }
        __syncthreads();
    }
}

// ---------------- uv GEMM via mma.sync: uv[b][n][j] = x[n,:].Wc[j,:] ------------
__device__ __forceinline__ void gemm_main(uint32_t sb, int lane, int wy, int wx,
                                          float acc[4][4][4]) {
    uint32_t a_hi = sb + SM_AH, a_lo = sb + SM_AL;
    uint32_t b_hi = sb + SM_BH, b_lo = sb + SM_BL;
    uint32_t aoff = (uint32_t)((wy * 64 + (lane & 15)) * LDB + (lane >> 4) * 16);
    uint32_t boff = (uint32_t)((wx * 32 + (lane & 7) + (lane >> 4) * 8) * LDB
                               + ((lane >> 3) & 1) * 16);
#pragma unroll
    for (int ks = 0; ks < 8; ks++) {
        uint32_t kb = ks * 32;
        uint32_t ah[4][4], al[4][4], bh[2][4], bl[2][4];
#pragma unroll
        for (int c = 0; c < 4; c++) {
            ldsm4(ah[c], a_hi + aoff + c * (16 * LDB) + kb);
            ldsm4(al[c], a_lo + aoff + c * (16 * LDB) + kb);
        }
#pragma unroll
        for (int d = 0; d < 2; d++) {
            ldsm4(bh[d], b_hi + boff + d * (16 * LDB) + kb);
            ldsm4(bl[d], b_lo + boff + d * (16 * LDB) + kb);
        }
#pragma unroll
        for (int c = 0; c < 4; c++)
#pragma unroll
            for (int f = 0; f < 4; f++) {
                int d = f >> 1, h = (f & 1) * 2;
                mma16816(acc[c][f], ah[c], bh[d][h], bh[d][h + 1]);
                mma16816(acc[c][f], ah[c], bl[d][h], bl[d][h + 1]);
                mma16816(acc[c][f], al[c], bh[d][h], bh[d][h + 1]);
            }
    }
}

__global__ __launch_bounds__(256) void k_uv_mma() {
    extern __shared__ char sm[];
    uint32_t sb = smem_u32(sm);
    int tid = threadIdx.x, wid = tid >> 5, lane = tid & 31;
    int b = blockIdx.z, n0 = blockIdx.y * 128, j0 = blockIdx.x * 128;

    const __nv_bfloat16* xh = g_xh + ((size_t)(b << 11) + n0) * Cc;
    const __nv_bfloat16* xl = g_xl + ((size_t)(b << 11) + n0) * Cc;
    load_tile_pad(xh, sm + SM_AH, tid);
    load_tile_pad(xl, sm + SM_AL, tid);
    load_tile_pad(g_Wch + (size_t)j0 * Cc, sm + SM_BH, tid);
    load_tile_pad(g_Wcl + (size_t)j0 * Cc, sm + SM_BL, tid);
    __syncthreads();

    int wy = wid >> 2, wx = wid & 3;
    float acc[4][4][4];
#pragma unroll
    for (int c = 0; c < 4; c++)
#pragma unroll
        for (int f = 0; f < 4; f++)
#pragma unroll
            for (int i = 0; i < 4; i++) acc[c][f][i] = 0.f;

    gemm_main(sb, lane, wy, wx, acc);

    float* uvb = g_uv + (size_t)(b << 11) * (2 * CO);
    int r = lane >> 2, q = (lane & 3) * 2;
#pragma unroll
    for (int c = 0; c < 4; c++)
#pragma unroll
        for (int f = 0; f < 4; f++) {
            int nn = wy * 64 + c * 16 + r;
            int jj = wx * 32 + f * 8 + q;
            float2 v0, v1;
            v0.x = acc[c][f][0]; v0.y = acc[c][f][1];
            v1.x = acc[c][f][2]; v1.y = acc[c][f][3];
            *(float2*)&uvb[(size_t)(n0 + nn) * (2 * CO) + j0 + jj] = v0;
            *(float2*)&uvb[(size_t)(n0 + nn + 8) * (2 * CO) + j0 + jj] = v1;
        }
}

// ---------------- gather: smem v slice + smem-staged knn indices ----------------
__global__ __launch_bounds__(256) void k_gather() {
    extern __shared__ char sm[];
    float* sv  = (float*)(sm + G_SV);             // [Nn][GCH]
    int* sidx  = (int*)(sm + G_SIDX);             // [GNT][KK]
    int b = blockIdx.y, o0 = blockIdx.x * GCH;
    int tid = threadIdx.x;
    const float* uvb = g_uv + (size_t)b * Nn * (2 * CO);

    // stage v slice: v[m][o0..o0+15] -> sv[m][0..15]
    {
        int ch = tid & 15, mr = tid >> 4;         // 16 m-rows x 16 ch per iter
        for (int m0 = 0; m0 < Nn; m0 += 16) {
            int m = m0 + mr;
            sv[m * GCH + ch] = uvb[(size_t)m * (2 * CO) + CO + o0 + ch];
        }
    }

    int ch = tid & 15, g = tid >> 4;              // 16 groups x 16 channels
    float s = 0.f, s2 = 0.f;
#pragma unroll 1
    for (int nt = 0; nt < Nn; nt += GNT) {
        __syncthreads();                          // prev tile consumers done (and sv on first iter)
        // stage indices for n in [nt, nt+GNT): coalesced 2560-int copy
        for (int i = tid; i < GNT * KK; i += 256)
            sidx[i] = g_knn[((b << 11) + nt) * KK + i];
        __syncthreads();

#pragma unroll 1
        for (int ni = 0; ni < GNT / 16; ni++) {   // group g handles n = nt + ni*16 + g
            int nl = ni * 16 + g;
            int n = nt + nl;
            float uo = uvb[(size_t)n * (2 * CO) + o0 + ch];
            const int* kp = sidx + nl * KK;
            float mx = -BIGF, mn = BIGF;
#pragma unroll
            for (int j = 0; j < KK; j++) {
                float y = uo + sv[kp[j] * GCH + ch];
                s += y;
                s2 = fmaf(y, y, s2);
                mx = fmaxf(mx, y);
                mn = fminf(mn, y);
            }
            size_t base = ((size_t)(b << 11) + n) * CO + o0 + ch;
            g_ymax[base] = mx;
            g_ymin[base] = mn;
        }
    }
    atomicAdd(&g_sum[o0 + ch], (double)s);
    atomicAdd(&g_sumsq[o0 + ch], (double)s2);
}

// ---------------- finalize BN stats ---------------------------------------------
__global__ void k_final(const float* __restrict__ gamma, const float* __restrict__ beta) {
    int o = threadIdx.x;
    double mean = g_sum[o] / CNT;
    double var = g_sumsq[o] / CNT - mean * mean;
    double inv = 1.0 / sqrt(var + 1e-5);
    float sc = (float)((double)gamma[o] * inv);
    g_scale[o] = sc;
    g_shift[o] = beta[o] - (float)(mean * (double)gamma[o] * inv);
}

// ---------------- output: affine + relu + transpose ------------------------------
__global__ void k_out(float* __restrict__ out) {
    __shared__ float tile[32][33];
    int b = blockIdx.z, o0 = blockIdx.y * 32, n0 = blockIdx.x * 32;
    int tx = threadIdx.x, ty = threadIdx.y;

    for (int i = ty; i < 32; i += 8) {
        int n = n0 + i;
        int o = o0 + tx;
        float sc = g_scale[o];
        size_t base = ((size_t)(b << 11) + n) * CO + o;
        float v;
        if (sc >= 0.f) v = g_ymax[base];
        else           v = g_ymin[base];
        float r = fmaf(sc, v, g_shift[o]);
        tile[i][tx] = fmaxf(r, 0.f);
    }
    __syncthreads();
    for (int i = ty; i < 32; i += 8) {
        int o = o0 + i;
        int n = n0 + tx;
        out[((size_t)b * CO + o) * Nn + n] = tile[tx][i];
    }
}

// ---------------- launch ----------------------------------------------------------
extern "C" void kernel_launch(void* const* d_in, const int* in_sizes, int n_in,
                              void* d_out, int out_size) {
    const float* x     = (const float*)d_in[0];
    const float* W     = (const float*)d_in[1];
    const float* gamma = (const float*)d_in[2];
    const float* beta  = (const float*)d_in[3];
    float* out = (float*)d_out;

    cudaFuncSetAttribute(k_distknn, cudaFuncAttributeMaxDynamicSharedMemorySize, F2_DYN);
    cudaFuncSetAttribute(k_uv_mma,  cudaFuncAttributeMaxDynamicSharedMemorySize, SM_DYN);
    cudaFuncSetAttribute(k_gather,  cudaFuncAttributeMaxDynamicSharedMemorySize, G_DYN);

    k_prep<<<256, 256>>>(W);
    k_sq<<<(Bb * Nn) / 256, 256>>>(x);
    k_split<<<dim3(Nn / 32, Cc / 32, Bb), dim3(32, 8)>>>(x);
    k_distknn<<<dim3(16, Bb), 256, F2_DYN>>>();
    k_fix<<<128, 256>>>();
    k_uv_mma<<<dim3((2 * CO) / 128, Nn / 128, Bb), 256, SM_DYN>>>();
    k_gather<<<dim3(CO / GCH, Bb), 256, G_DYN>>>();
    k_final<<<1, 256>>>(gamma, beta);
    k_out<<<dim3(Nn / 32, CO / 32, Bb), dim3(32, 8)>>>(out);
}

// round 11
// speedup vs baseline: 1.2413x; 1.2413x over previous
#include <cuda_runtime.h>
#include <cuda_bf16.h>
#include <cstdint>

#define Bb 16
#define Cc 128
#define Nn 2048
#define CO 256
#define KK 20
#define KL 12
#define CNT ((double)(Bb) * (double)(Nn) * (double)(KK))
#define BIGF 1e30f

// ---------------- scratch -----------------------------------------------------
__device__ float          g_sq[Bb * Nn];
__device__ int            g_knn[Bb * Nn * KK];
__device__ __nv_bfloat16  g_xh[(size_t)Bb * Nn * Cc];          // x transposed [b][n][c], hi
__device__ __nv_bfloat16  g_xl[(size_t)Bb * Nn * Cc];          // lo
__device__ __nv_bfloat16  g_Wch[(size_t)2 * CO * Cc];          // Wc [j][c] hi (j<256: W1-W2, else W2)
__device__ __nv_bfloat16  g_Wcl[(size_t)2 * CO * Cc];          // lo
__device__ float          g_uv[(size_t)Bb * Nn * 2 * CO];      // [b][n][0..255]=u, [256..511]=v
__device__ float          g_ymax[(size_t)Bb * Nn * CO];
__device__ float          g_ymin[(size_t)Bb * Nn * CO];
__device__ double         g_sum[CO];
__device__ double         g_sumsq[CO];
__device__ float          g_scale[CO];
__device__ float          g_shift[CO];
__device__ int            g_nfb;
__device__ int            g_fbrow[Bb * Nn];

// ---------------- helpers -----------------------------------------------------
__device__ __forceinline__ uint32_t smem_u32(const void* p) {
    uint32_t a;
    asm("{ .reg .u64 t; cvta.to.shared.u64 t, %1; cvt.u32.u64 %0, t; }" : "=r"(a) : "l"(p));
    return a;
}
__device__ __forceinline__ void ldsm4(uint32_t* r, uint32_t addr) {
    asm volatile("ldmatrix.sync.aligned.m8n8.x4.shared.b16 {%0,%1,%2,%3}, [%4];"
        : "=r"(r[0]), "=r"(r[1]), "=r"(r[2]), "=r"(r[3]) : "r"(addr));
}
__device__ __forceinline__ void mma16816(float* d, const uint32_t* a, uint32_t b0, uint32_t b1) {
    asm volatile("mma.sync.aligned.m16n8k16.row.col.f32.bf16.bf16.f32 "
        "{%0,%1,%2,%3}, {%4,%5,%6,%7}, {%8,%9}, {%0,%1,%2,%3};"
        : "+f"(d[0]), "+f"(d[1]), "+f"(d[2]), "+f"(d[3])
        : "r"(a[0]), "r"(a[1]), "r"(a[2]), "r"(a[3]), "r"(b0), "r"(b1));
}
#define CP16(dst, src) asm volatile("cp.async.cg.shared.global [%0], [%1], 16;" :: "r"(dst), "l"(src))
#define CP_COMMIT()    asm volatile("cp.async.commit_group;" ::: "memory")
#define CP_WAIT0()     asm volatile("cp.async.wait_group 0;" ::: "memory")

// padded smem tile: rows x 128 bf16, row stride 272 bytes (conflict-free ldmatrix)
#define LDB   272
#define TILEB (128 * LDB)          // 34816
#define TILEB64 (64 * LDB)         // 17408

// ---- uv kernel smem layout ----
#define SM_AH 0
#define SM_AL TILEB
#define SM_BH (2 * TILEB)
#define SM_BL (3 * TILEB)
#define SM_DYN (4 * TILEB + 1024)  // 140288

// ---- fused dist+knn smem layout (2 CTAs/SM) ----
#define F2_AH 0
#define F2_AL TILEB
#define F2_BH (2 * TILEB)                 // 69632
#define F2_BL (2 * TILEB + TILEB64)       // 87040
#define F2_SQ (2 * TILEB + 2 * TILEB64)   // 104448
#define F2_DYN (F2_SQ + 8192)             // 112640

__device__ __forceinline__ void load_tile_pad(const __nv_bfloat16* __restrict__ src,
                                              char* sm, int tid) {
#pragma unroll
    for (int it = 0; it < 8; it++) {
        int idx = it * 256 + tid;
        int row = idx >> 4, seg = idx & 15;
        uint4 v = *(const uint4*)(src + (size_t)row * 128 + seg * 8);
        *(uint4*)(sm + row * LDB + seg * 16) = v;
    }
}
__device__ __forceinline__ void tile_async(const __nv_bfloat16* __restrict__ src,
                                           uint32_t smbase, int tid) {
#pragma unroll
    for (int it = 0; it < 8; it++) {
        int idx = it * 256 + tid;
        int row = idx >> 4, seg = idx & 15;
        CP16(smbase + row * LDB + seg * 16, src + (size_t)row * 128 + seg * 8);
    }
}
__device__ __forceinline__ void tile_async64(const __nv_bfloat16* __restrict__ src,
                                             uint32_t smbase, int tid) {
#pragma unroll
    for (int it = 0; it < 4; it++) {
        int idx = it * 256 + tid;          // 1024 = 64 rows x 16 segs
        int row = idx >> 4, seg = idx & 15;
        CP16(smbase + row * LDB + seg * 16, src + (size_t)row * 128 + seg * 8);
    }
}

// key = (monotone-uint(dist) << 32) | index: lexicographic (dist, idx)
__device__ __forceinline__ uint64_t pd_key(float d, int m) {
    uint32_t b = __float_as_uint(d);
    b ^= ((uint32_t)((int32_t)b >> 31)) | 0x80000000u;
    return ((uint64_t)b << 32) | (uint32_t)m;
}

// paired insert: insert (da,ia),(db,ib) into sorted KL-list in ONE chain pass.
// Values > T are skippable (row-20th <= T proven by quad bound); keep == T.
__device__ __forceinline__ void insert2(float (&bd)[KL], int (&bi)[KL],
                                        float da, int ia, float db, int ib, float T) {
    {
        bool sw = db < da;
        float td = sw ? db : da;  int ti = sw ? ib : ia;
        db = sw ? da : db;        ib = sw ? ia : ib;
        da = td;                  ia = ti;
    }
    if (da < bd[KL - 1] && da <= T) {
#pragma unroll
        for (int i = 0; i < KL; i++) {
            bool lt = da < bd[i];
            float sv = lt ? da : bd[i];
            int   si = lt ? ia : bi[i];
            float c1 = lt ? bd[i] : da;       // displaced candidate
            int   ci = lt ? bi[i] : ia;
            bd[i] = sv; bi[i] = si;
            bool sw = db < c1;                // keep carried pair ordered
            da = sw ? db : c1;  ia = sw ? ib : ci;
            db = sw ? c1 : db;  ib = sw ? ci : ib;
        }
    }
}

// merge one row's 4 per-thread sorted lists (quad of lanes) -> top-20 to g_knn
__device__ __forceinline__ int quad_merge(float (&bd)[KL], int (&bi)[KL],
                                          int lane, int nglob) {
    uint64_t cur = pd_key(bd[0], bi[0]);
    int p = 0;
#pragma unroll 1
    for (int s = 0; s < KK; s++) {
        uint64_t v = cur;
        uint64_t o2 = __shfl_down_sync(0xffffffffu, v, 2, 4); v = o2 < v ? o2 : v;
        uint64_t o1 = __shfl_down_sync(0xffffffffu, v, 1, 4); v = o1 < v ? o1 : v;
        v = __shfl_sync(0xffffffffu, v, 0, 4);
        if ((lane & 3) == 0) g_knn[nglob * KK + s] = (int)(uint32_t)v;
        if (cur == v) {
            p++;
#pragma unroll
            for (int i = 0; i < KL - 1; i++) { bd[i] = bd[i + 1]; bi[i] = bi[i + 1]; }
            bd[KL - 1] = BIGF; bi[KL - 1] = 0x7fffffff;
            cur = pd_key(bd[0], bi[0]);
        }
    }
    return p >= KL ? 1 : 0;
}

// ---------------- prep: weights (folded + split) + zero accumulators ----------
__global__ void k_prep(const float* __restrict__ W) {
    int tid = blockIdx.x * blockDim.x + threadIdx.x;     // 65536
    int j = tid >> 7, c = tid & 127;
    float w;
    if (j < CO) w = W[j * (2 * Cc) + c] - W[j * (2 * Cc) + Cc + c];
    else        w = W[(j - CO) * (2 * Cc) + Cc + c];
    __nv_bfloat16 hi = __float2bfloat16(w);
    g_Wch[tid] = hi;
    g_Wcl[tid] = __float2bfloat16(w - __bfloat162float(hi));
    if (tid < CO) { g_sum[tid] = 0.0; g_sumsq[tid] = 0.0; }
    if (tid == 0) g_nfb = 0;
}

// ---------------- squared norms ------------------------------------------------
__global__ void k_sq(const float* __restrict__ x) {
    int i = blockIdx.x * 256 + threadIdx.x;
    int b = i >> 11, n = i & (Nn - 1);
    const float* xb = x + (size_t)b * Cc * Nn;
    float s = 0.f;
#pragma unroll 8
    for (int c = 0; c < Cc; c++) {
        float v = xb[(size_t)c * Nn + n];
        s = fmaf(v, v, s);
    }
    g_sq[i] = s;
}

// ---------------- transpose x -> [b][n][c] + bf16 hi/lo split -------------------
__global__ void k_split(const float* __restrict__ x) {
    __shared__ float t[32][33];
    int b = blockIdx.z, c0 = blockIdx.y * 32, n0 = blockIdx.x * 32;
    int tx = threadIdx.x, ty = threadIdx.y;
    const float* xb = x + ((size_t)b * Cc + c0) * Nn + n0;
    for (int i = ty; i < 32; i += 8)
        t[i][tx] = xb[(size_t)i * Nn + tx];
    __syncthreads();
    for (int i = ty; i < 32; i += 8) {
        float v = t[tx][i];
        __nv_bfloat16 hi = __float2bfloat16(v);
        float lo = v - __bfloat162float(hi);
        size_t o = ((size_t)b * Nn + n0 + i) * Cc + c0 + tx;
        g_xh[o] = hi;
        g_xl[o] = __float2bfloat16(lo);
    }
}

// ---------------- fused distance GEMM + top-k (2 CTAs/SM, 64-row B tiles) -------
__global__ __launch_bounds__(256, 2) void k_distknn() {
    extern __shared__ char sm[];
    uint32_t sb = smem_u32(sm);
    int tid = threadIdx.x, wid = tid >> 5, lane = tid & 31;
    int strip = blockIdx.x, b = blockIdx.y;
    int n0 = strip * 128;
    const __nv_bfloat16* xh = g_xh + ((size_t)b << 11) * Cc;
    const __nv_bfloat16* xl = g_xl + ((size_t)b << 11) * Cc;
    float* s_sqm = (float*)(sm + F2_SQ);

    {
        const float4* src = (const float4*)(g_sq + (b << 11));
        float4* dst = (float4*)s_sqm;
        for (int i = tid; i < 512; i += 256) dst[i] = src[i];
    }
    tile_async(xh + (size_t)n0 * Cc, sb + F2_AH, tid);
    tile_async(xl + (size_t)n0 * Cc, sb + F2_AL, tid);
    tile_async64(xh, sb + F2_BH, tid);
    tile_async64(xl, sb + F2_BL, tid);
    CP_COMMIT();
    CP_WAIT0();
    __syncthreads();

    int rw = wid * 16, r0 = lane >> 2, q = (lane & 3) * 2;
    float acc[8][4];
#pragma unroll
    for (int g = 0; g < 8; g++)
#pragma unroll
        for (int i = 0; i < 4; i++) acc[g][i] = 0.f;

    float bd0[KL], bd1[KL];
    int   bi0[KL], bi1[KL];
#pragma unroll
    for (int i = 0; i < KL; i++) { bd0[i] = BIGF; bd1[i] = BIGF; bi0[i] = 0x7fffffff; bi1[i] = 0x7fffffff; }
    float T0 = BIGF, T1 = BIGF;

    float sn0 = s_sqm[n0 + rw + r0];
    float sn1 = s_sqm[n0 + rw + r0 + 8];
    uint32_t aoff = (uint32_t)((rw + (lane & 15)) * LDB + (lane >> 4) * 16);
    uint32_t boff = (uint32_t)(((lane & 7) + ((lane >> 4) << 3)) * LDB + ((lane >> 3) & 1) * 16);
    uint32_t a_hi = sb + F2_AH, a_lo = sb + F2_AL;
    uint32_t b_hi = sb + F2_BH, b_lo = sb + F2_BL;

#pragma unroll 1
    for (int t = 0; t < 32; t++) {
#pragma unroll
        for (int ks = 0; ks < 8; ks++) {
            uint32_t kb = ks * 32;
            uint32_t ah[4], al[4];
            ldsm4(ah, a_hi + aoff + kb);
            ldsm4(al, a_lo + aoff + kb);
#pragma unroll
            for (int g = 0; g < 4; g++) {
                uint32_t bo = boff + g * (16 * LDB) + kb;
                uint32_t bhx[4], blx[4];
                ldsm4(bhx, b_hi + bo);
                ldsm4(blx, b_lo + bo);
                mma16816(acc[2 * g],     ah, bhx[0], bhx[1]);
                mma16816(acc[2 * g],     ah, blx[0], blx[1]);
                mma16816(acc[2 * g],     al, bhx[0], bhx[1]);
                mma16816(acc[2 * g + 1], ah, bhx[2], bhx[3]);
                mma16816(acc[2 * g + 1], ah, blx[2], blx[3]);
                mma16816(acc[2 * g + 1], al, bhx[2], bhx[3]);
            }
        }
        __syncthreads();                    // all warps done reading B tile t
        if (t < 31) {                       // overwrite B with tile t+1 (async)
            tile_async64(xh + (size_t)(t + 1) * 64 * Cc, b_hi, tid);
            tile_async64(xl + (size_t)(t + 1) * 64 * Cc, b_lo, tid);
            CP_COMMIT();
        }

        // epilogue (overlaps the async loads): d = sqn + sqm - 2*acc; inserts
        int m0 = t * 64;
#pragma unroll
        for (int g = 0; g < 8; g++) {
            int mm = m0 + g * 8 + q;
            float sm0v = s_sqm[mm], sm1v = s_sqm[mm + 1];
            float d00 = fmaf(-2.f, acc[g][0], sn0 + sm0v);
            float d01 = fmaf(-2.f, acc[g][1], sn0 + sm1v);
            float d10 = fmaf(-2.f, acc[g][2], sn1 + sm0v);
            float d11 = fmaf(-2.f, acc[g][3], sn1 + sm1v);
            insert2(bd0, bi0, d00, mm, d01, mm + 1, T0);
            insert2(bd1, bi1, d10, mm, d11, mm + 1, T1);
            acc[g][0] = acc[g][1] = acc[g][2] = acc[g][3] = 0.f;
        }
        // quad threshold: T = max over quad of bd[4]; >=20 union values <= T
        {
            float t0 = bd0[4];
            t0 = fmaxf(t0, __shfl_xor_sync(0xffffffffu, t0, 1, 4));
            t0 = fmaxf(t0, __shfl_xor_sync(0xffffffffu, t0, 2, 4));
            T0 = t0;
            float t1 = bd1[4];
            t1 = fmaxf(t1, __shfl_xor_sync(0xffffffffu, t1, 1, 4));
            t1 = fmaxf(t1, __shfl_xor_sync(0xffffffffu, t1, 2, 4));
            T1 = t1;
        }
        if (t < 31) {
            CP_WAIT0();
            __syncthreads();
        }
    }

    // merge quads -> g_knn; flag exhausted rows for exact redo
    int nbase = (b << 11) + n0 + rw;
    int bad0 = quad_merge(bd0, bi0, lane, nbase + r0);
    int bad1 = quad_merge(bd1, bi1, lane, nbase + r0 + 8);
    unsigned bm0 = __ballot_sync(0xffffffffu, bad0 != 0);
    unsigned bm1 = __ballot_sync(0xffffffffu, bad1 != 0);
    if ((lane & 3) == 0) {
        if ((bm0 >> lane) & 0xFu) { int s = atomicAdd(&g_nfb, 1); g_fbrow[s] = nbase + r0; }
        if ((bm1 >> lane) & 0xFu) { int s = atomicAdd(&g_nfb, 1); g_fbrow[s] = nbase + r0 + 8; }
    }
}

// ---------------- cleanup: exact fp32 top-20 for flagged rows (coalesced) -------
__global__ __launch_bounds__(256) void k_fix() {
    __shared__ float xn[Cc];
    __shared__ float sd[Nn];
    int nfb = g_nfb;
    int wid = threadIdx.x >> 5, lane = threadIdx.x & 31;
    for (int i = blockIdx.x; i < nfb; i += gridDim.x) {
        int rowid = g_fbrow[i];
        int b = rowid >> 11, n = rowid & (Nn - 1);
        const __nv_bfloat16* xh = g_xh + ((size_t)b << 11) * Cc;
        const __nv_bfloat16* xl = g_xl + ((size_t)b << 11) * Cc;
        if (threadIdx.x < Cc)
            xn[threadIdx.x] = __bfloat162float(xh[(size_t)n * Cc + threadIdx.x])
                            + __bfloat162float(xl[(size_t)n * Cc + threadIdx.x]);
        __syncthreads();
        float sqn = g_sq[(b << 11) + n];
        for (int m = wid; m < Nn; m += 8) {
            const __nv_bfloat162* rh = (const __nv_bfloat162*)(xh + (size_t)m * Cc);
            const __nv_bfloat162* rl = (const __nv_bfloat162*)(xl + (size_t)m * Cc);
            __nv_bfloat162 h0 = rh[lane * 2], h1 = rh[lane * 2 + 1];
            __nv_bfloat162 l0 = rl[lane * 2], l1 = rl[lane * 2 + 1];
            int c0 = lane * 4;
            float dot = xn[c0]     * (__bfloat162float(h0.x) + __bfloat162float(l0.x));
            dot = fmaf(xn[c0 + 1], (__bfloat162float(h0.y) + __bfloat162float(l0.y)), dot);
            dot = fmaf(xn[c0 + 2], (__bfloat162float(h1.x) + __bfloat162float(l1.x)), dot);
            dot = fmaf(xn[c0 + 3], (__bfloat162float(h1.y) + __bfloat162float(l1.y)), dot);
#pragma unroll
            for (int off = 16; off; off >>= 1)
                dot += __shfl_down_sync(0xffffffffu, dot, off);
            if (lane == 0)
                sd[m] = fmaf(-2.f, dot, sqn + g_sq[(b << 11) + m]);
        }
        __syncthreads();
        if (threadIdx.x < 32) {
            int lane2 = threadIdx.x;
            uint64_t best[KK];
#pragma unroll
            for (int ii = 0; ii < KK; ii++) best[ii] = ~0ull;
#pragma unroll 1
            for (int t = 0; t < Nn / 32; t++) {
                int m = t * 32 + lane2;
                uint64_t key = pd_key(sd[m], m);
                if (key < best[KK - 1]) {
#pragma unroll
                    for (int ii = 0; ii < KK; ii++) {
                        uint64_t bv = best[ii];
                        uint64_t lo = (key < bv) ? key : bv;
                        key          = (key < bv) ? bv : key;
                        best[ii] = lo;
                    }
                }
            }
            int p = 0;
            uint64_t cur = best[0];
#pragma unroll 1
            for (int s = 0; s < KK; s++) {
                uint64_t v = cur;
#pragma unroll
                for (int off = 16; off; off >>= 1) {
                    uint64_t ov = __shfl_down_sync(0xffffffffu, v, off);
                    v = (ov < v) ? ov : v;
                }
                v = __shfl_sync(0xffffffffu, v, 0);
                if (lane2 == 0) g_knn[((b << 11) + n) * KK + s] = (int)(uint32_t)v;
                if (cur == v) { p++; cur = (p < KK) ? best[p] : ~0ull; }
            }
        }
        __syncthreads();
    }
}

// ---------------- uv GEMM via mma.sync: uv[b][n][j] = x[n,:].Wc[j,:] ------------
__device__ __forceinline__ void gemm_main(uint32_t sb, int lane, int wy, int wx,
                                          float acc[4][4][4]) {
    uint32_t a_hi = sb + SM_AH, a_lo = sb + SM_AL;
    uint32_t b_hi = sb + SM_BH, b_lo = sb + SM_BL;
    uint32_t aoff = (uint32_t)((wy * 64 + (lane & 15)) * LDB + (lane >> 4) * 16);
    uint32_t boff = (uint32_t)((wx * 32 + (lane & 7) + (lane >> 4) * 8) * LDB
                               + ((lane >> 3) & 1) * 16);
#pragma unroll
    for (int ks = 0; ks < 8; ks++) {
        uint32_t kb = ks * 32;
        uint32_t ah[4][4], al[4][4], bh[2][4], bl[2][4];
#pragma unroll
        for (int c = 0; c < 4; c++) {
            ldsm4(ah[c], a_hi + aoff + c * (16 * LDB) + kb);
            ldsm4(al[c], a_lo + aoff + c * (16 * LDB) + kb);
        }
#pragma unroll
        for (int d = 0; d < 2; d++) {
            ldsm4(bh[d], b_hi + boff + d * (16 * LDB) + kb);
            ldsm4(bl[d], b_lo + boff + d * (16 * LDB) + kb);
        }
#pragma unroll
        for (int c = 0; c < 4; c++)
#pragma unroll
            for (int f = 0; f < 4; f++) {
                int d = f >> 1, h = (f & 1) * 2;
                mma16816(acc[c][f], ah[c], bh[d][h], bh[d][h + 1]);
                mma16816(acc[c][f], ah[c], bl[d][h], bl[d][h + 1]);
                mma16816(acc[c][f], al[c], bh[d][h], bh[d][h + 1]);
            }
    }
}

__global__ __launch_bounds__(256) void k_uv_mma() {
    extern __shared__ char sm[];
    uint32_t sb = smem_u32(sm);
    int tid = threadIdx.x, wid = tid >> 5, lane = tid & 31;
    int b = blockIdx.z, n0 = blockIdx.y * 128, j0 = blockIdx.x * 128;

    const __nv_bfloat16* xh = g_xh + ((size_t)(b << 11) + n0) * Cc;
    const __nv_bfloat16* xl = g_xl + ((size_t)(b << 11) + n0) * Cc;
    load_tile_pad(xh, sm + SM_AH, tid);
    load_tile_pad(xl, sm + SM_AL, tid);
    load_tile_pad(g_Wch + (size_t)j0 * Cc, sm + SM_BH, tid);
    load_tile_pad(g_Wcl + (size_t)j0 * Cc, sm + SM_BL, tid);
    __syncthreads();

    int wy = wid >> 2, wx = wid & 3;
    float acc[4][4][4];
#pragma unroll
    for (int c = 0; c < 4; c++)
#pragma unroll
        for (int f = 0; f < 4; f++)
#pragma unroll
            for (int i = 0; i < 4; i++) acc[c][f][i] = 0.f;

    gemm_main(sb, lane, wy, wx, acc);

    float* uvb = g_uv + (size_t)(b << 11) * (2 * CO);
    int r = lane >> 2, q = (lane & 3) * 2;
#pragma unroll
    for (int c = 0; c < 4; c++)
#pragma unroll
        for (int f = 0; f < 4; f++) {
            int nn = wy * 64 + c * 16 + r;
            int jj = wx * 32 + f * 8 + q;
            float2 v0, v1;
            v0.x = acc[c][f][0]; v0.y = acc[c][f][1];
            v1.x = acc[c][f][2]; v1.y = acc[c][f][3];
            *(float2*)&uvb[(size_t)(n0 + nn) * (2 * CO) + j0 + jj] = v0;
            *(float2*)&uvb[(size_t)(n0 + nn + 8) * (2 * CO) + j0 + jj] = v1;
        }
}

// ---------------- gather (R8 version): y = u + v[knn]; stats + max/min ----------
#define NT 32
__global__ __launch_bounds__(256) void k_gather() {
    int blk = blockIdx.x;                  // Bb * (Nn/NT) = 1024 blocks
    int b = blk >> 6;
    int n0 = (blk & 63) * NT;
    int o = threadIdx.x;
    const float* uvb = g_uv + (size_t)b * Nn * (2 * CO);

    __shared__ int sidx[NT * KK];
    for (int i = threadIdx.x; i < NT * KK; i += 256) {
        int nn = i / KK, jj = i % KK;
        sidx[i] = g_knn[((b << 11) + n0 + nn) * KK + jj];
    }
    __syncthreads();

    float s = 0.f, s2 = 0.f;
#pragma unroll 1
    for (int nn = 0; nn < NT; nn++) {
        int n = n0 + nn;
        float uo = uvb[(size_t)n * (2 * CO) + o];
        float mx = -BIGF, mn = BIGF;
#pragma unroll
        for (int j = 0; j < KK; j++) {
            int m = sidx[nn * KK + j];
            float y = uo + uvb[(size_t)m * (2 * CO) + CO + o];
            s += y;
            s2 = fmaf(y, y, s2);
            mx = fmaxf(mx, y);
            mn = fminf(mn, y);
        }
        size_t base = ((size_t)(b << 11) + n) * CO + o;
        g_ymax[base] = mx;
        g_ymin[base] = mn;
    }
    atomicAdd(&g_sum[o], (double)s);
    atomicAdd(&g_sumsq[o], (double)s2);
}

// ---------------- finalize BN stats ---------------------------------------------
__global__ void k_final(const float* __restrict__ gamma, const float* __restrict__ beta) {
    int o = threadIdx.x;
    double mean = g_sum[o] / CNT;
    double var = g_sumsq[o] / CNT - mean * mean;
    double inv = 1.0 / sqrt(var + 1e-5);
    float sc = (float)((double)gamma[o] * inv);
    g_scale[o] = sc;
    g_shift[o] = beta[o] - (float)(mean * (double)gamma[o] * inv);
}

// ---------------- output: affine + relu + transpose ------------------------------
__global__ void k_out(float* __restrict__ out) {
    __shared__ float tile[32][33];
    int b = blockIdx.z, o0 = blockIdx.y * 32, n0 = blockIdx.x * 32;
    int tx = threadIdx.x, ty = threadIdx.y;

    for (int i = ty; i < 32; i += 8) {
        int n = n0 + i;
        int o = o0 + tx;
        float sc = g_scale[o];
        size_t base = ((size_t)(b << 11) + n) * CO + o;
        float v;
        if (sc >= 0.f) v = g_ymax[base];
        else           v = g_ymin[base];
        float r = fmaf(sc, v, g_shift[o]);
        tile[i][tx] = fmaxf(r, 0.f);
    }
    __syncthreads();
    for (int i = ty; i < 32; i += 8) {
        int o = o0 + i;
        int n = n0 + tx;
        out[((size_t)b * CO + o) * Nn + n] = tile[tx][i];
    }
}

// ---------------- launch ----------------------------------------------------------
extern "C" void kernel_launch(void* const* d_in, const int* in_sizes, int n_in,
                              void* d_out, int out_size) {
    const float* x     = (const float*)d_in[0];
    const float* W     = (const float*)d_in[1];
    const float* gamma = (const float*)d_in[2];
    const float* beta  = (const float*)d_in[3];
    float* out = (float*)d_out;

    cudaFuncSetAttribute(k_distknn, cudaFuncAttributeMaxDynamicSharedMemorySize, F2_DYN);
    cudaFuncSetAttribute(k_uv_mma,  cudaFuncAttributeMaxDynamicSharedMemorySize, SM_DYN);

    k_prep<<<256, 256>>>(W);
    k_sq<<<(Bb * Nn) / 256, 256>>>(x);
    k_split<<<dim3(Nn / 32, Cc / 32, Bb), dim3(32, 8)>>>(x);
    k_distknn<<<dim3(16, Bb), 256, F2_DYN>>>();
    k_fix<<<128, 256>>>();
    k_uv_mma<<<dim3((2 * CO) / 128, Nn / 128, Bb), 256, SM_DYN>>>();
    k_gather<<<Bb * (Nn / NT), 256>>>();
    k_final<<<1, 256>>>(gamma, beta);
    k_out<<<dim3(Nn / 32, CO / 32, Bb), dim3(32, 8)>>>(out);
}

// round 12
// speedup vs baseline: 1.2444x; 1.0025x over previous
#include <cuda_runtime.h>
#include <cuda_bf16.h>
#include <cstdint>

#define Bb 16
#define Cc 128
#define Nn 2048
#define CO 256
#define KK 20
#define KL 12
#define NB 8
#define CNT ((double)(Bb) * (double)(Nn) * (double)(KK))
#define BIGF 1e30f

// ---------------- scratch -----------------------------------------------------
__device__ float          g_sq[Bb * Nn];
__device__ int            g_knn[Bb * Nn * KK];
__device__ __nv_bfloat16  g_xh[(size_t)Bb * Nn * Cc];          // x transposed [b][n][c], hi
__device__ __nv_bfloat16  g_xl[(size_t)Bb * Nn * Cc];          // lo
__device__ __nv_bfloat16  g_Wch[(size_t)2 * CO * Cc];          // Wc [j][c] hi (j<256: W1-W2, else W2)
__device__ __nv_bfloat16  g_Wcl[(size_t)2 * CO * Cc];          // lo
__device__ float          g_uv[(size_t)Bb * Nn * 2 * CO];      // [b][n][0..255]=u, [256..511]=v
__device__ float          g_ysel[(size_t)Bb * Nn * CO];        // selected extremum per (b,n,o)
__device__ int            g_gpos[CO];                          // gamma[o] >= 0
__device__ double         g_sum[NB * CO];
__device__ double         g_sumsq[NB * CO];
__device__ float          g_scale[CO];
__device__ float          g_shift[CO];
__device__ int            g_nfb;
__device__ int            g_fbrow[Bb * Nn];

// ---------------- helpers -----------------------------------------------------
__device__ __forceinline__ uint32_t smem_u32(const void* p) {
    uint32_t a;
    asm("{ .reg .u64 t; cvta.to.shared.u64 t, %1; cvt.u32.u64 %0, t; }" : "=r"(a) : "l"(p));
    return a;
}
__device__ __forceinline__ void ldsm4(uint32_t* r, uint32_t addr) {
    asm volatile("ldmatrix.sync.aligned.m8n8.x4.shared.b16 {%0,%1,%2,%3}, [%4];"
        : "=r"(r[0]), "=r"(r[1]), "=r"(r[2]), "=r"(r[3]) : "r"(addr));
}
__device__ __forceinline__ void mma16816(float* d, const uint32_t* a, uint32_t b0, uint32_t b1) {
    asm volatile("mma.sync.aligned.m16n8k16.row.col.f32.bf16.bf16.f32 "
        "{%0,%1,%2,%3}, {%4,%5,%6,%7}, {%8,%9}, {%0,%1,%2,%3};"
        : "+f"(d[0]), "+f"(d[1]), "+f"(d[2]), "+f"(d[3])
        : "r"(a[0]), "r"(a[1]), "r"(a[2]), "r"(a[3]), "r"(b0), "r"(b1));
}
#define CP16(dst, src) asm volatile("cp.async.cg.shared.global [%0], [%1], 16;" :: "r"(dst), "l"(src))
#define CP_COMMIT()    asm volatile("cp.async.commit_group;" ::: "memory")
#define CP_WAIT0()     asm volatile("cp.async.wait_group 0;" ::: "memory")

// padded smem tile: rows x 128 bf16, row stride 272 bytes (conflict-free ldmatrix)
#define LDB   272
#define TILEB (128 * LDB)          // 34816
#define TILEB64 (64 * LDB)         // 17408

// ---- shared 2-CTA smem layout (distknn + uv) ----
#define F2_AH 0
#define F2_AL TILEB
#define F2_BH (2 * TILEB)                 // 69632
#define F2_BL (2 * TILEB + TILEB64)       // 87040
#define F2_SQ (2 * TILEB + 2 * TILEB64)   // 104448
#define F2_DYN (F2_SQ + 8192)             // 112640

__device__ __forceinline__ void tile_async(const __nv_bfloat16* __restrict__ src,
                                           uint32_t smbase, int tid) {
#pragma unroll
    for (int it = 0; it < 8; it++) {
        int idx = it * 256 + tid;
        int row = idx >> 4, seg = idx & 15;
        CP16(smbase + row * LDB + seg * 16, src + (size_t)row * 128 + seg * 8);
    }
}
__device__ __forceinline__ void tile_async64(const __nv_bfloat16* __restrict__ src,
                                             uint32_t smbase, int tid) {
#pragma unroll
    for (int it = 0; it < 4; it++) {
        int idx = it * 256 + tid;          // 1024 = 64 rows x 16 segs
        int row = idx >> 4, seg = idx & 15;
        CP16(smbase + row * LDB + seg * 16, src + (size_t)row * 128 + seg * 8);
    }
}

// key = (monotone-uint(dist) << 32) | index: lexicographic (dist, idx)
__device__ __forceinline__ uint64_t pd_key(float d, int m) {
    uint32_t b = __float_as_uint(d);
    b ^= ((uint32_t)((int32_t)b >> 31)) | 0x80000000u;
    return ((uint64_t)b << 32) | (uint32_t)m;
}

// paired insert: insert (da,ia),(db,ib) into sorted KL-list in ONE chain pass.
// Values > T are skippable (row-20th <= T proven by quad bound); keep == T.
__device__ __forceinline__ void insert2(float (&bd)[KL], int (&bi)[KL],
                                        float da, int ia, float db, int ib, float T) {
    {
        bool sw = db < da;
        float td = sw ? db : da;  int ti = sw ? ib : ia;
        db = sw ? da : db;        ib = sw ? ia : ib;
        da = td;                  ia = ti;
    }
    if (da < bd[KL - 1] && da <= T) {
#pragma unroll
        for (int i = 0; i < KL; i++) {
            bool lt = da < bd[i];
            float sv = lt ? da : bd[i];
            int   si = lt ? ia : bi[i];
            float c1 = lt ? bd[i] : da;       // displaced candidate
            int   ci = lt ? bi[i] : ia;
            bd[i] = sv; bi[i] = si;
            bool sw = db < c1;                // keep carried pair ordered
            da = sw ? db : c1;  ia = sw ? ib : ci;
            db = sw ? c1 : db;  ib = sw ? ci : ib;
        }
    }
}

// merge one row's 4 per-thread sorted lists (quad of lanes) -> top-20 to g_knn
__device__ __forceinline__ int quad_merge(float (&bd)[KL], int (&bi)[KL],
                                          int lane, int nglob) {
    uint64_t cur = pd_key(bd[0], bi[0]);
    int p = 0;
#pragma unroll 1
    for (int s = 0; s < KK; s++) {
        uint64_t v = cur;
        uint64_t o2 = __shfl_down_sync(0xffffffffu, v, 2, 4); v = o2 < v ? o2 : v;
        uint64_t o1 = __shfl_down_sync(0xffffffffu, v, 1, 4); v = o1 < v ? o1 : v;
        v = __shfl_sync(0xffffffffu, v, 0, 4);
        if ((lane & 3) == 0) g_knn[nglob * KK + s] = (int)(uint32_t)v;
        if (cur == v) {
            p++;
#pragma unroll
            for (int i = 0; i < KL - 1; i++) { bd[i] = bd[i + 1]; bi[i] = bi[i + 1]; }
            bd[KL - 1] = BIGF; bi[KL - 1] = 0x7fffffff;
            cur = pd_key(bd[0], bi[0]);
        }
    }
    return p >= KL ? 1 : 0;
}

// ---------------- prep: weights (folded + split) + zero accumulators ----------
__global__ void k_prep(const float* __restrict__ W, const float* __restrict__ gamma) {
    int tid = blockIdx.x * blockDim.x + threadIdx.x;     // 65536
    int j = tid >> 7, c = tid & 127;
    float w;
    if (j < CO) w = W[j * (2 * Cc) + c] - W[j * (2 * Cc) + Cc + c];
    else        w = W[(j - CO) * (2 * Cc) + Cc + c];
    __nv_bfloat16 hi = __float2bfloat16(w);
    g_Wch[tid] = hi;
    g_Wcl[tid] = __float2bfloat16(w - __bfloat162float(hi));
    if (tid < NB * CO) { g_sum[tid] = 0.0; g_sumsq[tid] = 0.0; }
    if (tid < CO) g_gpos[tid] = (gamma[tid] >= 0.f) ? 1 : 0;
    if (tid == 0) g_nfb = 0;
}

// ---------------- squared norms ------------------------------------------------
__global__ void k_sq(const float* __restrict__ x) {
    int i = blockIdx.x * 256 + threadIdx.x;
    int b = i >> 11, n = i & (Nn - 1);
    const float* xb = x + (size_t)b * Cc * Nn;
    float s = 0.f;
#pragma unroll 8
    for (int c = 0; c < Cc; c++) {
        float v = xb[(size_t)c * Nn + n];
        s = fmaf(v, v, s);
    }
    g_sq[i] = s;
}

// ---------------- transpose x -> [b][n][c] + bf16 hi/lo split -------------------
__global__ void k_split(const float* __restrict__ x) {
    __shared__ float t[32][33];
    int b = blockIdx.z, c0 = blockIdx.y * 32, n0 = blockIdx.x * 32;
    int tx = threadIdx.x, ty = threadIdx.y;
    const float* xb = x + ((size_t)b * Cc + c0) * Nn + n0;
    for (int i = ty; i < 32; i += 8)
        t[i][tx] = xb[(size_t)i * Nn + tx];
    __syncthreads();
    for (int i = ty; i < 32; i += 8) {
        float v = t[tx][i];
        __nv_bfloat16 hi = __float2bfloat16(v);
        float lo = v - __bfloat162float(hi);
        size_t o = ((size_t)b * Nn + n0 + i) * Cc + c0 + tx;
        g_xh[o] = hi;
        g_xl[o] = __float2bfloat16(lo);
    }
}

// ---------------- fused distance GEMM + top-k (2 CTAs/SM, 64-row B tiles) -------
__global__ __launch_bounds__(256, 2) void k_distknn() {
    extern __shared__ char sm[];
    uint32_t sb = smem_u32(sm);
    int tid = threadIdx.x, wid = tid >> 5, lane = tid & 31;
    int strip = blockIdx.x, b = blockIdx.y;
    int n0 = strip * 128;
    const __nv_bfloat16* xh = g_xh + ((size_t)b << 11) * Cc;
    const __nv_bfloat16* xl = g_xl + ((size_t)b << 11) * Cc;
    float* s_sqm = (float*)(sm + F2_SQ);

    {
        const float4* src = (const float4*)(g_sq + (b << 11));
        float4* dst = (float4*)s_sqm;
        for (int i = tid; i < 512; i += 256) dst[i] = src[i];
    }
    tile_async(xh + (size_t)n0 * Cc, sb + F2_AH, tid);
    tile_async(xl + (size_t)n0 * Cc, sb + F2_AL, tid);
    tile_async64(xh, sb + F2_BH, tid);
    tile_async64(xl, sb + F2_BL, tid);
    CP_COMMIT();
    CP_WAIT0();
    __syncthreads();

    int rw = wid * 16, r0 = lane >> 2, q = (lane & 3) * 2;
    float acc[8][4];
#pragma unroll
    for (int g = 0; g < 8; g++)
#pragma unroll
        for (int i = 0; i < 4; i++) acc[g][i] = 0.f;

    float bd0[KL], bd1[KL];
    int   bi0[KL], bi1[KL];
#pragma unroll
    for (int i = 0; i < KL; i++) { bd0[i] = BIGF; bd1[i] = BIGF; bi0[i] = 0x7fffffff; bi1[i] = 0x7fffffff; }
    float T0 = BIGF, T1 = BIGF;

    float sn0 = s_sqm[n0 + rw + r0];
    float sn1 = s_sqm[n0 + rw + r0 + 8];
    uint32_t aoff = (uint32_t)((rw + (lane & 15)) * LDB + (lane >> 4) * 16);
    uint32_t boff = (uint32_t)(((lane & 7) + ((lane >> 4) << 3)) * LDB + ((lane >> 3) & 1) * 16);
    uint32_t a_hi = sb + F2_AH, a_lo = sb + F2_AL;
    uint32_t b_hi = sb + F2_BH, b_lo = sb + F2_BL;

#pragma unroll 1
    for (int t = 0; t < 32; t++) {
#pragma unroll
        for (int ks = 0; ks < 8; ks++) {
            uint32_t kb = ks * 32;
            uint32_t ah[4], al[4];
            ldsm4(ah, a_hi + aoff + kb);
            ldsm4(al, a_lo + aoff + kb);
#pragma unroll
            for (int g = 0; g < 4; g++) {
                uint32_t bo = boff + g * (16 * LDB) + kb;
                uint32_t bhx[4], blx[4];
                ldsm4(bhx, b_hi + bo);
                ldsm4(blx, b_lo + bo);
                mma16816(acc[2 * g],     ah, bhx[0], bhx[1]);
                mma16816(acc[2 * g],     ah, blx[0], blx[1]);
                mma16816(acc[2 * g],     al, bhx[0], bhx[1]);
                mma16816(acc[2 * g + 1], ah, bhx[2], bhx[3]);
                mma16816(acc[2 * g + 1], ah, blx[2], blx[3]);
                mma16816(acc[2 * g + 1], al, bhx[2], bhx[3]);
            }
        }
        __syncthreads();                    // all warps done reading B tile t
        if (t < 31) {                       // overwrite B with tile t+1 (async)
            tile_async64(xh + (size_t)(t + 1) * 64 * Cc, b_hi, tid);
            tile_async64(xl + (size_t)(t + 1) * 64 * Cc, b_lo, tid);
            CP_COMMIT();
        }

        // epilogue (overlaps the async loads): d = sqn + sqm - 2*acc; inserts
        int m0 = t * 64;
#pragma unroll
        for (int g = 0; g < 8; g++) {
            int mm = m0 + g * 8 + q;
            float sm0v = s_sqm[mm], sm1v = s_sqm[mm + 1];
            float d00 = fmaf(-2.f, acc[g][0], sn0 + sm0v);
            float d01 = fmaf(-2.f, acc[g][1], sn0 + sm1v);
            float d10 = fmaf(-2.f, acc[g][2], sn1 + sm0v);
            float d11 = fmaf(-2.f, acc[g][3], sn1 + sm1v);
            insert2(bd0, bi0, d00, mm, d01, mm + 1, T0);
            insert2(bd1, bi1, d10, mm, d11, mm + 1, T1);
            acc[g][0] = acc[g][1] = acc[g][2] = acc[g][3] = 0.f;
        }
        // quad threshold: T = max over quad of bd[4]; >=20 union values <= T
        {
            float t0 = bd0[4];
            t0 = fmaxf(t0, __shfl_xor_sync(0xffffffffu, t0, 1, 4));
            t0 = fmaxf(t0, __shfl_xor_sync(0xffffffffu, t0, 2, 4));
            T0 = t0;
            float t1 = bd1[4];
            t1 = fmaxf(t1, __shfl_xor_sync(0xffffffffu, t1, 1, 4));
            t1 = fmaxf(t1, __shfl_xor_sync(0xffffffffu, t1, 2, 4));
            T1 = t1;
        }
        if (t < 31) {
            CP_WAIT0();
            __syncthreads();
        }
    }

    // merge quads -> g_knn; flag exhausted rows for exact redo
    int nbase = (b << 11) + n0 + rw;
    int bad0 = quad_merge(bd0, bi0, lane, nbase + r0);
    int bad1 = quad_merge(bd1, bi1, lane, nbase + r0 + 8);
    unsigned bm0 = __ballot_sync(0xffffffffu, bad0 != 0);
    unsigned bm1 = __ballot_sync(0xffffffffu, bad1 != 0);
    if ((lane & 3) == 0) {
        if ((bm0 >> lane) & 0xFu) { int s = atomicAdd(&g_nfb, 1); g_fbrow[s] = nbase + r0; }
        if ((bm1 >> lane) & 0xFu) { int s = atomicAdd(&g_nfb, 1); g_fbrow[s] = nbase + r0 + 8; }
    }
}

// ---------------- cleanup: exact fp32 top-20 for flagged rows (coalesced) -------
__global__ __launch_bounds__(256) void k_fix() {
    __shared__ float xn[Cc];
    __shared__ float sd[Nn];
    int nfb = g_nfb;
    int wid = threadIdx.x >> 5, lane = threadIdx.x & 31;
    for (int i = blockIdx.x; i < nfb; i += gridDim.x) {
        int rowid = g_fbrow[i];
        int b = rowid >> 11, n = rowid & (Nn - 1);
        const __nv_bfloat16* xh = g_xh + ((size_t)b << 11) * Cc;
        const __nv_bfloat16* xl = g_xl + ((size_t)b << 11) * Cc;
        if (threadIdx.x < Cc)
            xn[threadIdx.x] = __bfloat162float(xh[(size_t)n * Cc + threadIdx.x])
                            + __bfloat162float(xl[(size_t)n * Cc + threadIdx.x]);
        __syncthreads();
        float sqn = g_sq[(b << 11) + n];
        for (int m = wid; m < Nn; m += 8) {
            const __nv_bfloat162* rh = (const __nv_bfloat162*)(xh + (size_t)m * Cc);
            const __nv_bfloat162* rl = (const __nv_bfloat162*)(xl + (size_t)m * Cc);
            __nv_bfloat162 h0 = rh[lane * 2], h1 = rh[lane * 2 + 1];
            __nv_bfloat162 l0 = rl[lane * 2], l1 = rl[lane * 2 + 1];
            int c0 = lane * 4;
            float dot = xn[c0]     * (__bfloat162float(h0.x) + __bfloat162float(l0.x));
            dot = fmaf(xn[c0 + 1], (__bfloat162float(h0.y) + __bfloat162float(l0.y)), dot);
            dot = fmaf(xn[c0 + 2], (__bfloat162float(h1.x) + __bfloat162float(l1.x)), dot);
            dot = fmaf(xn[c0 + 3], (__bfloat162float(h1.y) + __bfloat162float(l1.y)), dot);
#pragma unroll
            for (int off = 16; off; off >>= 1)
                dot += __shfl_down_sync(0xffffffffu, dot, off);
            if (lane == 0)
                sd[m] = fmaf(-2.f, dot, sqn + g_sq[(b << 11) + m]);
        }
        __syncthreads();
        if (threadIdx.x < 32) {
            int lane2 = threadIdx.x;
            uint64_t best[KK];
#pragma unroll
            for (int ii = 0; ii < KK; ii++) best[ii] = ~0ull;
#pragma unroll 1
            for (int t = 0; t < Nn / 32; t++) {
                int m = t * 32 + lane2;
                uint64_t key = pd_key(sd[m], m);
                if (key < best[KK - 1]) {
#pragma unroll
                    for (int ii = 0; ii < KK; ii++) {
                        uint64_t bv = best[ii];
                        uint64_t lo = (key < bv) ? key : bv;
                        key          = (key < bv) ? bv : key;
                        best[ii] = lo;
                    }
                }
            }
            int p = 0;
            uint64_t cur = best[0];
#pragma unroll 1
            for (int s = 0; s < KK; s++) {
                uint64_t v = cur;
#pragma unroll
                for (int off = 16; off; off >>= 1) {
                    uint64_t ov = __shfl_down_sync(0xffffffffu, v, off);
                    v = (ov < v) ? ov : v;
                }
                v = __shfl_sync(0xffffffffu, v, 0);
                if (lane2 == 0) g_knn[((b << 11) + n) * KK + s] = (int)(uint32_t)v;
                if (cur == v) { p++; cur = (p < KK) ? best[p] : ~0ull; }
            }
        }
        __syncthreads();
    }
}

// ---------------- uv GEMM (2-CTA skeleton): uv[b][n][j] = x[n,:].Wc[j,:] --------
__global__ __launch_bounds__(256, 2) void k_uv_mma() {
    extern __shared__ char sm[];
    uint32_t sb = smem_u32(sm);
    int tid = threadIdx.x, wid = tid >> 5, lane = tid & 31;
    int strip = blockIdx.x, b = blockIdx.y;
    int n0 = strip * 128;
    const __nv_bfloat16* xh = g_xh + ((size_t)b << 11) * Cc;
    const __nv_bfloat16* xl = g_xl + ((size_t)b << 11) * Cc;

    tile_async(xh + (size_t)n0 * Cc, sb + F2_AH, tid);
    tile_async(xl + (size_t)n0 * Cc, sb + F2_AL, tid);
    tile_async64(g_Wch, sb + F2_BH, tid);
    tile_async64(g_Wcl, sb + F2_BL, tid);
    CP_COMMIT();
    CP_WAIT0();
    __syncthreads();

    int rw = wid * 16, r0 = lane >> 2, q = (lane & 3) * 2;
    float acc[8][4];
#pragma unroll
    for (int g = 0; g < 8; g++)
#pragma unroll
        for (int i = 0; i < 4; i++) acc[g][i] = 0.f;

    uint32_t aoff = (uint32_t)((rw + (lane & 15)) * LDB + (lane >> 4) * 16);
    uint32_t boff = (uint32_t)(((lane & 7) + ((lane >> 4) << 3)) * LDB + ((lane >> 3) & 1) * 16);
    uint32_t a_hi = sb + F2_AH, a_lo = sb + F2_AL;
    uint32_t b_hi = sb + F2_BH, b_lo = sb + F2_BL;
    float* uvb = g_uv + (size_t)(b << 11) * (2 * CO);

#pragma unroll 1
    for (int t = 0; t < 8; t++) {
#pragma unroll
        for (int ks = 0; ks < 8; ks++) {
            uint32_t kb = ks * 32;
            uint32_t ah[4], al[4];
            ldsm4(ah, a_hi + aoff + kb);
            ldsm4(al, a_lo + aoff + kb);
#pragma unroll
            for (int g = 0; g < 4; g++) {
                uint32_t bo = boff + g * (16 * LDB) + kb;
                uint32_t bhx[4], blx[4];
                ldsm4(bhx, b_hi + bo);
                ldsm4(blx, b_lo + bo);
                mma16816(acc[2 * g],     ah, bhx[0], bhx[1]);
                mma16816(acc[2 * g],     ah, blx[0], blx[1]);
                mma16816(acc[2 * g],     al, bhx[0], bhx[1]);
                mma16816(acc[2 * g + 1], ah, bhx[2], bhx[3]);
                mma16816(acc[2 * g + 1], ah, blx[2], blx[3]);
                mma16816(acc[2 * g + 1], al, bhx[2], bhx[3]);
            }
        }
        __syncthreads();
        if (t < 7) {
            tile_async64(g_Wch + (size_t)(t + 1) * 64 * Cc, b_hi, tid);
            tile_async64(g_Wcl + (size_t)(t + 1) * 64 * Cc, b_lo, tid);
            CP_COMMIT();
        }

        // epilogue: write uv[n][j] for j-tile t (overlaps async loads)
        int j0 = t * 64;
#pragma unroll
        for (int g = 0; g < 8; g++) {
            int jj = j0 + g * 8 + q;
            int nn = n0 + rw + r0;
            *(float2*)&uvb[(size_t)nn * (2 * CO) + jj] =
                make_float2(acc[g][0], acc[g][1]);
            *(float2*)&uvb[(size_t)(nn + 8) * (2 * CO) + jj] =
                make_float2(acc[g][2], acc[g][3]);
            acc[g][0] = acc[g][1] = acc[g][2] = acc[g][3] = 0.f;
        }
        if (t < 7) {
            CP_WAIT0();
            __syncthreads();
        }
    }
}

// ---------------- gather: y = u + v[knn]; stats + selected extremum -------------
#define NT 32
__global__ __launch_bounds__(256) void k_gather() {
    int blk = blockIdx.x;                  // Bb * (Nn/NT) = 1024 blocks
    int b = blk >> 6;
    int n0 = (blk & 63) * NT;
    int o = threadIdx.x;
    const float* uvb = g_uv + (size_t)b * Nn * (2 * CO);
    int gpos = g_gpos[o];

    __shared__ int sidx[NT * KK];
    for (int i = threadIdx.x; i < NT * KK; i += 256) {
        int nn = i / KK, jj = i % KK;
        sidx[i] = g_knn[((b << 11) + n0 + nn) * KK + jj];
    }
    __syncthreads();

    float s = 0.f, s2 = 0.f;
#pragma unroll 1
    for (int nn = 0; nn < NT; nn++) {
        int n = n0 + nn;
        float uo = uvb[(size_t)n * (2 * CO) + o];
        float mx = -BIGF, mn = BIGF;
#pragma unroll
        for (int j = 0; j < KK; j++) {
            int m = sidx[nn * KK + j];
            float y = uo + uvb[(size_t)m * (2 * CO) + CO + o];
            s += y;
            s2 = fmaf(y, y, s2);
            mx = fmaxf(mx, y);
            mn = fminf(mn, y);
        }
        g_ysel[((size_t)(b << 11) + n) * CO + o] = gpos ? mx : mn;
    }
    int bkt = (blk & (NB - 1)) * CO + o;
    atomicAdd(&g_sum[bkt], (double)s);
    atomicAdd(&g_sumsq[bkt], (double)s2);
}

// ---------------- finalize BN stats ---------------------------------------------
__global__ void k_final(const float* __restrict__ gamma, const float* __restrict__ beta) {
    int o = threadIdx.x;
    double sum = 0.0, sumsq = 0.0;
#pragma unroll
    for (int k = 0; k < NB; k++) { sum += g_sum[k * CO + o]; sumsq += g_sumsq[k * CO + o]; }
    double mean = sum / CNT;
    double var = sumsq / CNT - mean * mean;
    double inv = 1.0 / sqrt(var + 1e-5);
    float sc = (float)((double)gamma[o] * inv);
    g_scale[o] = sc;
    g_shift[o] = beta[o] - (float)(mean * (double)gamma[o] * inv);
}

// ---------------- output: affine + relu + transpose ------------------------------
__global__ void k_out(float* __restrict__ out) {
    __shared__ float tile[32][33];
    int b = blockIdx.z, o0 = blockIdx.y * 32, n0 = blockIdx.x * 32;
    int tx = threadIdx.x, ty = threadIdx.y;

    for (int i = ty; i < 32; i += 8) {
        int n = n0 + i;
        int o = o0 + tx;
        float sc = g_scale[o];
        float v = g_ysel[((size_t)(b << 11) + n) * CO + o];
        float r = fmaf(sc, v, g_shift[o]);
        tile[i][tx] = fmaxf(r, 0.f);
    }
    __syncthreads();
    for (int i = ty; i < 32; i += 8) {
        int o = o0 + i;
        int n = n0 + tx;
        out[((size_t)b * CO + o) * Nn + n] = tile[tx][i];
    }
}

// ---------------- launch ----------------------------------------------------------
extern "C" void kernel_launch(void* const* d_in, const int* in_sizes, int n_in,
                              void* d_out, int out_size) {
    const float* x     = (const float*)d_in[0];
    const float* W     = (const float*)d_in[1];
    const float* gamma = (const float*)d_in[2];
    const float* beta  = (const float*)d_in[3];
    float* out = (float*)d_out;

    cudaFuncSetAttribute(k_distknn, cudaFuncAttributeMaxDynamicSharedMemorySize, F2_DYN);
    cudaFuncSetAttribute(k_uv_mma,  cudaFuncAttributeMaxDynamicSharedMemorySize, F2_DYN);

    k_prep<<<256, 256>>>(W, gamma);
    k_sq<<<(Bb * Nn) / 256, 256>>>(x);
    k_split<<<dim3(Nn / 32, Cc / 32, Bb), dim3(32, 8)>>>(x);
    k_distknn<<<dim3(16, Bb), 256, F2_DYN>>>();
    k_fix<<<128, 256>>>();
    k_uv_mma<<<dim3(16, Bb), 256, F2_DYN>>>();
    k_gather<<<Bb * (Nn / NT), 256>>>();
    k_final<<<1, 256>>>(gamma, beta);
    k_out<<<dim3(Nn / 32, CO / 32, Bb), dim3(32, 8)>>>(out);
}

// round 13
// speedup vs baseline: 1.3686x; 1.0998x over previous
#include <cuda_runtime.h>
#include <cuda_bf16.h>
#include <cstdint>

#define Bb 16
#define Cc 128
#define Nn 2048
#define CO 256
#define KK 20
#define KL 12
#define NB 8
#define CNT ((double)(Bb) * (double)(Nn) * (double)(KK))
#define BIGF 1e30f

// ---------------- scratch -----------------------------------------------------
__device__ float          g_sq[Bb * Nn];
__device__ int            g_knn[Bb * Nn * KK];
__device__ __nv_bfloat16  g_xh[(size_t)Bb * Nn * Cc];          // x transposed [b][n][c], hi
__device__ __nv_bfloat16  g_xl[(size_t)Bb * Nn * Cc];          // lo
__device__ __nv_bfloat16  g_Wch[(size_t)2 * CO * Cc];          // Wc [j][c] hi (j<256: W1-W2, else W2)
__device__ __nv_bfloat16  g_Wcl[(size_t)2 * CO * Cc];          // lo
__device__ float          g_uv[(size_t)Bb * Nn * 2 * CO];      // [b][n][0..255]=u, [256..511]=v
__device__ float          g_ysel[(size_t)Bb * Nn * CO];        // selected extremum per (b,n,o)
__device__ int            g_gpos[CO];                          // gamma[o] >= 0
__device__ double         g_sum[NB * CO];
__device__ double         g_sumsq[NB * CO];
__device__ float          g_scale[CO];
__device__ float          g_shift[CO];
__device__ int            g_nfb;
__device__ int            g_fbrow[Bb * Nn];

// ---------------- helpers -----------------------------------------------------
__device__ __forceinline__ uint32_t smem_u32(const void* p) {
    uint32_t a;
    asm("{ .reg .u64 t; cvta.to.shared.u64 t, %1; cvt.u32.u64 %0, t; }" : "=r"(a) : "l"(p));
    return a;
}
__device__ __forceinline__ void ldsm4(uint32_t* r, uint32_t addr) {
    asm volatile("ldmatrix.sync.aligned.m8n8.x4.shared.b16 {%0,%1,%2,%3}, [%4];"
        : "=r"(r[0]), "=r"(r[1]), "=r"(r[2]), "=r"(r[3]) : "r"(addr));
}
__device__ __forceinline__ void mma16816(float* d, const uint32_t* a, uint32_t b0, uint32_t b1) {
    asm volatile("mma.sync.aligned.m16n8k16.row.col.f32.bf16.bf16.f32 "
        "{%0,%1,%2,%3}, {%4,%5,%6,%7}, {%8,%9}, {%0,%1,%2,%3};"
        : "+f"(d[0]), "+f"(d[1]), "+f"(d[2]), "+f"(d[3])
        : "r"(a[0]), "r"(a[1]), "r"(a[2]), "r"(a[3]), "r"(b0), "r"(b1));
}
#define CP16(dst, src) asm volatile("cp.async.cg.shared.global [%0], [%1], 16;" :: "r"(dst), "l"(src))
#define CP_COMMIT()    asm volatile("cp.async.commit_group;" ::: "memory")
#define CP_WAIT0()     asm volatile("cp.async.wait_group 0;" ::: "memory")

// padded smem tile: rows x 128 bf16, row stride 272 bytes (conflict-free ldmatrix)
#define LDB   272
#define TILEB (128 * LDB)          // 34816
#define TILEB64 (64 * LDB)         // 17408

// ---- shared 2-CTA smem layout (distknn + uv) ----
#define F2_AH 0
#define F2_AL TILEB
#define F2_BH (2 * TILEB)                 // 69632
#define F2_BL (2 * TILEB + TILEB64)       // 87040
#define F2_SQ (2 * TILEB + 2 * TILEB64)   // 104448
#define F2_DYN (F2_SQ + 8192)             // 112640

__device__ __forceinline__ void tile_async(const __nv_bfloat16* __restrict__ src,
                                           uint32_t smbase, int tid) {
#pragma unroll
    for (int it = 0; it < 8; it++) {
        int idx = it * 256 + tid;
        int row = idx >> 4, seg = idx & 15;
        CP16(smbase + row * LDB + seg * 16, src + (size_t)row * 128 + seg * 8);
    }
}
__device__ __forceinline__ void tile_async64(const __nv_bfloat16* __restrict__ src,
                                             uint32_t smbase, int tid) {
#pragma unroll
    for (int it = 0; it < 4; it++) {
        int idx = it * 256 + tid;          // 1024 = 64 rows x 16 segs
        int row = idx >> 4, seg = idx & 15;
        CP16(smbase + row * LDB + seg * 16, src + (size_t)row * 128 + seg * 8);
    }
}

// key = (monotone-uint(dist) << 32) | index: lexicographic (dist, idx)
__device__ __forceinline__ uint64_t pd_key(float d, int m) {
    uint32_t b = __float_as_uint(d);
    b ^= ((uint32_t)((int32_t)b >> 31)) | 0x80000000u;
    return ((uint64_t)b << 32) | (uint32_t)m;
}

// paired insert: insert (da,ia),(db,ib) into sorted KL-list in ONE chain pass.
// Values > T are skippable (row-20th <= T proven by quad bound); keep == T.
__device__ __forceinline__ void insert2(float (&bd)[KL], int (&bi)[KL],
                                        float da, int ia, float db, int ib, float T) {
    {
        bool sw = db < da;
        float td = sw ? db : da;  int ti = sw ? ib : ia;
        db = sw ? da : db;        ib = sw ? ia : ib;
        da = td;                  ia = ti;
    }
    if (da < bd[KL - 1] && da <= T) {
#pragma unroll
        for (int i = 0; i < KL; i++) {
            bool lt = da < bd[i];
            float sv = lt ? da : bd[i];
            int   si = lt ? ia : bi[i];
            float c1 = lt ? bd[i] : da;       // displaced candidate
            int   ci = lt ? bi[i] : ia;
            bd[i] = sv; bi[i] = si;
            bool sw = db < c1;                // keep carried pair ordered
            da = sw ? db : c1;  ia = sw ? ib : ci;
            db = sw ? c1 : db;  ib = sw ? ci : ib;
        }
    }
}

// merge one row's 4 per-thread sorted lists (quad of lanes) -> top-20 to g_knn
__device__ __forceinline__ int quad_merge(float (&bd)[KL], int (&bi)[KL],
                                          int lane, int nglob) {
    uint64_t cur = pd_key(bd[0], bi[0]);
    int p = 0;
#pragma unroll 1
    for (int s = 0; s < KK; s++) {
        uint64_t v = cur;
        uint64_t o2 = __shfl_down_sync(0xffffffffu, v, 2, 4); v = o2 < v ? o2 : v;
        uint64_t o1 = __shfl_down_sync(0xffffffffu, v, 1, 4); v = o1 < v ? o1 : v;
        v = __shfl_sync(0xffffffffu, v, 0, 4);
        if ((lane & 3) == 0) g_knn[nglob * KK + s] = (int)(uint32_t)v;
        if (cur == v) {
            p++;
#pragma unroll
            for (int i = 0; i < KL - 1; i++) { bd[i] = bd[i + 1]; bi[i] = bi[i + 1]; }
            bd[KL - 1] = BIGF; bi[KL - 1] = 0x7fffffff;
            cur = pd_key(bd[0], bi[0]);
        }
    }
    return p >= KL ? 1 : 0;
}

// ---------------- prep: weights (folded + split) + zero accumulators ----------
__global__ void k_prep(const float* __restrict__ W, const float* __restrict__ gamma) {
    int tid = blockIdx.x * blockDim.x + threadIdx.x;     // 65536
    int j = tid >> 7, c = tid & 127;
    float w;
    if (j < CO) w = W[j * (2 * Cc) + c] - W[j * (2 * Cc) + Cc + c];
    else        w = W[(j - CO) * (2 * Cc) + Cc + c];
    __nv_bfloat16 hi = __float2bfloat16(w);
    g_Wch[tid] = hi;
    g_Wcl[tid] = __float2bfloat16(w - __bfloat162float(hi));
    if (tid < NB * CO) { g_sum[tid] = 0.0; g_sumsq[tid] = 0.0; }
    if (tid < CO) g_gpos[tid] = (gamma[tid] >= 0.f) ? 1 : 0;
    if (tid == 0) g_nfb = 0;
}

// ---------------- transpose x -> [b][n][c] bf16 hi/lo + fused squared norms -----
__global__ void k_split(const float* __restrict__ x) {
    __shared__ float t[32][33];
    __shared__ float sqa[32];
    int b = blockIdx.y, n0 = blockIdx.x * 32;
    int tx = threadIdx.x, ty = threadIdx.y;
    if (ty == 0) sqa[tx] = 0.f;

#pragma unroll 1
    for (int c0 = 0; c0 < Cc; c0 += 32) {
        const float* xb = x + ((size_t)b * Cc + c0) * Nn + n0;
        __syncthreads();                   // t / sqa safe to (re)load
        for (int i = ty; i < 32; i += 8)
            t[i][tx] = xb[(size_t)i * Nn + tx];
        __syncthreads();
        for (int i = ty; i < 32; i += 8) {
            float v = t[tx][i];            // row n0+i, channel c0+tx
            __nv_bfloat16 hi = __float2bfloat16(v);
            float lo = v - __bfloat162float(hi);
            size_t o = ((size_t)b * Nn + n0 + i) * Cc + c0 + tx;
            g_xh[o] = hi;
            g_xl[o] = __float2bfloat16(lo);
            // fused sq: warp-reduce v^2 over the 32 channel lanes of this row
            float ssq = v * v;
#pragma unroll
            for (int off = 16; off; off >>= 1)
                ssq += __shfl_down_sync(0xffffffffu, ssq, off);
            if (tx == 0) sqa[i] += ssq;    // warp ty owns rows {ty, ty+8, ...}: no race
        }
    }
    __syncthreads();
    if (ty == 0) g_sq[(b << 11) + n0 + tx] = sqa[tx];
}

// ---------------- fused distance GEMM + top-k (2 CTAs/SM, 64-row B tiles) -------
__global__ __launch_bounds__(256, 2) void k_distknn() {
    extern __shared__ char sm[];
    uint32_t sb = smem_u32(sm);
    int tid = threadIdx.x, wid = tid >> 5, lane = tid & 31;
    int strip = blockIdx.x, b = blockIdx.y;
    int n0 = strip * 128;
    const __nv_bfloat16* xh = g_xh + ((size_t)b << 11) * Cc;
    const __nv_bfloat16* xl = g_xl + ((size_t)b << 11) * Cc;
    float* s_sqm = (float*)(sm + F2_SQ);

    {
        const float4* src = (const float4*)(g_sq + (b << 11));
        float4* dst = (float4*)s_sqm;
        for (int i = tid; i < 512; i += 256) dst[i] = src[i];
    }
    tile_async(xh + (size_t)n0 * Cc, sb + F2_AH, tid);
    tile_async(xl + (size_t)n0 * Cc, sb + F2_AL, tid);
    tile_async64(xh, sb + F2_BH, tid);
    tile_async64(xl, sb + F2_BL, tid);
    CP_COMMIT();
    CP_WAIT0();
    __syncthreads();

    int rw = wid * 16, r0 = lane >> 2, q = (lane & 3) * 2;
    float acc[8][4];
#pragma unroll
    for (int g = 0; g < 8; g++)
#pragma unroll
        for (int i = 0; i < 4; i++) acc[g][i] = 0.f;

    float bd0[KL], bd1[KL];
    int   bi0[KL], bi1[KL];
#pragma unroll
    for (int i = 0; i < KL; i++) { bd0[i] = BIGF; bd1[i] = BIGF; bi0[i] = 0x7fffffff; bi1[i] = 0x7fffffff; }
    float T0 = BIGF, T1 = BIGF;

    float sn0 = s_sqm[n0 + rw + r0];
    float sn1 = s_sqm[n0 + rw + r0 + 8];
    uint32_t aoff = (uint32_t)((rw + (lane & 15)) * LDB + (lane >> 4) * 16);
    uint32_t boff = (uint32_t)(((lane & 7) + ((lane >> 4) << 3)) * LDB + ((lane >> 3) & 1) * 16);
    uint32_t a_hi = sb + F2_AH, a_lo = sb + F2_AL;
    uint32_t b_hi = sb + F2_BH, b_lo = sb + F2_BL;

#pragma unroll 1
    for (int t = 0; t < 32; t++) {
#pragma unroll
        for (int ks = 0; ks < 8; ks++) {
            uint32_t kb = ks * 32;
            uint32_t ah[4], al[4];
            ldsm4(ah, a_hi + aoff + kb);
            ldsm4(al, a_lo + aoff + kb);
#pragma unroll
            for (int g = 0; g < 4; g++) {
                uint32_t bo = boff + g * (16 * LDB) + kb;
                uint32_t bhx[4], blx[4];
                ldsm4(bhx, b_hi + bo);
                ldsm4(blx, b_lo + bo);
                mma16816(acc[2 * g],     ah, bhx[0], bhx[1]);
                mma16816(acc[2 * g],     ah, blx[0], blx[1]);
                mma16816(acc[2 * g],     al, bhx[0], bhx[1]);
                mma16816(acc[2 * g + 1], ah, bhx[2], bhx[3]);
                mma16816(acc[2 * g + 1], ah, blx[2], blx[3]);
                mma16816(acc[2 * g + 1], al, bhx[2], bhx[3]);
            }
        }
        __syncthreads();                    // all warps done reading B tile t
        if (t < 31) {                       // overwrite B with tile t+1 (async)
            tile_async64(xh + (size_t)(t + 1) * 64 * Cc, b_hi, tid);
            tile_async64(xl + (size_t)(t + 1) * 64 * Cc, b_lo, tid);
            CP_COMMIT();
        }

        // epilogue (overlaps the async loads): d = sqn + sqm - 2*acc; inserts
        int m0 = t * 64;
#pragma unroll
        for (int g = 0; g < 8; g++) {
            int mm = m0 + g * 8 + q;
            float sm0v = s_sqm[mm], sm1v = s_sqm[mm + 1];
            float d00 = fmaf(-2.f, acc[g][0], sn0 + sm0v);
            float d01 = fmaf(-2.f, acc[g][1], sn0 + sm1v);
            float d10 = fmaf(-2.f, acc[g][2], sn1 + sm0v);
            float d11 = fmaf(-2.f, acc[g][3], sn1 + sm1v);
            insert2(bd0, bi0, d00, mm, d01, mm + 1, T0);
            insert2(bd1, bi1, d10, mm, d11, mm + 1, T1);
            acc[g][0] = acc[g][1] = acc[g][2] = acc[g][3] = 0.f;
        }
        // quad threshold: T = max over quad of bd[4]; >=20 union values <= T
        {
            float t0 = bd0[4];
            t0 = fmaxf(t0, __shfl_xor_sync(0xffffffffu, t0, 1, 4));
            t0 = fmaxf(t0, __shfl_xor_sync(0xffffffffu, t0, 2, 4));
            T0 = t0;
            float t1 = bd1[4];
            t1 = fmaxf(t1, __shfl_xor_sync(0xffffffffu, t1, 1, 4));
            t1 = fmaxf(t1, __shfl_xor_sync(0xffffffffu, t1, 2, 4));
            T1 = t1;
        }
        if (t < 31) {
            CP_WAIT0();
            __syncthreads();
        }
    }

    // merge quads -> g_knn; flag exhausted rows for exact redo
    int nbase = (b << 11) + n0 + rw;
    int bad0 = quad_merge(bd0, bi0, lane, nbase + r0);
    int bad1 = quad_merge(bd1, bi1, lane, nbase + r0 + 8);
    unsigned bm0 = __ballot_sync(0xffffffffu, bad0 != 0);
    unsigned bm1 = __ballot_sync(0xffffffffu, bad1 != 0);
    if ((lane & 3) == 0) {
        if ((bm0 >> lane) & 0xFu) { int s = atomicAdd(&g_nfb, 1); g_fbrow[s] = nbase + r0; }
        if ((bm1 >> lane) & 0xFu) { int s = atomicAdd(&g_nfb, 1); g_fbrow[s] = nbase + r0 + 8; }
    }
}

// ---------------- cleanup: exact fp32 top-20 for flagged rows -------------------
// m-loop: 8 lanes per m (lane covers 16 channels), 4 m per warp, width-8 reduce.
__global__ __launch_bounds__(256) void k_fix() {
    __shared__ float xn[Cc];
    __shared__ float sd[Nn];
    int nfb = g_nfb;
    int wid = threadIdx.x >> 5, lane = threadIdx.x & 31;
    int msub = lane >> 3, cl = lane & 7;
    for (int i = blockIdx.x; i < nfb; i += gridDim.x) {
        int rowid = g_fbrow[i];
        int b = rowid >> 11, n = rowid & (Nn - 1);
        const __nv_bfloat16* xh = g_xh + ((size_t)b << 11) * Cc;
        const __nv_bfloat16* xl = g_xl + ((size_t)b << 11) * Cc;
        if (threadIdx.x < Cc)
            xn[threadIdx.x] = __bfloat162float(xh[(size_t)n * Cc + threadIdx.x])
                            + __bfloat162float(xl[(size_t)n * Cc + threadIdx.x]);
        __syncthreads();
        float sqn = g_sq[(b << 11) + n];
#pragma unroll 1
        for (int m0 = wid * 4; m0 < Nn; m0 += 32) {
            int m = m0 + msub;
            const __nv_bfloat162* rh = (const __nv_bfloat162*)(xh + (size_t)m * Cc);
            const __nv_bfloat162* rl = (const __nv_bfloat162*)(xl + (size_t)m * Cc);
            float dot = 0.f;
#pragma unroll
            for (int kk = 0; kk < 8; kk++) {
                __nv_bfloat162 h = rh[cl * 8 + kk];
                __nv_bfloat162 l = rl[cl * 8 + kk];
                int c = cl * 16 + kk * 2;
                dot = fmaf(xn[c],     __bfloat162float(h.x) + __bfloat162float(l.x), dot);
                dot = fmaf(xn[c + 1], __bfloat162float(h.y) + __bfloat162float(l.y), dot);
            }
            dot += __shfl_down_sync(0xffffffffu, dot, 1, 8);
            dot += __shfl_down_sync(0xffffffffu, dot, 2, 8);
            dot += __shfl_down_sync(0xffffffffu, dot, 4, 8);
            if (cl == 0)
                sd[m] = fmaf(-2.f, dot, sqn + g_sq[(b << 11) + m]);
        }
        __syncthreads();
        if (threadIdx.x < 32) {
            int lane2 = threadIdx.x;
            uint64_t best[KK];
#pragma unroll
            for (int ii = 0; ii < KK; ii++) best[ii] = ~0ull;
#pragma unroll 1
            for (int t = 0; t < Nn / 32; t++) {
                int m = t * 32 + lane2;
                uint64_t key = pd_key(sd[m], m);
                if (key < best[KK - 1]) {
#pragma unroll
                    for (int ii = 0; ii < KK; ii++) {
                        uint64_t bv = best[ii];
                        uint64_t lo = (key < bv) ? key : bv;
                        key          = (key < bv) ? bv : key;
                        best[ii] = lo;
                    }
                }
            }
            int p = 0;
            uint64_t cur = best[0];
#pragma unroll 1
            for (int s = 0; s < KK; s++) {
                uint64_t v = cur;
#pragma unroll
                for (int off = 16; off; off >>= 1) {
                    uint64_t ov = __shfl_down_sync(0xffffffffu, v, off);
                    v = (ov < v) ? ov : v;
                }
                v = __shfl_sync(0xffffffffu, v, 0);
                if (lane2 == 0) g_knn[((b << 11) + n) * KK + s] = (int)(uint32_t)v;
                if (cur == v) { p++; cur = (p < KK) ? best[p] : ~0ull; }
            }
        }
        __syncthreads();
    }
}

// ---------------- uv GEMM (2-CTA skeleton): uv[b][n][j] = x[n,:].Wc[j,:] --------
__global__ __launch_bounds__(256, 2) void k_uv_mma() {
    extern __shared__ char sm[];
    uint32_t sb = smem_u32(sm);
    int tid = threadIdx.x, wid = tid >> 5, lane = tid & 31;
    int strip = blockIdx.x, b = blockIdx.y;
    int n0 = strip * 128;
    const __nv_bfloat16* xh = g_xh + ((size_t)b << 11) * Cc;
    const __nv_bfloat16* xl = g_xl + ((size_t)b << 11) * Cc;

    tile_async(xh + (size_t)n0 * Cc, sb + F2_AH, tid);
    tile_async(xl + (size_t)n0 * Cc, sb + F2_AL, tid);
    tile_async64(g_Wch, sb + F2_BH, tid);
    tile_async64(g_Wcl, sb + F2_BL, tid);
    CP_COMMIT();
    CP_WAIT0();
    __syncthreads();

    int rw = wid * 16, r0 = lane >> 2, q = (lane & 3) * 2;
    float acc[8][4];
#pragma unroll
    for (int g = 0; g < 8; g++)
#pragma unroll
        for (int i = 0; i < 4; i++) acc[g][i] = 0.f;

    uint32_t aoff = (uint32_t)((rw + (lane & 15)) * LDB + (lane >> 4) * 16);
    uint32_t boff = (uint32_t)(((lane & 7) + ((lane >> 4) << 3)) * LDB + ((lane >> 3) & 1) * 16);
    uint32_t a_hi = sb + F2_AH, a_lo = sb + F2_AL;
    uint32_t b_hi = sb + F2_BH, b_lo = sb + F2_BL;
    float* uvb = g_uv + (size_t)(b << 11) * (2 * CO);

#pragma unroll 1
    for (int t = 0; t < 8; t++) {
#pragma unroll
        for (int ks = 0; ks < 8; ks++) {
            uint32_t kb = ks * 32;
            uint32_t ah[4], al[4];
            ldsm4(ah, a_hi + aoff + kb);
            ldsm4(al, a_lo + aoff + kb);
#pragma unroll
            for (int g = 0; g < 4; g++) {
                uint32_t bo = boff + g * (16 * LDB) + kb;
                uint32_t bhx[4], blx[4];
                ldsm4(bhx, b_hi + bo);
                ldsm4(blx, b_lo + bo);
                mma16816(acc[2 * g],     ah, bhx[0], bhx[1]);
                mma16816(acc[2 * g],     ah, blx[0], blx[1]);
                mma16816(acc[2 * g],     al, bhx[0], bhx[1]);
                mma16816(acc[2 * g + 1], ah, bhx[2], bhx[3]);
                mma16816(acc[2 * g + 1], ah, blx[2], blx[3]);
                mma16816(acc[2 * g + 1], al, bhx[2], bhx[3]);
            }
        }
        __syncthreads();
        if (t < 7) {
            tile_async64(g_Wch + (size_t)(t + 1) * 64 * Cc, b_hi, tid);
            tile_async64(g_Wcl + (size_t)(t + 1) * 64 * Cc, b_lo, tid);
            CP_COMMIT();
        }

        // epilogue: write uv[n][j] for j-tile t (overlaps async loads)
        int j0 = t * 64;
#pragma unroll
        for (int g = 0; g < 8; g++) {
            int jj = j0 + g * 8 + q;
            int nn = n0 + rw + r0;
            *(float2*)&uvb[(size_t)nn * (2 * CO) + jj] =
                make_float2(acc[g][0], acc[g][1]);
            *(float2*)&uvb[(size_t)(nn + 8) * (2 * CO) + jj] =
                make_float2(acc[g][2], acc[g][3]);
            acc[g][0] = acc[g][1] = acc[g][2] = acc[g][3] = 0.f;
        }
        if (t < 7) {
            CP_WAIT0();
            __syncthreads();
        }
    }
}

// ---------------- gather: y = u + v[knn]; stats + selected extremum -------------
#define NT 32
__global__ __launch_bounds__(256) void k_gather() {
    int blk = blockIdx.x;                  // Bb * (Nn/NT) = 1024 blocks
    int b = blk >> 6;
    int n0 = (blk & 63) * NT;
    int o = threadIdx.x;
    const float* uvb = g_uv + (size_t)b * Nn * (2 * CO);
    int gpos = g_gpos[o];

    __shared__ int sidx[NT * KK];
    for (int i = threadIdx.x; i < NT * KK; i += 256) {
        int nn = i / KK, jj = i % KK;
        sidx[i] = g_knn[((b << 11) + n0 + nn) * KK + jj];
    }
    __syncthreads();

    float s = 0.f, s2 = 0.f;
#pragma unroll 1
    for (int nn = 0; nn < NT; nn++) {
        int n = n0 + nn;
        float uo = uvb[(size_t)n * (2 * CO) + o];
        float mx = -BIGF, mn = BIGF;
#pragma unroll
        for (int j = 0; j < KK; j++) {
            int m = sidx[nn * KK + j];
            float y = uo + uvb[(size_t)m * (2 * CO) + CO + o];
            s += y;
            s2 = fmaf(y, y, s2);
            mx = fmaxf(mx, y);
            mn = fminf(mn, y);
        }
        g_ysel[((size_t)(b << 11) + n) * CO + o] = gpos ? mx : mn;
    }
    int bkt = (blk & (NB - 1)) * CO + o;
    atomicAdd(&g_sum[bkt], (double)s);
    atomicAdd(&g_sumsq[bkt], (double)s2);
}

// ---------------- finalize BN stats ---------------------------------------------
__global__ void k_final(const float* __restrict__ gamma, const float* __restrict__ beta) {
    int o = threadIdx.x;
    double sum = 0.0, sumsq = 0.0;
#pragma unroll
    for (int k = 0; k < NB; k++) { sum += g_sum[k * CO + o]; sumsq += g_sumsq[k * CO + o]; }
    double mean = sum / CNT;
    double var = sumsq / CNT - mean * mean;
    double inv = 1.0 / sqrt(var + 1e-5);
    float sc = (float)((double)gamma[o] * inv);
    g_scale[o] = sc;
    g_shift[o] = beta[o] - (float)(mean * (double)gamma[o] * inv);
}

// ---------------- output: affine + relu + transpose ------------------------------
__global__ void k_out(float* __restrict__ out) {
    __shared__ float tile[32][33];
    int b = blockIdx.z, o0 = blockIdx.y * 32, n0 = blockIdx.x * 32;
    int tx = threadIdx.x, ty = threadIdx.y;

    for (int i = ty; i < 32; i += 8) {
        int n = n0 + i;
        int o = o0 + tx;
        float sc = g_scale[o];
        float v = g_ysel[((size_t)(b << 11) + n) * CO + o];
        float r = fmaf(sc, v, g_shift[o]);
        tile[i][tx] = fmaxf(r, 0.f);
    }
    __syncthreads();
    for (int i = ty; i < 32; i += 8) {
        int o = o0 + i;
        int n = n0 + tx;
        out[((size_t)b * CO + o) * Nn + n] = tile[tx][i];
    }
}

// ---------------- launch ----------------------------------------------------------
extern "C" void kernel_launch(void* const* d_in, const int* in_sizes, int n_in,
                              void* d_out, int out_size) {
    const float* x     = (const float*)d_in[0];
    const float* W     = (const float*)d_in[1];
    const float* gamma = (const float*)d_in[2];
    const float* beta  = (const float*)d_in[3];
    float* out = (float*)d_out;

    cudaFuncSetAttribute(k_distknn, cudaFuncAttributeMaxDynamicSharedMemorySize, F2_DYN);
    cudaFuncSetAttribute(k_uv_mma,  cudaFuncAttributeMaxDynamicSharedMemorySize, F2_DYN);

    k_prep<<<256, 256>>>(W, gamma);
    k_split<<<dim3(Nn / 32, Bb), dim3(32, 8)>>>(x);
    k_distknn<<<dim3(16, Bb), 256, F2_DYN>>>();
    k_fix<<<128, 256>>>();
    k_uv_mma<<<dim3(16, Bb), 256, F2_DYN>>>();
    k_gather<<<Bb * (Nn / NT), 256>>>();
    k_final<<<1, 256>>>(gamma, beta);
    k_out<<<dim3(Nn / 32, CO / 32, Bb), dim3(32, 8)>>>(out);
}

// round 14
// speedup vs baseline: 1.4029x; 1.0251x over previous
#include <cuda_runtime.h>
#include <cuda_bf16.h>
#include <cstdint>

#define Bb 16
#define Cc 128
#define Nn 2048
#define CO 256
#define KK 20
#define KL 12
#define NB 8
#define CNT ((double)(Bb) * (double)(Nn) * (double)(KK))
#define BIGF 1e30f

// ---------------- scratch -----------------------------------------------------
__device__ float          g_sq[Bb * Nn];
__device__ int            g_knn[Bb * Nn * KK];
__device__ __nv_bfloat16  g_xh[(size_t)Bb * Nn * Cc];          // x transposed [b][n][c], hi
__device__ __nv_bfloat16  g_xl[(size_t)Bb * Nn * Cc];          // lo
__device__ __nv_bfloat16  g_Wch[(size_t)2 * CO * Cc];          // Wc [j][c] hi (j<256: W1-W2, else W2)
__device__ __nv_bfloat16  g_Wcl[(size_t)2 * CO * Cc];          // lo
__device__ float          g_uv[(size_t)Bb * Nn * 2 * CO];      // [b][n][0..255]=u, [256..511]=v
__device__ float          g_ysel[(size_t)Bb * Nn * CO];        // selected extremum per (b,n,o)
__device__ int            g_gpos[CO];                          // gamma[o] >= 0
__device__ double         g_sum[NB * CO];
__device__ double         g_sumsq[NB * CO];
__device__ float          g_scale[CO];
__device__ float          g_shift[CO];
__device__ int            g_nfb;
__device__ int            g_fbrow[Bb * Nn];

// ---------------- helpers -----------------------------------------------------
__device__ __forceinline__ uint32_t smem_u32(const void* p) {
    uint32_t a;
    asm("{ .reg .u64 t; cvta.to.shared.u64 t, %1; cvt.u32.u64 %0, t; }" : "=r"(a) : "l"(p));
    return a;
}
__device__ __forceinline__ void ldsm4(uint32_t* r, uint32_t addr) {
    asm volatile("ldmatrix.sync.aligned.m8n8.x4.shared.b16 {%0,%1,%2,%3}, [%4];"
        : "=r"(r[0]), "=r"(r[1]), "=r"(r[2]), "=r"(r[3]) : "r"(addr));
}
__device__ __forceinline__ void mma16816(float* d, const uint32_t* a, uint32_t b0, uint32_t b1) {
    asm volatile("mma.sync.aligned.m16n8k16.row.col.f32.bf16.bf16.f32 "
        "{%0,%1,%2,%3}, {%4,%5,%6,%7}, {%8,%9}, {%0,%1,%2,%3};"
        : "+f"(d[0]), "+f"(d[1]), "+f"(d[2]), "+f"(d[3])
        : "r"(a[0]), "r"(a[1]), "r"(a[2]), "r"(a[3]), "r"(b0), "r"(b1));
}
#define CP16(dst, src) asm volatile("cp.async.cg.shared.global [%0], [%1], 16;" :: "r"(dst), "l"(src))
#define CP_COMMIT()    asm volatile("cp.async.commit_group;" ::: "memory")
#define CP_WAIT0()     asm volatile("cp.async.wait_group 0;" ::: "memory")

// padded smem tile: rows x 128 bf16, row stride 272 bytes (conflict-free ldmatrix)
#define LDB   272
#define TILEB (128 * LDB)          // 34816
#define TILEB64 (64 * LDB)         // 17408

// ---- shared 2-CTA smem layout (distknn + uv) ----
#define F2_AH 0
#define F2_AL TILEB
#define F2_BH (2 * TILEB)                 // 69632
#define F2_BL (2 * TILEB + TILEB64)       // 87040
#define F2_SQ (2 * TILEB + 2 * TILEB64)   // 104448
#define F2_DYN (F2_SQ + 8192)             // 112640

__device__ __forceinline__ void tile_async(const __nv_bfloat16* __restrict__ src,
                                           uint32_t smbase, int tid) {
#pragma unroll
    for (int it = 0; it < 8; it++) {
        int idx = it * 256 + tid;
        int row = idx >> 4, seg = idx & 15;
        CP16(smbase + row * LDB + seg * 16, src + (size_t)row * 128 + seg * 8);
    }
}
__device__ __forceinline__ void tile_async64(const __nv_bfloat16* __restrict__ src,
                                             uint32_t smbase, int tid) {
#pragma unroll
    for (int it = 0; it < 4; it++) {
        int idx = it * 256 + tid;          // 1024 = 64 rows x 16 segs
        int row = idx >> 4, seg = idx & 15;
        CP16(smbase + row * LDB + seg * 16, src + (size_t)row * 128 + seg * 8);
    }
}

// key = (monotone-uint(dist) << 32) | index: lexicographic (dist, idx)
__device__ __forceinline__ uint64_t pd_key(float d, int m) {
    uint32_t b = __float_as_uint(d);
    b ^= ((uint32_t)((int32_t)b >> 31)) | 0x80000000u;
    return ((uint64_t)b << 32) | (uint32_t)m;
}

// paired insert: insert (da,ia),(db,ib) into sorted KL-list in ONE chain pass.
// Values > T are skippable (row-20th <= T proven by quad bound); keep == T.
__device__ __forceinline__ void insert2(float (&bd)[KL], int (&bi)[KL],
                                        float da, int ia, float db, int ib, float T) {
    {
        bool sw = db < da;
        float td = sw ? db : da;  int ti = sw ? ib : ia;
        db = sw ? da : db;        ib = sw ? ia : ib;
        da = td;                  ia = ti;
    }
    if (da < bd[KL - 1] && da <= T) {
#pragma unroll
        for (int i = 0; i < KL; i++) {
            bool lt = da < bd[i];
            float sv = lt ? da : bd[i];
            int   si = lt ? ia : bi[i];
            float c1 = lt ? bd[i] : da;       // displaced candidate
            int   ci = lt ? bi[i] : ia;
            bd[i] = sv; bi[i] = si;
            bool sw = db < c1;                // keep carried pair ordered
            da = sw ? db : c1;  ia = sw ? ib : ci;
            db = sw ? c1 : db;  ib = sw ? ci : ib;
        }
    }
}

// merge one row's 4 per-thread sorted lists (quad of lanes) -> top-20 to g_knn
__device__ __forceinline__ int quad_merge(float (&bd)[KL], int (&bi)[KL],
                                          int lane, int nglob) {
    uint64_t cur = pd_key(bd[0], bi[0]);
    int p = 0;
#pragma unroll 1
    for (int s = 0; s < KK; s++) {
        uint64_t v = cur;
        uint64_t o2 = __shfl_down_sync(0xffffffffu, v, 2, 4); v = o2 < v ? o2 : v;
        uint64_t o1 = __shfl_down_sync(0xffffffffu, v, 1, 4); v = o1 < v ? o1 : v;
        v = __shfl_sync(0xffffffffu, v, 0, 4);
        if ((lane & 3) == 0) g_knn[nglob * KK + s] = (int)(uint32_t)v;
        if (cur == v) {
            p++;
#pragma unroll
            for (int i = 0; i < KL - 1; i++) { bd[i] = bd[i + 1]; bi[i] = bi[i + 1]; }
            bd[KL - 1] = BIGF; bi[KL - 1] = 0x7fffffff;
            cur = pd_key(bd[0], bi[0]);
        }
    }
    return p >= KL ? 1 : 0;
}

// ---------------- prep: weights (folded + split) + zero accumulators ----------
__global__ void k_prep(const float* __restrict__ W, const float* __restrict__ gamma) {
    int tid = blockIdx.x * blockDim.x + threadIdx.x;     // 65536
    int j = tid >> 7, c = tid & 127;
    float w;
    if (j < CO) w = W[j * (2 * Cc) + c] - W[j * (2 * Cc) + Cc + c];
    else        w = W[(j - CO) * (2 * Cc) + Cc + c];
    __nv_bfloat16 hi = __float2bfloat16(w);
    g_Wch[tid] = hi;
    g_Wcl[tid] = __float2bfloat16(w - __bfloat162float(hi));
    if (tid < NB * CO) { g_sum[tid] = 0.0; g_sumsq[tid] = 0.0; }
    if (tid < CO) g_gpos[tid] = (gamma[tid] >= 0.f) ? 1 : 0;
    if (tid == 0) g_nfb = 0;
}

// ---------------- transpose x -> [b][n][c] bf16 hi/lo + fused squared norms -----
__global__ void k_split(const float* __restrict__ x) {
    __shared__ float t[32][33];
    __shared__ float sqa[32];
    int b = blockIdx.y, n0 = blockIdx.x * 32;
    int tx = threadIdx.x, ty = threadIdx.y;
    if (ty == 0) sqa[tx] = 0.f;

#pragma unroll 1
    for (int c0 = 0; c0 < Cc; c0 += 32) {
        const float* xb = x + ((size_t)b * Cc + c0) * Nn + n0;
        __syncthreads();                   // t / sqa safe to (re)load
        for (int i = ty; i < 32; i += 8)
            t[i][tx] = xb[(size_t)i * Nn + tx];
        __syncthreads();
        for (int i = ty; i < 32; i += 8) {
            float v = t[tx][i];            // row n0+i, channel c0+tx
            __nv_bfloat16 hi = __float2bfloat16(v);
            float lo = v - __bfloat162float(hi);
            size_t o = ((size_t)b * Nn + n0 + i) * Cc + c0 + tx;
            g_xh[o] = hi;
            g_xl[o] = __float2bfloat16(lo);
            // fused sq: warp-reduce v^2 over the 32 channel lanes of this row
            float ssq = v * v;
#pragma unroll
            for (int off = 16; off; off >>= 1)
                ssq += __shfl_down_sync(0xffffffffu, ssq, off);
            if (tx == 0) sqa[i] += ssq;    // warp ty owns rows {ty, ty+8, ...}: no race
        }
    }
    __syncthreads();
    if (ty == 0) g_sq[(b << 11) + n0 + tx] = sqa[tx];
}

// ---------------- fused distance GEMM + top-k (2 CTAs/SM, 64-row B tiles) -------
__global__ __launch_bounds__(256, 2) void k_distknn() {
    extern __shared__ char sm[];
    uint32_t sb = smem_u32(sm);
    int tid = threadIdx.x, wid = tid >> 5, lane = tid & 31;
    int strip = blockIdx.x, b = blockIdx.y;
    int n0 = strip * 128;
    const __nv_bfloat16* xh = g_xh + ((size_t)b << 11) * Cc;
    const __nv_bfloat16* xl = g_xl + ((size_t)b << 11) * Cc;
    float* s_sqm = (float*)(sm + F2_SQ);

    {
        const float4* src = (const float4*)(g_sq + (b << 11));
        float4* dst = (float4*)s_sqm;
        for (int i = tid; i < 512; i += 256) dst[i] = src[i];
    }
    tile_async(xh + (size_t)n0 * Cc, sb + F2_AH, tid);
    tile_async(xl + (size_t)n0 * Cc, sb + F2_AL, tid);
    tile_async64(xh, sb + F2_BH, tid);
    tile_async64(xl, sb + F2_BL, tid);
    CP_COMMIT();
    CP_WAIT0();
    __syncthreads();

    int rw = wid * 16, r0 = lane >> 2, q = (lane & 3) * 2;
    float acc[8][4];
#pragma unroll
    for (int g = 0; g < 8; g++)
#pragma unroll
        for (int i = 0; i < 4; i++) acc[g][i] = 0.f;

    float bd0[KL], bd1[KL];
    int   bi0[KL], bi1[KL];
#pragma unroll
    for (int i = 0; i < KL; i++) { bd0[i] = BIGF; bd1[i] = BIGF; bi0[i] = 0x7fffffff; bi1[i] = 0x7fffffff; }
    float T0 = BIGF, T1 = BIGF;

    float sn0 = s_sqm[n0 + rw + r0];
    float sn1 = s_sqm[n0 + rw + r0 + 8];
    uint32_t aoff = (uint32_t)((rw + (lane & 15)) * LDB + (lane >> 4) * 16);
    uint32_t boff = (uint32_t)(((lane & 7) + ((lane >> 4) << 3)) * LDB + ((lane >> 3) & 1) * 16);
    uint32_t a_hi = sb + F2_AH, a_lo = sb + F2_AL;
    uint32_t b_hi = sb + F2_BH, b_lo = sb + F2_BL;

#pragma unroll 1
    for (int t = 0; t < 32; t++) {
#pragma unroll
        for (int ks = 0; ks < 8; ks++) {
            uint32_t kb = ks * 32;
            uint32_t ah[4], al[4];
            ldsm4(ah, a_hi + aoff + kb);
            ldsm4(al, a_lo + aoff + kb);
#pragma unroll
            for (int g = 0; g < 4; g++) {
                uint32_t bo = boff + g * (16 * LDB) + kb;
                uint32_t bhx[4], blx[4];
                ldsm4(bhx, b_hi + bo);
                ldsm4(blx, b_lo + bo);
                mma16816(acc[2 * g],     ah, bhx[0], bhx[1]);
                mma16816(acc[2 * g],     ah, blx[0], blx[1]);
                mma16816(acc[2 * g],     al, bhx[0], bhx[1]);
                mma16816(acc[2 * g + 1], ah, bhx[2], bhx[3]);
                mma16816(acc[2 * g + 1], ah, blx[2], blx[3]);
                mma16816(acc[2 * g + 1], al, bhx[2], bhx[3]);
            }
        }
        __syncthreads();                    // all warps done reading B tile t
        if (t < 31) {                       // overwrite B with tile t+1 (async)
            tile_async64(xh + (size_t)(t + 1) * 64 * Cc, b_hi, tid);
            tile_async64(xl + (size_t)(t + 1) * 64 * Cc, b_lo, tid);
            CP_COMMIT();
        }

        // epilogue (overlaps the async loads): d = sqn + sqm - 2*acc; inserts
        int m0 = t * 64;
#pragma unroll
        for (int g = 0; g < 8; g++) {
            int mm = m0 + g * 8 + q;
            float sm0v = s_sqm[mm], sm1v = s_sqm[mm + 1];
            float d00 = fmaf(-2.f, acc[g][0], sn0 + sm0v);
            float d01 = fmaf(-2.f, acc[g][1], sn0 + sm1v);
            float d10 = fmaf(-2.f, acc[g][2], sn1 + sm0v);
            float d11 = fmaf(-2.f, acc[g][3], sn1 + sm1v);
            insert2(bd0, bi0, d00, mm, d01, mm + 1, T0);
            insert2(bd1, bi1, d10, mm, d11, mm + 1, T1);
            acc[g][0] = acc[g][1] = acc[g][2] = acc[g][3] = 0.f;
        }
        // quad threshold: T = max over quad of bd[4]; >=20 union values <= T
        {
            float t0 = bd0[4];
            t0 = fmaxf(t0, __shfl_xor_sync(0xffffffffu, t0, 1, 4));
            t0 = fmaxf(t0, __shfl_xor_sync(0xffffffffu, t0, 2, 4));
            T0 = t0;
            float t1 = bd1[4];
            t1 = fmaxf(t1, __shfl_xor_sync(0xffffffffu, t1, 1, 4));
            t1 = fmaxf(t1, __shfl_xor_sync(0xffffffffu, t1, 2, 4));
            T1 = t1;
        }
        if (t < 31) {
            CP_WAIT0();
            __syncthreads();
        }
    }

    // merge quads -> g_knn; flag exhausted rows for exact redo
    int nbase = (b << 11) + n0 + rw;
    int bad0 = quad_merge(bd0, bi0, lane, nbase + r0);
    int bad1 = quad_merge(bd1, bi1, lane, nbase + r0 + 8);
    unsigned bm0 = __ballot_sync(0xffffffffu, bad0 != 0);
    unsigned bm1 = __ballot_sync(0xffffffffu, bad1 != 0);
    if ((lane & 3) == 0) {
        if ((bm0 >> lane) & 0xFu) { int s = atomicAdd(&g_nfb, 1); g_fbrow[s] = nbase + r0; }
        if ((bm1 >> lane) & 0xFu) { int s = atomicAdd(&g_nfb, 1); g_fbrow[s] = nbase + r0 + 8; }
    }
}

// ---------------- cleanup: exact fp32 top-20 for flagged rows -------------------
// m-loop: 8 lanes per m (lane covers 16 channels via 2x LDG.128 per array).
__global__ __launch_bounds__(256) void k_fix() {
    __shared__ float xn[Cc];
    __shared__ float sd[Nn];
    int nfb = g_nfb;
    int wid = threadIdx.x >> 5, lane = threadIdx.x & 31;
    int msub = lane >> 3, cl = lane & 7;
    for (int i = blockIdx.x; i < nfb; i += gridDim.x) {
        int rowid = g_fbrow[i];
        int b = rowid >> 11, n = rowid & (Nn - 1);
        const __nv_bfloat16* xh = g_xh + ((size_t)b << 11) * Cc;
        const __nv_bfloat16* xl = g_xl + ((size_t)b << 11) * Cc;
        if (threadIdx.x < Cc)
            xn[threadIdx.x] = __bfloat162float(xh[(size_t)n * Cc + threadIdx.x])
                            + __bfloat162float(xl[(size_t)n * Cc + threadIdx.x]);
        __syncthreads();
        float sqn = g_sq[(b << 11) + n];
#pragma unroll 1
        for (int m0 = wid * 4; m0 < Nn; m0 += 32) {
            int m = m0 + msub;
            const uint4* rh = (const uint4*)(xh + (size_t)m * Cc);  // 16B = 8 bf16
            const uint4* rl = (const uint4*)(xl + (size_t)m * Cc);
            uint4 H0 = rh[cl * 2], H1 = rh[cl * 2 + 1];
            uint4 L0 = rl[cl * 2], L1 = rl[cl * 2 + 1];
            const __nv_bfloat162* h0 = (const __nv_bfloat162*)&H0;
            const __nv_bfloat162* h1 = (const __nv_bfloat162*)&H1;
            const __nv_bfloat162* l0 = (const __nv_bfloat162*)&L0;
            const __nv_bfloat162* l1 = (const __nv_bfloat162*)&L1;
            int c0 = cl * 16;
            float dot = 0.f;
#pragma unroll
            for (int k = 0; k < 4; k++) {
                dot = fmaf(xn[c0 + 2 * k],     __bfloat162float(h0[k].x) + __bfloat162float(l0[k].x), dot);
                dot = fmaf(xn[c0 + 2 * k + 1], __bfloat162float(h0[k].y) + __bfloat162float(l0[k].y), dot);
            }
#pragma unroll
            for (int k = 0; k < 4; k++) {
                dot = fmaf(xn[c0 + 8 + 2 * k],     __bfloat162float(h1[k].x) + __bfloat162float(l1[k].x), dot);
                dot = fmaf(xn[c0 + 8 + 2 * k + 1], __bfloat162float(h1[k].y) + __bfloat162float(l1[k].y), dot);
            }
            dot += __shfl_down_sync(0xffffffffu, dot, 1, 8);
            dot += __shfl_down_sync(0xffffffffu, dot, 2, 8);
            dot += __shfl_down_sync(0xffffffffu, dot, 4, 8);
            if (cl == 0)
                sd[m] = fmaf(-2.f, dot, sqn + g_sq[(b << 11) + m]);
        }
        __syncthreads();
        if (threadIdx.x < 32) {
            int lane2 = threadIdx.x;
            uint64_t best[KK];
#pragma unroll
            for (int ii = 0; ii < KK; ii++) best[ii] = ~0ull;
#pragma unroll 1
            for (int t = 0; t < Nn / 32; t++) {
                int m = t * 32 + lane2;
                uint64_t key = pd_key(sd[m], m);
                if (key < best[KK - 1]) {
#pragma unroll
                    for (int ii = 0; ii < KK; ii++) {
                        uint64_t bv = best[ii];
                        uint64_t lo = (key < bv) ? key : bv;
                        key          = (key < bv) ? bv : key;
                        best[ii] = lo;
                    }
                }
            }
            int p = 0;
            uint64_t cur = best[0];
#pragma unroll 1
            for (int s = 0; s < KK; s++) {
                uint64_t v = cur;
#pragma unroll
                for (int off = 16; off; off >>= 1) {
                    uint64_t ov = __shfl_down_sync(0xffffffffu, v, off);
                    v = (ov < v) ? ov : v;
                }
                v = __shfl_sync(0xffffffffu, v, 0);
                if (lane2 == 0) g_knn[((b << 11) + n) * KK + s] = (int)(uint32_t)v;
                if (cur == v) { p++; cur = (p < KK) ? best[p] : ~0ull; }
            }
        }
        __syncthreads();
    }
}

// ---------------- uv GEMM (2-CTA skeleton): uv[b][n][j] = x[n,:].Wc[j,:] --------
__global__ __launch_bounds__(256, 2) void k_uv_mma() {
    extern __shared__ char sm[];
    uint32_t sb = smem_u32(sm);
    int tid = threadIdx.x, wid = tid >> 5, lane = tid & 31;
    int strip = blockIdx.x, b = blockIdx.y;
    int n0 = strip * 128;
    const __nv_bfloat16* xh = g_xh + ((size_t)b << 11) * Cc;
    const __nv_bfloat16* xl = g_xl + ((size_t)b << 11) * Cc;

    tile_async(xh + (size_t)n0 * Cc, sb + F2_AH, tid);
    tile_async(xl + (size_t)n0 * Cc, sb + F2_AL, tid);
    tile_async64(g_Wch, sb + F2_BH, tid);
    tile_async64(g_Wcl, sb + F2_BL, tid);
    CP_COMMIT();
    CP_WAIT0();
    __syncthreads();

    int rw = wid * 16, r0 = lane >> 2, q = (lane & 3) * 2;
    float acc[8][4];
#pragma unroll
    for (int g = 0; g < 8; g++)
#pragma unroll
        for (int i = 0; i < 4; i++) acc[g][i] = 0.f;

    uint32_t aoff = (uint32_t)((rw + (lane & 15)) * LDB + (lane >> 4) * 16);
    uint32_t boff = (uint32_t)(((lane & 7) + ((lane >> 4) << 3)) * LDB + ((lane >> 3) & 1) * 16);
    uint32_t a_hi = sb + F2_AH, a_lo = sb + F2_AL;
    uint32_t b_hi = sb + F2_BH, b_lo = sb + F2_BL;
    float* uvb = g_uv + (size_t)(b << 11) * (2 * CO);

#pragma unroll 1
    for (int t = 0; t < 8; t++) {
#pragma unroll
        for (int ks = 0; ks < 8; ks++) {
            uint32_t kb = ks * 32;
            uint32_t ah[4], al[4];
            ldsm4(ah, a_hi + aoff + kb);
            ldsm4(al, a_lo + aoff + kb);
#pragma unroll
            for (int g = 0; g < 4; g++) {
                uint32_t bo = boff + g * (16 * LDB) + kb;
                uint32_t bhx[4], blx[4];
                ldsm4(bhx, b_hi + bo);
                ldsm4(blx, b_lo + bo);
                mma16816(acc[2 * g],     ah, bhx[0], bhx[1]);
                mma16816(acc[2 * g],     ah, blx[0], blx[1]);
                mma16816(acc[2 * g],     al, bhx[0], bhx[1]);
                mma16816(acc[2 * g + 1], ah, bhx[2], bhx[3]);
                mma16816(acc[2 * g + 1], ah, blx[2], blx[3]);
                mma16816(acc[2 * g + 1], al, bhx[2], bhx[3]);
            }
        }
        __syncthreads();
        if (t < 7) {
            tile_async64(g_Wch + (size_t)(t + 1) * 64 * Cc, b_hi, tid);
            tile_async64(g_Wcl + (size_t)(t + 1) * 64 * Cc, b_lo, tid);
            CP_COMMIT();
        }

        // epilogue: write uv[n][j] for j-tile t (overlaps async loads)
        int j0 = t * 64;
#pragma unroll
        for (int g = 0; g < 8; g++) {
            int jj = j0 + g * 8 + q;
            int nn = n0 + rw + r0;
            *(float2*)&uvb[(size_t)nn * (2 * CO) + jj] =
                make_float2(acc[g][0], acc[g][1]);
            *(float2*)&uvb[(size_t)(nn + 8) * (2 * CO) + jj] =
                make_float2(acc[g][2], acc[g][3]);
            acc[g][0] = acc[g][1] = acc[g][2] = acc[g][3] = 0.f;
        }
        if (t < 7) {
            CP_WAIT0();
            __syncthreads();
        }
    }
}

// ---------------- gather: y = u + v[knn]; stats + selected extremum -------------
#define NT 32
__global__ __launch_bounds__(256) void k_gather() {
    int blk = blockIdx.x;                  // Bb * (Nn/NT) = 1024 blocks
    int b = blk >> 6;
    int n0 = (blk & 63) * NT;
    int o = threadIdx.x;
    const float* uvb = g_uv + (size_t)b * Nn * (2 * CO);
    int gpos = g_gpos[o];

    __shared__ int sidx[NT * KK];
    for (int i = threadIdx.x; i < NT * KK; i += 256) {
        int nn = i / KK, jj = i % KK;
        sidx[i] = g_knn[((b << 11) + n0 + nn) * KK + jj];
    }
    __syncthreads();

    float s = 0.f, s2 = 0.f;
#pragma unroll 1
    for (int nn = 0; nn < NT; nn++) {
        int n = n0 + nn;
        float uo = uvb[(size_t)n * (2 * CO) + o];
        float mx = -BIGF, mn = BIGF;
#pragma unroll
        for (int j = 0; j < KK; j++) {
            int m = sidx[nn * KK + j];
            float y = uo + uvb[(size_t)m * (2 * CO) + CO + o];
            s += y;
            s2 = fmaf(y, y, s2);
            mx = fmaxf(mx, y);
            mn = fminf(mn, y);
        }
        g_ysel[((size_t)(b << 11) + n) * CO + o] = gpos ? mx : mn;
    }
    int bkt = (blk & (NB - 1)) * CO + o;
    atomicAdd(&g_sum[bkt], (double)s);
    atomicAdd(&g_sumsq[bkt], (double)s2);
}

// ---------------- finalize BN stats ---------------------------------------------
__global__ void k_final(const float* __restrict__ gamma, const float* __restrict__ beta) {
    int o = threadIdx.x;
    double sum = 0.0, sumsq = 0.0;
#pragma unroll
    for (int k = 0; k < NB; k++) { sum += g_sum[k * CO + o]; sumsq += g_sumsq[k * CO + o]; }
    double mean = sum / CNT;
    double var = sumsq / CNT - mean * mean;
    double inv = 1.0 / sqrt(var + 1e-5);
    float sc = (float)((double)gamma[o] * inv);
    g_scale[o] = sc;
    g_shift[o] = beta[o] - (float)(mean * (double)gamma[o] * inv);
}

// ---------------- output: affine + relu + transpose ------------------------------
__global__ void k_out(float* __restrict__ out) {
    __shared__ float tile[32][33];
    int b = blockIdx.z, o0 = blockIdx.y * 32, n0 = blockIdx.x * 32;
    int tx = threadIdx.x, ty = threadIdx.y;

    for (int i = ty; i < 32; i += 8) {
        int n = n0 + i;
        int o = o0 + tx;
        float sc = g_scale[o];
        float v = g_ysel[((size_t)(b << 11) + n) * CO + o];
        float r = fmaf(sc, v, g_shift[o]);
        tile[i][tx] = fmaxf(r, 0.f);
    }
    __syncthreads();
    for (int i = ty; i < 32; i += 8) {
        int o = o0 + i;
        int n = n0 + tx;
        out[((size_t)b * CO + o) * Nn + n] = tile[tx][i];
    }
}

// ---------------- launch ----------------------------------------------------------
extern "C" void kernel_launch(void* const* d_in, const int* in_sizes, int n_in,
                              void* d_out, int out_size) {
    const float* x     = (const float*)d_in[0];
    const float* W     = (const float*)d_in[1];
    const float* gamma = (const float*)d_in[2];
    const float* beta  = (const float*)d_in[3];
    float* out = (float*)d_out;

    cudaFuncSetAttribute(k_distknn, cudaFuncAttributeMaxDynamicSharedMemorySize, F2_DYN);
    cudaFuncSetAttribute(k_uv_mma,  cudaFuncAttributeMaxDynamicSharedMemorySize, F2_DYN);

    k_prep<<<256, 256>>>(W, gamma);
    k_split<<<dim3(Nn / 32, Bb), dim3(32, 8)>>>(x);
    k_distknn<<<dim3(16, Bb), 256, F2_DYN>>>();
    k_fix<<<1024, 256>>>();
    k_uv_mma<<<dim3(16, Bb), 256, F2_DYN>>>();
    k_gather<<<Bb * (Nn / NT), 256>>>();
    k_final<<<1, 256>>>(gamma, beta);
    k_out<<<dim3(Nn / 32, CO / 32, Bb), dim3(32, 8)>>>(out);
}

// round 15
// speedup vs baseline: 1.4323x; 1.0209x over previous
#include <cuda_runtime.h>
#include <cuda_bf16.h>
#include <cstdint>

#define Bb 16
#define Cc 128
#define Nn 2048
#define CO 256
#define KK 20
#define KL 12
#define NB 8
#define CNT ((double)(Bb) * (double)(Nn) * (double)(KK))
#define BIGF 1e30f

// ---------------- scratch -----------------------------------------------------
__device__ float          g_sq[Bb * Nn];
__device__ int            g_knn[Bb * Nn * KK];
__device__ __nv_bfloat16  g_xh[(size_t)Bb * Nn * Cc];          // x transposed [b][n][c], hi
__device__ __nv_bfloat16  g_xl[(size_t)Bb * Nn * Cc];          // lo
__device__ __nv_bfloat16  g_Wch[(size_t)2 * CO * Cc];          // Wc [j][c] hi (j<256: W1-W2, else W2)
__device__ __nv_bfloat16  g_Wcl[(size_t)2 * CO * Cc];          // lo
__device__ float          g_uv[(size_t)Bb * Nn * 2 * CO];      // [b][n][0..255]=u, [256..511]=v
__device__ float          g_ysel[(size_t)Bb * Nn * CO];        // selected extremum per (b,n,o)
__device__ int            g_gpos[CO];                          // gamma[o] >= 0
__device__ double         g_sum[NB * CO];
__device__ double         g_sumsq[NB * CO];
__device__ float          g_scale[CO];
__device__ float          g_shift[CO];
__device__ int            g_nfb;
__device__ int            g_fbrow[Bb * Nn];

// ---------------- helpers -----------------------------------------------------
__device__ __forceinline__ uint32_t smem_u32(const void* p) {
    uint32_t a;
    asm("{ .reg .u64 t; cvta.to.shared.u64 t, %1; cvt.u32.u64 %0, t; }" : "=r"(a) : "l"(p));
    return a;
}
__device__ __forceinline__ void ldsm4(uint32_t* r, uint32_t addr) {
    asm volatile("ldmatrix.sync.aligned.m8n8.x4.shared.b16 {%0,%1,%2,%3}, [%4];"
        : "=r"(r[0]), "=r"(r[1]), "=r"(r[2]), "=r"(r[3]) : "r"(addr));
}
__device__ __forceinline__ void mma16816(float* d, const uint32_t* a, uint32_t b0, uint32_t b1) {
    asm volatile("mma.sync.aligned.m16n8k16.row.col.f32.bf16.bf16.f32 "
        "{%0,%1,%2,%3}, {%4,%5,%6,%7}, {%8,%9}, {%0,%1,%2,%3};"
        : "+f"(d[0]), "+f"(d[1]), "+f"(d[2]), "+f"(d[3])
        : "r"(a[0]), "r"(a[1]), "r"(a[2]), "r"(a[3]), "r"(b0), "r"(b1));
}
#define CP16(dst, src) asm volatile("cp.async.cg.shared.global [%0], [%1], 16;" :: "r"(dst), "l"(src))
#define CP_COMMIT()    asm volatile("cp.async.commit_group;" ::: "memory")
#define CP_WAIT0()     asm volatile("cp.async.wait_group 0;" ::: "memory")

// padded smem tile: rows x 128 bf16, row stride 272 bytes (conflict-free ldmatrix)
#define LDB   272
#define TILEB (128 * LDB)          // 34816
#define TILEB64 (64 * LDB)         // 17408

// ---- shared 2-CTA smem layout (distknn + uv) ----
#define F2_AH 0
#define F2_AL TILEB
#define F2_BH (2 * TILEB)                 // 69632
#define F2_BL (2 * TILEB + TILEB64)       // 87040
#define F2_SQ (2 * TILEB + 2 * TILEB64)   // 104448
#define F2_DYN (F2_SQ + 8192)             // 112640

__device__ __forceinline__ void tile_async(const __nv_bfloat16* __restrict__ src,
                                           uint32_t smbase, int tid) {
#pragma unroll
    for (int it = 0; it < 8; it++) {
        int idx = it * 256 + tid;
        int row = idx >> 4, seg = idx & 15;
        CP16(smbase + row * LDB + seg * 16, src + (size_t)row * 128 + seg * 8);
    }
}
__device__ __forceinline__ void tile_async64(const __nv_bfloat16* __restrict__ src,
                                             uint32_t smbase, int tid) {
#pragma unroll
    for (int it = 0; it < 4; it++) {
        int idx = it * 256 + tid;          // 1024 = 64 rows x 16 segs
        int row = idx >> 4, seg = idx & 15;
        CP16(smbase + row * LDB + seg * 16, src + (size_t)row * 128 + seg * 8);
    }
}

// key = (monotone-uint(dist) << 32) | index: lexicographic (dist, idx)
__device__ __forceinline__ uint64_t pd_key(float d, int m) {
    uint32_t b = __float_as_uint(d);
    b ^= ((uint32_t)((int32_t)b >> 31)) | 0x80000000u;
    return ((uint64_t)b << 32) | (uint32_t)m;
}

// paired insert: insert (da,ia),(db,ib) into sorted KL-list in ONE chain pass.
// Values > T are skippable (row-20th <= T proven by quad bound); keep == T.
__device__ __forceinline__ void insert2(float (&bd)[KL], int (&bi)[KL],
                                        float da, int ia, float db, int ib, float T) {
    {
        bool sw = db < da;
        float td = sw ? db : da;  int ti = sw ? ib : ia;
        db = sw ? da : db;        ib = sw ? ia : ib;
        da = td;                  ia = ti;
    }
    if (da < bd[KL - 1] && da <= T) {
#pragma unroll
        for (int i = 0; i < KL; i++) {
            bool lt = da < bd[i];
            float sv = lt ? da : bd[i];
            int   si = lt ? ia : bi[i];
            float c1 = lt ? bd[i] : da;       // displaced candidate
            int   ci = lt ? bi[i] : ia;
            bd[i] = sv; bi[i] = si;
            bool sw = db < c1;                // keep carried pair ordered
            da = sw ? db : c1;  ia = sw ? ib : ci;
            db = sw ? c1 : db;  ib = sw ? ci : ib;
        }
    }
}

// merge one row's 4 per-thread sorted lists (quad of lanes) -> top-20 to g_knn
__device__ __forceinline__ int quad_merge(float (&bd)[KL], int (&bi)[KL],
                                          int lane, int nglob) {
    uint64_t cur = pd_key(bd[0], bi[0]);
    int p = 0;
#pragma unroll 1
    for (int s = 0; s < KK; s++) {
        uint64_t v = cur;
        uint64_t o2 = __shfl_down_sync(0xffffffffu, v, 2, 4); v = o2 < v ? o2 : v;
        uint64_t o1 = __shfl_down_sync(0xffffffffu, v, 1, 4); v = o1 < v ? o1 : v;
        v = __shfl_sync(0xffffffffu, v, 0, 4);
        if ((lane & 3) == 0) g_knn[nglob * KK + s] = (int)(uint32_t)v;
        if (cur == v) {
            p++;
#pragma unroll
            for (int i = 0; i < KL - 1; i++) { bd[i] = bd[i + 1]; bi[i] = bi[i + 1]; }
            bd[KL - 1] = BIGF; bi[KL - 1] = 0x7fffffff;
            cur = pd_key(bd[0], bi[0]);
        }
    }
    return p >= KL ? 1 : 0;
}

// ---------------- prep: weights (folded + split) + zero accumulators ----------
__global__ void k_prep(const float* __restrict__ W, const float* __restrict__ gamma) {
    int tid = blockIdx.x * blockDim.x + threadIdx.x;     // 65536
    int j = tid >> 7, c = tid & 127;
    float w;
    if (j < CO) w = W[j * (2 * Cc) + c] - W[j * (2 * Cc) + Cc + c];
    else        w = W[(j - CO) * (2 * Cc) + Cc + c];
    __nv_bfloat16 hi = __float2bfloat16(w);
    g_Wch[tid] = hi;
    g_Wcl[tid] = __float2bfloat16(w - __bfloat162float(hi));
    if (tid < NB * CO) { g_sum[tid] = 0.0; g_sumsq[tid] = 0.0; }
    if (tid < CO) g_gpos[tid] = (gamma[tid] >= 0.f) ? 1 : 0;
    if (tid == 0) g_nfb = 0;
}

// ---------------- transpose x -> [b][n][c] bf16 hi/lo + fused squared norms -----
__global__ void k_split(const float* __restrict__ x) {
    __shared__ float t[32][33];
    __shared__ float sqa[32];
    int b = blockIdx.y, n0 = blockIdx.x * 32;
    int tx = threadIdx.x, ty = threadIdx.y;
    if (ty == 0) sqa[tx] = 0.f;

#pragma unroll 1
    for (int c0 = 0; c0 < Cc; c0 += 32) {
        const float* xb = x + ((size_t)b * Cc + c0) * Nn + n0;
        __syncthreads();                   // t / sqa safe to (re)load
        for (int i = ty; i < 32; i += 8)
            t[i][tx] = xb[(size_t)i * Nn + tx];
        __syncthreads();
        for (int i = ty; i < 32; i += 8) {
            float v = t[tx][i];            // row n0+i, channel c0+tx
            __nv_bfloat16 hi = __float2bfloat16(v);
            float lo = v - __bfloat162float(hi);
            size_t o = ((size_t)b * Nn + n0 + i) * Cc + c0 + tx;
            g_xh[o] = hi;
            g_xl[o] = __float2bfloat16(lo);
            // fused sq: warp-reduce v^2 over the 32 channel lanes of this row
            float ssq = v * v;
#pragma unroll
            for (int off = 16; off; off >>= 1)
                ssq += __shfl_down_sync(0xffffffffu, ssq, off);
            if (tx == 0) sqa[i] += ssq;    // warp ty owns rows {ty, ty+8, ...}: no race
        }
    }
    __syncthreads();
    if (ty == 0) g_sq[(b << 11) + n0 + tx] = sqa[tx];
}

// ---------------- fused distance GEMM + top-k (2 CTAs/SM, 64-row B tiles) -------
__global__ __launch_bounds__(256, 2) void k_distknn() {
    extern __shared__ char sm[];
    uint32_t sb = smem_u32(sm);
    int tid = threadIdx.x, wid = tid >> 5, lane = tid & 31;
    int strip = blockIdx.x, b = blockIdx.y;
    int n0 = strip * 128;
    const __nv_bfloat16* xh = g_xh + ((size_t)b << 11) * Cc;
    const __nv_bfloat16* xl = g_xl + ((size_t)b << 11) * Cc;
    float* s_sqm = (float*)(sm + F2_SQ);

    {
        const float4* src = (const float4*)(g_sq + (b << 11));
        float4* dst = (float4*)s_sqm;
        for (int i = tid; i < 512; i += 256) dst[i] = src[i];
    }
    tile_async(xh + (size_t)n0 * Cc, sb + F2_AH, tid);
    tile_async(xl + (size_t)n0 * Cc, sb + F2_AL, tid);
    tile_async64(xh, sb + F2_BH, tid);
    tile_async64(xl, sb + F2_BL, tid);
    CP_COMMIT();
    CP_WAIT0();
    __syncthreads();

    int rw = wid * 16, r0 = lane >> 2, q = (lane & 3) * 2;
    float acc[8][4];
#pragma unroll
    for (int g = 0; g < 8; g++)
#pragma unroll
        for (int i = 0; i < 4; i++) acc[g][i] = 0.f;

    float bd0[KL], bd1[KL];
    int   bi0[KL], bi1[KL];
#pragma unroll
    for (int i = 0; i < KL; i++) { bd0[i] = BIGF; bd1[i] = BIGF; bi0[i] = 0x7fffffff; bi1[i] = 0x7fffffff; }
    float T0 = BIGF, T1 = BIGF;

    float sn0 = s_sqm[n0 + rw + r0];
    float sn1 = s_sqm[n0 + rw + r0 + 8];
    uint32_t aoff = (uint32_t)((rw + (lane & 15)) * LDB + (lane >> 4) * 16);
    uint32_t boff = (uint32_t)(((lane & 7) + ((lane >> 4) << 3)) * LDB + ((lane >> 3) & 1) * 16);
    uint32_t a_hi = sb + F2_AH, a_lo = sb + F2_AL;
    uint32_t b_hi = sb + F2_BH, b_lo = sb + F2_BL;

#pragma unroll 1
    for (int t = 0; t < 32; t++) {
#pragma unroll
        for (int ks = 0; ks < 8; ks++) {
            uint32_t kb = ks * 32;
            uint32_t ah[4], al[4];
            ldsm4(ah, a_hi + aoff + kb);
            ldsm4(al, a_lo + aoff + kb);
#pragma unroll
            for (int g = 0; g < 4; g++) {
                uint32_t bo = boff + g * (16 * LDB) + kb;
                uint32_t bhx[4], blx[4];
                ldsm4(bhx, b_hi + bo);
                ldsm4(blx, b_lo + bo);
                mma16816(acc[2 * g],     ah, bhx[0], bhx[1]);
                mma16816(acc[2 * g],     ah, blx[0], blx[1]);
                mma16816(acc[2 * g],     al, bhx[0], bhx[1]);
                mma16816(acc[2 * g + 1], ah, bhx[2], bhx[3]);
                mma16816(acc[2 * g + 1], ah, blx[2], blx[3]);
                mma16816(acc[2 * g + 1], al, bhx[2], bhx[3]);
            }
        }
        __syncthreads();                    // all warps done reading B tile t
        if (t < 31) {                       // overwrite B with tile t+1 (async)
            tile_async64(xh + (size_t)(t + 1) * 64 * Cc, b_hi, tid);
            tile_async64(xl + (size_t)(t + 1) * 64 * Cc, b_lo, tid);
            CP_COMMIT();
        }

        // epilogue (overlaps the async loads): d = sqn + sqm - 2*acc; inserts
        int m0 = t * 64;
#pragma unroll
        for (int g = 0; g < 8; g++) {
            int mm = m0 + g * 8 + q;
            float sm0v = s_sqm[mm], sm1v = s_sqm[mm + 1];
            float d00 = fmaf(-2.f, acc[g][0], sn0 + sm0v);
            float d01 = fmaf(-2.f, acc[g][1], sn0 + sm1v);
            float d10 = fmaf(-2.f, acc[g][2], sn1 + sm0v);
            float d11 = fmaf(-2.f, acc[g][3], sn1 + sm1v);
            insert2(bd0, bi0, d00, mm, d01, mm + 1, T0);
            insert2(bd1, bi1, d10, mm, d11, mm + 1, T1);
            acc[g][0] = acc[g][1] = acc[g][2] = acc[g][3] = 0.f;
        }
        // quad threshold: T = max over quad of bd[4]; >=20 union values <= T
        {
            float t0 = bd0[4];
            t0 = fmaxf(t0, __shfl_xor_sync(0xffffffffu, t0, 1, 4));
            t0 = fmaxf(t0, __shfl_xor_sync(0xffffffffu, t0, 2, 4));
            T0 = t0;
            float t1 = bd1[4];
            t1 = fmaxf(t1, __shfl_xor_sync(0xffffffffu, t1, 1, 4));
            t1 = fmaxf(t1, __shfl_xor_sync(0xffffffffu, t1, 2, 4));
            T1 = t1;
        }
        if (t < 31) {
            CP_WAIT0();
            __syncthreads();
        }
    }

    // merge quads -> g_knn; flag exhausted rows for exact redo
    int nbase = (b << 11) + n0 + rw;
    int bad0 = quad_merge(bd0, bi0, lane, nbase + r0);
    int bad1 = quad_merge(bd1, bi1, lane, nbase + r0 + 8);
    unsigned bm0 = __ballot_sync(0xffffffffu, bad0 != 0);
    unsigned bm1 = __ballot_sync(0xffffffffu, bad1 != 0);
    if ((lane & 3) == 0) {
        if ((bm0 >> lane) & 0xFu) { int s = atomicAdd(&g_nfb, 1); g_fbrow[s] = nbase + r0; }
        if ((bm1 >> lane) & 0xFu) { int s = atomicAdd(&g_nfb, 1); g_fbrow[s] = nbase + r0 + 8; }
    }
}

// ---------------- cleanup: exact fp32 top-20 for flagged rows -------------------
// m-loop: 8 lanes per m, unrolled x4 so ptxas batches 16 LDG.128 per warp (MLP).
__global__ __launch_bounds__(256) void k_fix() {
    __shared__ float xn[Cc];
    __shared__ float sd[Nn];
    int nfb = g_nfb;
    int wid = threadIdx.x >> 5, lane = threadIdx.x & 31;
    int msub = lane >> 3, cl = lane & 7;
    for (int i = blockIdx.x; i < nfb; i += gridDim.x) {
        int rowid = g_fbrow[i];
        int b = rowid >> 11, n = rowid & (Nn - 1);
        const __nv_bfloat16* xh = g_xh + ((size_t)b << 11) * Cc;
        const __nv_bfloat16* xl = g_xl + ((size_t)b << 11) * Cc;
        if (threadIdx.x < Cc)
            xn[threadIdx.x] = __bfloat162float(xh[(size_t)n * Cc + threadIdx.x])
                            + __bfloat162float(xl[(size_t)n * Cc + threadIdx.x]);
        __syncthreads();
        float sqn = g_sq[(b << 11) + n];
#pragma unroll 4
        for (int m0 = wid * 4; m0 < Nn; m0 += 32) {
            int m = m0 + msub;
            const uint4* rh = (const uint4*)(xh + (size_t)m * Cc);  // 16B = 8 bf16
            const uint4* rl = (const uint4*)(xl + (size_t)m * Cc);
            uint4 H0 = rh[cl * 2], H1 = rh[cl * 2 + 1];
            uint4 L0 = rl[cl * 2], L1 = rl[cl * 2 + 1];
            const __nv_bfloat162* h0 = (const __nv_bfloat162*)&H0;
            const __nv_bfloat162* h1 = (const __nv_bfloat162*)&H1;
            const __nv_bfloat162* l0 = (const __nv_bfloat162*)&L0;
            const __nv_bfloat162* l1 = (const __nv_bfloat162*)&L1;
            int c0 = cl * 16;
            float dot = 0.f;
#pragma unroll
            for (int k = 0; k < 4; k++) {
                dot = fmaf(xn[c0 + 2 * k],     __bfloat162float(h0[k].x) + __bfloat162float(l0[k].x), dot);
                dot = fmaf(xn[c0 + 2 * k + 1], __bfloat162float(h0[k].y) + __bfloat162float(l0[k].y), dot);
            }
#pragma unroll
            for (int k = 0; k < 4; k++) {
                dot = fmaf(xn[c0 + 8 + 2 * k],     __bfloat162float(h1[k].x) + __bfloat162float(l1[k].x), dot);
                dot = fmaf(xn[c0 + 8 + 2 * k + 1], __bfloat162float(h1[k].y) + __bfloat162float(l1[k].y), dot);
            }
            dot += __shfl_down_sync(0xffffffffu, dot, 1, 8);
            dot += __shfl_down_sync(0xffffffffu, dot, 2, 8);
            dot += __shfl_down_sync(0xffffffffu, dot, 4, 8);
            if (cl == 0)
                sd[m] = fmaf(-2.f, dot, sqn + g_sq[(b << 11) + m]);
        }
        __syncthreads();
        if (threadIdx.x < 32) {
            int lane2 = threadIdx.x;
            uint64_t best[KK];
#pragma unroll
            for (int ii = 0; ii < KK; ii++) best[ii] = ~0ull;
#pragma unroll 1
            for (int t = 0; t < Nn / 32; t++) {
                int m = t * 32 + lane2;
                uint64_t key = pd_key(sd[m], m);
                if (key < best[KK - 1]) {
#pragma unroll
                    for (int ii = 0; ii < KK; ii++) {
                        uint64_t bv = best[ii];
                        uint64_t lo = (key < bv) ? key : bv;
                        key          = (key < bv) ? bv : key;
                        best[ii] = lo;
                    }
                }
            }
            int p = 0;
            uint64_t cur = best[0];
#pragma unroll 1
            for (int s = 0; s < KK; s++) {
                uint64_t v = cur;
#pragma unroll
                for (int off = 16; off; off >>= 1) {
                    uint64_t ov = __shfl_down_sync(0xffffffffu, v, off);
                    v = (ov < v) ? ov : v;
                }
                v = __shfl_sync(0xffffffffu, v, 0);
                if (lane2 == 0) g_knn[((b << 11) + n) * KK + s] = (int)(uint32_t)v;
                if (cur == v) { p++; cur = (p < KK) ? best[p] : ~0ull; }
            }
        }
        __syncthreads();
    }
}

// ---------------- uv GEMM (2-CTA skeleton): uv[b][n][j] = x[n,:].Wc[j,:] --------
__global__ __launch_bounds__(256, 2) void k_uv_mma() {
    extern __shared__ char sm[];
    uint32_t sb = smem_u32(sm);
    int tid = threadIdx.x, wid = tid >> 5, lane = tid & 31;
    int strip = blockIdx.x, b = blockIdx.y;
    int n0 = strip * 128;
    const __nv_bfloat16* xh = g_xh + ((size_t)b << 11) * Cc;
    const __nv_bfloat16* xl = g_xl + ((size_t)b << 11) * Cc;

    tile_async(xh + (size_t)n0 * Cc, sb + F2_AH, tid);
    tile_async(xl + (size_t)n0 * Cc, sb + F2_AL, tid);
    tile_async64(g_Wch, sb + F2_BH, tid);
    tile_async64(g_Wcl, sb + F2_BL, tid);
    CP_COMMIT();
    CP_WAIT0();
    __syncthreads();

    int rw = wid * 16, r0 = lane >> 2, q = (lane & 3) * 2;
    float acc[8][4];
#pragma unroll
    for (int g = 0; g < 8; g++)
#pragma unroll
        for (int i = 0; i < 4; i++) acc[g][i] = 0.f;

    uint32_t aoff = (uint32_t)((rw + (lane & 15)) * LDB + (lane >> 4) * 16);
    uint32_t boff = (uint32_t)(((lane & 7) + ((lane >> 4) << 3)) * LDB + ((lane >> 3) & 1) * 16);
    uint32_t a_hi = sb + F2_AH, a_lo = sb + F2_AL;
    uint32_t b_hi = sb + F2_BH, b_lo = sb + F2_BL;
    float* uvb = g_uv + (size_t)(b << 11) * (2 * CO);

#pragma unroll 1
    for (int t = 0; t < 8; t++) {
#pragma unroll
        for (int ks = 0; ks < 8; ks++) {
            uint32_t kb = ks * 32;
            uint32_t ah[4], al[4];
            ldsm4(ah, a_hi + aoff + kb);
            ldsm4(al, a_lo + aoff + kb);
#pragma unroll
            for (int g = 0; g < 4; g++) {
                uint32_t bo = boff + g * (16 * LDB) + kb;
                uint32_t bhx[4], blx[4];
                ldsm4(bhx, b_hi + bo);
                ldsm4(blx, b_lo + bo);
                mma16816(acc[2 * g],     ah, bhx[0], bhx[1]);
                mma16816(acc[2 * g],     ah, blx[0], blx[1]);
                mma16816(acc[2 * g],     al, bhx[0], bhx[1]);
                mma16816(acc[2 * g + 1], ah, bhx[2], bhx[3]);
                mma16816(acc[2 * g + 1], ah, blx[2], blx[3]);
                mma16816(acc[2 * g + 1], al, bhx[2], bhx[3]);
            }
        }
        __syncthreads();
        if (t < 7) {
            tile_async64(g_Wch + (size_t)(t + 1) * 64 * Cc, b_hi, tid);
            tile_async64(g_Wcl + (size_t)(t + 1) * 64 * Cc, b_lo, tid);
            CP_COMMIT();
        }

        // epilogue: write uv[n][j] for j-tile t (overlaps async loads)
        int j0 = t * 64;
#pragma unroll
        for (int g = 0; g < 8; g++) {
            int jj = j0 + g * 8 + q;
            int nn = n0 + rw + r0;
            *(float2*)&uvb[(size_t)nn * (2 * CO) + jj] =
                make_float2(acc[g][0], acc[g][1]);
            *(float2*)&uvb[(size_t)(nn + 8) * (2 * CO) + jj] =
                make_float2(acc[g][2], acc[g][3]);
            acc[g][0] = acc[g][1] = acc[g][2] = acc[g][3] = 0.f;
        }
        if (t < 7) {
            CP_WAIT0();
            __syncthreads();
        }
    }
}

// ---------------- gather: y = u + v[knn]; stats + selected extremum -------------
#define NT 32
__global__ __launch_bounds__(256) void k_gather() {
    int blk = blockIdx.x;                  // Bb * (Nn/NT) = 1024 blocks
    int b = blk >> 6;
    int n0 = (blk & 63) * NT;
    int o = threadIdx.x;
    const float* uvb = g_uv + (size_t)b * Nn * (2 * CO);
    int gpos = g_gpos[o];

    __shared__ int sidx[NT * KK];
    for (int i = threadIdx.x; i < NT * KK; i += 256) {
        int nn = i / KK, jj = i % KK;
        sidx[i] = g_knn[((b << 11) + n0 + nn) * KK + jj];
    }
    __syncthreads();

    float s = 0.f, s2 = 0.f;
#pragma unroll 1
    for (int nn = 0; nn < NT; nn++) {
        int n = n0 + nn;
        float uo = uvb[(size_t)n * (2 * CO) + o];
        float mx = -BIGF, mn = BIGF;
#pragma unroll
        for (int j = 0; j < KK; j++) {
            int m = sidx[nn * KK + j];
            float y = uo + uvb[(size_t)m * (2 * CO) + CO + o];
            s += y;
            s2 = fmaf(y, y, s2);
            mx = fmaxf(mx, y);
            mn = fminf(mn, y);
        }
        g_ysel[((size_t)(b << 11) + n) * CO + o] = gpos ? mx : mn;
    }
    int bkt = (blk & (NB - 1)) * CO + o;
    atomicAdd(&g_sum[bkt], (double)s);
    atomicAdd(&g_sumsq[bkt], (double)s2);
}

// ---------------- finalize BN stats ---------------------------------------------
__global__ void k_final(const float* __restrict__ gamma, const float* __restrict__ beta) {
    int o = threadIdx.x;
    double sum = 0.0, sumsq = 0.0;
#pragma unroll
    for (int k = 0; k < NB; k++) { sum += g_sum[k * CO + o]; sumsq += g_sumsq[k * CO + o]; }
    double mean = sum / CNT;
    double var = sumsq / CNT - mean * mean;
    double inv = 1.0 / sqrt(var + 1e-5);
    float sc = (float)((double)gamma[o] * inv);
    g_scale[o] = sc;
    g_shift[o] = beta[o] - (float)(mean * (double)gamma[o] * inv);
}

// ---------------- output: affine + relu + transpose ------------------------------
__global__ void k_out(float* __restrict__ out) {
    __shared__ float tile[32][33];
    int b = blockIdx.z, o0 = blockIdx.y * 32, n0 = blockIdx.x * 32;
    int tx = threadIdx.x, ty = threadIdx.y;

    for (int i = ty; i < 32; i += 8) {
        int n = n0 + i;
        int o = o0 + tx;
        float sc = g_scale[o];
        float v = g_ysel[((size_t)(b << 11) + n) * CO + o];
        float r = fmaf(sc, v, g_shift[o]);
        tile[i][tx] = fmaxf(r, 0.f);
    }
    __syncthreads();
    for (int i = ty; i < 32; i += 8) {
        int o = o0 + i;
        int n = n0 + tx;
        out[((size_t)b * CO + o) * Nn + n] = tile[tx][i];
    }
}

// ---------------- launch ----------------------------------------------------------
extern "C" void kernel_launch(void* const* d_in, const int* in_sizes, int n_in,
                              void* d_out, int out_size) {
    const float* x     = (const float*)d_in[0];
    const float* W     = (const float*)d_in[1];
    const float* gamma = (const float*)d_in[2];
    const float* beta  = (const float*)d_in[3];
    float* out = (float*)d_out;

    cudaFuncSetAttribute(k_distknn, cudaFuncAttributeMaxDynamicSharedMemorySize, F2_DYN);
    cudaFuncSetAttribute(k_uv_mma,  cudaFuncAttributeMaxDynamicSharedMemorySize, F2_DYN);

    k_prep<<<256, 256>>>(W, gamma);
    k_split<<<dim3(Nn / 32, Bb), dim3(32, 8)>>>(x);
    k_distknn<<<dim3(16, Bb), 256, F2_DYN>>>();
    k_fix<<<1024, 256>>>();
    k_uv_mma<<<dim3(16, Bb), 256, F2_DYN>>>();
    k_gather<<<Bb * (Nn / NT), 256>>>();
    k_final<<<1, 256>>>(gamma, beta);
    k_out<<<dim3(Nn / 32, CO / 32, Bb), dim3(32, 8)>>>(out);
}

// round 16
// speedup vs baseline: 1.4966x; 1.0449x over previous
#include <cuda_runtime.h>
#include <cuda_bf16.h>
#include <cstdint>

#define Bb 16
#define Cc 128
#define Nn 2048
#define CO 256
#define KK 20
#define KL 12
#define NB 8
#define CNT ((double)(Bb) * (double)(Nn) * (double)(KK))
#define BIGF 1e30f

// ---------------- scratch -----------------------------------------------------
__device__ float          g_sq[Bb * Nn];
__device__ int            g_knn[Bb * Nn * KK];
__device__ __nv_bfloat16  g_xh[(size_t)Bb * Nn * Cc];          // x transposed [b][n][c], hi
__device__ __nv_bfloat16  g_xl[(size_t)Bb * Nn * Cc];          // lo
__device__ __nv_bfloat16  g_Wch[(size_t)2 * CO * Cc];          // Wc [j][c] hi (j<256: W1-W2, else W2)
__device__ __nv_bfloat16  g_Wcl[(size_t)2 * CO * Cc];          // lo
__device__ float          g_uv[(size_t)Bb * Nn * 2 * CO];      // [b][n][0..255]=u, [256..511]=v
__device__ float          g_ysel[(size_t)Bb * Nn * CO];        // selected extremum per (b,n,o)
__device__ int            g_gpos[CO];                          // gamma[o] >= 0
__device__ double         g_sum[NB * CO];
__device__ double         g_sumsq[NB * CO];
__device__ float          g_scale[CO];
__device__ float          g_shift[CO];
__device__ int            g_nfb;
__device__ int            g_fbrow[Bb * Nn];

// ---------------- helpers -----------------------------------------------------
__device__ __forceinline__ uint32_t smem_u32(const void* p) {
    uint32_t a;
    asm("{ .reg .u64 t; cvta.to.shared.u64 t, %1; cvt.u32.u64 %0, t; }" : "=r"(a) : "l"(p));
    return a;
}
__device__ __forceinline__ void ldsm4(uint32_t* r, uint32_t addr) {
    asm volatile("ldmatrix.sync.aligned.m8n8.x4.shared.b16 {%0,%1,%2,%3}, [%4];"
        : "=r"(r[0]), "=r"(r[1]), "=r"(r[2]), "=r"(r[3]) : "r"(addr));
}
__device__ __forceinline__ void mma16816(float* d, const uint32_t* a, uint32_t b0, uint32_t b1) {
    asm volatile("mma.sync.aligned.m16n8k16.row.col.f32.bf16.bf16.f32 "
        "{%0,%1,%2,%3}, {%4,%5,%6,%7}, {%8,%9}, {%0,%1,%2,%3};"
        : "+f"(d[0]), "+f"(d[1]), "+f"(d[2]), "+f"(d[3])
        : "r"(a[0]), "r"(a[1]), "r"(a[2]), "r"(a[3]), "r"(b0), "r"(b1));
}
#define CP16(dst, src) asm volatile("cp.async.cg.shared.global [%0], [%1], 16;" :: "r"(dst), "l"(src))
#define CP_COMMIT()    asm volatile("cp.async.commit_group;" ::: "memory")
#define CP_WAIT0()     asm volatile("cp.async.wait_group 0;" ::: "memory")

// padded smem tile: rows x 128 bf16, row stride 272 bytes (conflict-free ldmatrix)
#define LDB   272
#define TILEB (128 * LDB)          // 34816
#define TILEB64 (64 * LDB)         // 17408

// ---- shared 2-CTA smem layout (distknn + uv) ----
#define F2_AH 0
#define F2_AL TILEB
#define F2_BH (2 * TILEB)                 // 69632
#define F2_BL (2 * TILEB + TILEB64)       // 87040
#define F2_SQ (2 * TILEB + 2 * TILEB64)   // 104448
#define F2_DYN (F2_SQ + 8192)             // 112640

__device__ __forceinline__ void tile_async(const __nv_bfloat16* __restrict__ src,
                                           uint32_t smbase, int tid) {
#pragma unroll
    for (int it = 0; it < 8; it++) {
        int idx = it * 256 + tid;
        int row = idx >> 4, seg = idx & 15;
        CP16(smbase + row * LDB + seg * 16, src + (size_t)row * 128 + seg * 8);
    }
}
__device__ __forceinline__ void tile_async64(const __nv_bfloat16* __restrict__ src,
                                             uint32_t smbase, int tid) {
#pragma unroll
    for (int it = 0; it < 4; it++) {
        int idx = it * 256 + tid;          // 1024 = 64 rows x 16 segs
        int row = idx >> 4, seg = idx & 15;
        CP16(smbase + row * LDB + seg * 16, src + (size_t)row * 128 + seg * 8);
    }
}

// key = (monotone-uint(dist) << 32) | index: lexicographic (dist, idx)
__device__ __forceinline__ uint64_t pd_key(float d, int m) {
    uint32_t b = __float_as_uint(d);
    b ^= ((uint32_t)((int32_t)b >> 31)) | 0x80000000u;
    return ((uint64_t)b << 32) | (uint32_t)m;
}

// paired insert: insert (da,ia),(db,ib) into sorted KL-list in ONE chain pass.
// Values > T are skippable (row-20th <= T proven by quad bound); keep == T.
__device__ __forceinline__ void insert2(float (&bd)[KL], int (&bi)[KL],
                                        float da, int ia, float db, int ib, float T) {
    {
        bool sw = db < da;
        float td = sw ? db : da;  int ti = sw ? ib : ia;
        db = sw ? da : db;        ib = sw ? ia : ib;
        da = td;                  ia = ti;
    }
    if (da < bd[KL - 1] && da <= T) {
#pragma unroll
        for (int i = 0; i < KL; i++) {
            bool lt = da < bd[i];
            float sv = lt ? da : bd[i];
            int   si = lt ? ia : bi[i];
            float c1 = lt ? bd[i] : da;       // displaced candidate
            int   ci = lt ? bi[i] : ia;
            bd[i] = sv; bi[i] = si;
            bool sw = db < c1;                // keep carried pair ordered
            da = sw ? db : c1;  ia = sw ? ib : ci;
            db = sw ? c1 : db;  ib = sw ? ci : ib;
        }
    }
}

// merge one row's 4 per-thread sorted lists (quad of lanes) -> top-20 to g_knn
__device__ __forceinline__ int quad_merge(float (&bd)[KL], int (&bi)[KL],
                                          int lane, int nglob) {
    uint64_t cur = pd_key(bd[0], bi[0]);
    int p = 0;
#pragma unroll 1
    for (int s = 0; s < KK; s++) {
        uint64_t v = cur;
        uint64_t o2 = __shfl_down_sync(0xffffffffu, v, 2, 4); v = o2 < v ? o2 : v;
        uint64_t o1 = __shfl_down_sync(0xffffffffu, v, 1, 4); v = o1 < v ? o1 : v;
        v = __shfl_sync(0xffffffffu, v, 0, 4);
        if ((lane & 3) == 0) g_knn[nglob * KK + s] = (int)(uint32_t)v;
        if (cur == v) {
            p++;
#pragma unroll
            for (int i = 0; i < KL - 1; i++) { bd[i] = bd[i + 1]; bi[i] = bi[i + 1]; }
            bd[KL - 1] = BIGF; bi[KL - 1] = 0x7fffffff;
            cur = pd_key(bd[0], bi[0]);
        }
    }
    return p >= KL ? 1 : 0;
}

// ---------------- prep: weights (folded + split) + zero accumulators ----------
__global__ void k_prep(const float* __restrict__ W, const float* __restrict__ gamma) {
    int tid = blockIdx.x * blockDim.x + threadIdx.x;     // 65536
    int j = tid >> 7, c = tid & 127;
    float w;
    if (j < CO) w = W[j * (2 * Cc) + c] - W[j * (2 * Cc) + Cc + c];
    else        w = W[(j - CO) * (2 * Cc) + Cc + c];
    __nv_bfloat16 hi = __float2bfloat16(w);
    g_Wch[tid] = hi;
    g_Wcl[tid] = __float2bfloat16(w - __bfloat162float(hi));
    if (tid < NB * CO) { g_sum[tid] = 0.0; g_sumsq[tid] = 0.0; }
    if (tid < CO) g_gpos[tid] = (gamma[tid] >= 0.f) ? 1 : 0;
    if (tid == 0) g_nfb = 0;
}

// ---------------- transpose x -> [b][n][c] bf16 hi/lo + fused squared norms -----
__global__ void k_split(const float* __restrict__ x) {
    __shared__ float t[32][33];
    __shared__ float sqa[32];
    int b = blockIdx.y, n0 = blockIdx.x * 32;
    int tx = threadIdx.x, ty = threadIdx.y;
    if (ty == 0) sqa[tx] = 0.f;

#pragma unroll 1
    for (int c0 = 0; c0 < Cc; c0 += 32) {
        const float* xb = x + ((size_t)b * Cc + c0) * Nn + n0;
        __syncthreads();
        for (int i = ty; i < 32; i += 8)
            t[i][tx] = xb[(size_t)i * Nn + tx];
        __syncthreads();
        for (int i = ty; i < 32; i += 8) {
            float v = t[tx][i];
            __nv_bfloat16 hi = __float2bfloat16(v);
            float lo = v - __bfloat162float(hi);
            size_t o = ((size_t)b * Nn + n0 + i) * Cc + c0 + tx;
            g_xh[o] = hi;
            g_xl[o] = __float2bfloat16(lo);
            float ssq = v * v;
#pragma unroll
            for (int off = 16; off; off >>= 1)
                ssq += __shfl_down_sync(0xffffffffu, ssq, off);
            if (tx == 0) sqa[i] += ssq;
        }
    }
    __syncthreads();
    if (ty == 0) g_sq[(b << 11) + n0 + tx] = sqa[tx];
}

// ---------------- fused distance GEMM + top-k (2 CTAs/SM, 64-row B tiles) -------
__global__ __launch_bounds__(256, 2) void k_distknn() {
    extern __shared__ char sm[];
    uint32_t sb = smem_u32(sm);
    int tid = threadIdx.x, wid = tid >> 5, lane = tid & 31;
    int strip = blockIdx.x, b = blockIdx.y;
    int n0 = strip * 128;
    const __nv_bfloat16* xh = g_xh + ((size_t)b << 11) * Cc;
    const __nv_bfloat16* xl = g_xl + ((size_t)b << 11) * Cc;
    float* s_sqm = (float*)(sm + F2_SQ);

    {
        const float4* src = (const float4*)(g_sq + (b << 11));
        float4* dst = (float4*)s_sqm;
        for (int i = tid; i < 512; i += 256) dst[i] = src[i];
    }
    tile_async(xh + (size_t)n0 * Cc, sb + F2_AH, tid);
    tile_async(xl + (size_t)n0 * Cc, sb + F2_AL, tid);
    tile_async64(xh, sb + F2_BH, tid);
    tile_async64(xl, sb + F2_BL, tid);
    CP_COMMIT();
    CP_WAIT0();
    __syncthreads();

    int rw = wid * 16, r0 = lane >> 2, q = (lane & 3) * 2;
    float acc[8][4];
#pragma unroll
    for (int g = 0; g < 8; g++)
#pragma unroll
        for (int i = 0; i < 4; i++) acc[g][i] = 0.f;

    float bd0[KL], bd1[KL];
    int   bi0[KL], bi1[KL];
#pragma unroll
    for (int i = 0; i < KL; i++) { bd0[i] = BIGF; bd1[i] = BIGF; bi0[i] = 0x7fffffff; bi1[i] = 0x7fffffff; }
    float T0 = BIGF, T1 = BIGF;

    float sn0 = s_sqm[n0 + rw + r0];
    float sn1 = s_sqm[n0 + rw + r0 + 8];
    uint32_t aoff = (uint32_t)((rw + (lane & 15)) * LDB + (lane >> 4) * 16);
    uint32_t boff = (uint32_t)(((lane & 7) + ((lane >> 4) << 3)) * LDB + ((lane >> 3) & 1) * 16);
    uint32_t a_hi = sb + F2_AH, a_lo = sb + F2_AL;
    uint32_t b_hi = sb + F2_BH, b_lo = sb + F2_BL;

#pragma unroll 1
    for (int t = 0; t < 32; t++) {
#pragma unroll
        for (int ks = 0; ks < 8; ks++) {
            uint32_t kb = ks * 32;
            uint32_t ah[4], al[4];
            ldsm4(ah, a_hi + aoff + kb);
            ldsm4(al, a_lo + aoff + kb);
#pragma unroll
            for (int g = 0; g < 4; g++) {
                uint32_t bo = boff + g * (16 * LDB) + kb;
                uint32_t bhx[4], blx[4];
                ldsm4(bhx, b_hi + bo);
                ldsm4(blx, b_lo + bo);
                mma16816(acc[2 * g],     ah, bhx[0], bhx[1]);
                mma16816(acc[2 * g],     ah, blx[0], blx[1]);
                mma16816(acc[2 * g],     al, bhx[0], bhx[1]);
                mma16816(acc[2 * g + 1], ah, bhx[2], bhx[3]);
                mma16816(acc[2 * g + 1], ah, blx[2], blx[3]);
                mma16816(acc[2 * g + 1], al, bhx[2], bhx[3]);
            }
        }
        __syncthreads();                    // all warps done reading B tile t
        if (t < 31) {                       // overwrite B with tile t+1 (async)
            tile_async64(xh + (size_t)(t + 1) * 64 * Cc, b_hi, tid);
            tile_async64(xl + (size_t)(t + 1) * 64 * Cc, b_lo, tid);
            CP_COMMIT();
        }

        // epilogue (overlaps the async loads): d = sqn + sqm - 2*acc; inserts
        int m0 = t * 64;
#pragma unroll
        for (int g = 0; g < 8; g++) {
            int mm = m0 + g * 8 + q;
            float sm0v = s_sqm[mm], sm1v = s_sqm[mm + 1];
            float d00 = fmaf(-2.f, acc[g][0], sn0 + sm0v);
            float d01 = fmaf(-2.f, acc[g][1], sn0 + sm1v);
            float d10 = fmaf(-2.f, acc[g][2], sn1 + sm0v);
            float d11 = fmaf(-2.f, acc[g][3], sn1 + sm1v);
            insert2(bd0, bi0, d00, mm, d01, mm + 1, T0);
            insert2(bd1, bi1, d10, mm, d11, mm + 1, T1);
            acc[g][0] = acc[g][1] = acc[g][2] = acc[g][3] = 0.f;
        }
        // quad threshold: T = max over quad of bd[4]; >=20 union values <= T
        {
            float t0 = bd0[4];
            t0 = fmaxf(t0, __shfl_xor_sync(0xffffffffu, t0, 1, 4));
            t0 = fmaxf(t0, __shfl_xor_sync(0xffffffffu, t0, 2, 4));
            T0 = t0;
            float t1 = bd1[4];
            t1 = fmaxf(t1, __shfl_xor_sync(0xffffffffu, t1, 1, 4));
            t1 = fmaxf(t1, __shfl_xor_sync(0xffffffffu, t1, 2, 4));
            T1 = t1;
        }
        if (t < 31) {
            CP_WAIT0();
            __syncthreads();
        }
    }

    // merge quads -> g_knn; flag exhausted rows for exact redo
    int nbase = (b << 11) + n0 + rw;
    int bad0 = quad_merge(bd0, bi0, lane, nbase + r0);
    int bad1 = quad_merge(bd1, bi1, lane, nbase + r0 + 8);
    unsigned bm0 = __ballot_sync(0xffffffffu, bad0 != 0);
    unsigned bm1 = __ballot_sync(0xffffffffu, bad1 != 0);
    if ((lane & 3) == 0) {
        if ((bm0 >> lane) & 0xFu) { int s = atomicAdd(&g_nfb, 1); g_fbrow[s] = nbase + r0; }
        if ((bm1 >> lane) & 0xFu) { int s = atomicAdd(&g_nfb, 1); g_fbrow[s] = nbase + r0 + 8; }
    }
}

// ---------------- cleanup: exact fp32 top-20 for flagged rows -------------------
// 512 threads: 16 warps on dots; scan split over warps 0-3; warp 0 final merge.
__global__ __launch_bounds__(512) void k_fix() {
    __shared__ float xn[Cc];
    __shared__ float sd[Nn];
    __shared__ uint64_t s_cand[4 * KK];
    int nfb = g_nfb;
    int wid = threadIdx.x >> 5, lane = threadIdx.x & 31;
    int msub = lane >> 3, cl = lane & 7;
    for (int i = blockIdx.x; i < nfb; i += gridDim.x) {
        int rowid = g_fbrow[i];
        int b = rowid >> 11, n = rowid & (Nn - 1);
        const __nv_bfloat16* xh = g_xh + ((size_t)b << 11) * Cc;
        const __nv_bfloat16* xl = g_xl + ((size_t)b << 11) * Cc;
        if (threadIdx.x < Cc)
            xn[threadIdx.x] = __bfloat162float(xh[(size_t)n * Cc + threadIdx.x])
                            + __bfloat162float(xl[(size_t)n * Cc + threadIdx.x]);
        __syncthreads();
        float sqn = g_sq[(b << 11) + n];
        // dots: 16 warps, 8 lanes per m, vectorized LDG.128
#pragma unroll 4
        for (int m0 = wid * 4; m0 < Nn; m0 += 64) {
            int m = m0 + msub;
            const uint4* rh = (const uint4*)(xh + (size_t)m * Cc);
            const uint4* rl = (const uint4*)(xl + (size_t)m * Cc);
            uint4 H0 = rh[cl * 2], H1 = rh[cl * 2 + 1];
            uint4 L0 = rl[cl * 2], L1 = rl[cl * 2 + 1];
            const __nv_bfloat162* h0 = (const __nv_bfloat162*)&H0;
            const __nv_bfloat162* h1 = (const __nv_bfloat162*)&H1;
            const __nv_bfloat162* l0 = (const __nv_bfloat162*)&L0;
            const __nv_bfloat162* l1 = (const __nv_bfloat162*)&L1;
            int c0 = cl * 16;
            float dot = 0.f;
#pragma unroll
            for (int k = 0; k < 4; k++) {
                dot = fmaf(xn[c0 + 2 * k],     __bfloat162float(h0[k].x) + __bfloat162float(l0[k].x), dot);
                dot = fmaf(xn[c0 + 2 * k + 1], __bfloat162float(h0[k].y) + __bfloat162float(l0[k].y), dot);
            }
#pragma unroll
            for (int k = 0; k < 4; k++) {
                dot = fmaf(xn[c0 + 8 + 2 * k],     __bfloat162float(h1[k].x) + __bfloat162float(l1[k].x), dot);
                dot = fmaf(xn[c0 + 8 + 2 * k + 1], __bfloat162float(h1[k].y) + __bfloat162float(l1[k].y), dot);
            }
            dot += __shfl_down_sync(0xffffffffu, dot, 1, 8);
            dot += __shfl_down_sync(0xffffffffu, dot, 2, 8);
            dot += __shfl_down_sync(0xffffffffu, dot, 4, 8);
            if (cl == 0)
                sd[m] = fmaf(-2.f, dot, sqn + g_sq[(b << 11) + m]);
        }
        __syncthreads();
        // scan: warps 0-3, warp w over sd[w*512 .. w*512+511]; lane holds 16 values
        if (wid < 4) {
            uint64_t lst[16];
#pragma unroll
            for (int ii = 0; ii < 16; ii++) lst[ii] = ~0ull;
#pragma unroll 1
            for (int t = 0; t < 16; t++) {
                int m = wid * 512 + t * 32 + lane;
                uint64_t key = pd_key(sd[m], m);
#pragma unroll
                for (int ii = 0; ii < 16; ii++) {
                    uint64_t bv = lst[ii];
                    uint64_t lo = (key < bv) ? key : bv;
                    key          = (key < bv) ? bv : key;
                    lst[ii] = lo;
                }
            }
            // pop this warp's top-20 into s_cand (sorted)
            uint64_t cur = lst[0];
#pragma unroll 1
            for (int s = 0; s < KK; s++) {
                uint64_t v = cur;
#pragma unroll
                for (int off = 16; off; off >>= 1) {
                    uint64_t ov = __shfl_down_sync(0xffffffffu, v, off);
                    v = (ov < v) ? ov : v;
                }
                v = __shfl_sync(0xffffffffu, v, 0);
                if (lane == 0) s_cand[wid * KK + s] = v;
                if (cur == v) {
#pragma unroll
                    for (int ii = 0; ii < 15; ii++) lst[ii] = lst[ii + 1];
                    lst[15] = ~0ull;
                    cur = lst[0];
                }
            }
        }
        __syncthreads();
        // final merge: warp 0 over 80 candidates (lane holds <=3, sorted)
        if (wid == 0) {
            uint64_t a = s_cand[lane];
            uint64_t bb = (lane + 32 < 4 * KK) ? s_cand[lane + 32] : ~0ull;
            uint64_t c = (lane + 64 < 4 * KK) ? s_cand[lane + 64] : ~0ull;
            uint64_t t;
            if (bb < a) { t = a; a = bb; bb = t; }
            if (c < bb) { t = bb; bb = c; c = t; }
            if (bb < a) { t = a; a = bb; bb = t; }
            uint64_t cur = a;
#pragma unroll 1
            for (int s = 0; s < KK; s++) {
                uint64_t v = cur;
#pragma unroll
                for (int off = 16; off; off >>= 1) {
                    uint64_t ov = __shfl_down_sync(0xffffffffu, v, off);
                    v = (ov < v) ? ov : v;
                }
                v = __shfl_sync(0xffffffffu, v, 0);
                if (lane == 0) g_knn[((b << 11) + n) * KK + s] = (int)(uint32_t)v;
                if (cur == v) { a = bb; bb = c; c = ~0ull; cur = a; }
            }
        }
        __syncthreads();
    }
}

// ---------------- uv GEMM (2-CTA skeleton): uv[b][n][j] = x[n,:].Wc[j,:] --------
__global__ __launch_bounds__(256, 2) void k_uv_mma() {
    extern __shared__ char sm[];
    uint32_t sb = smem_u32(sm);
    int tid = threadIdx.x, wid = tid >> 5, lane = tid & 31;
    int strip = blockIdx.x, b = blockIdx.y;
    int n0 = strip * 128;
    const __nv_bfloat16* xh = g_xh + ((size_t)b << 11) * Cc;
    const __nv_bfloat16* xl = g_xl + ((size_t)b << 11) * Cc;

    tile_async(xh + (size_t)n0 * Cc, sb + F2_AH, tid);
    tile_async(xl + (size_t)n0 * Cc, sb + F2_AL, tid);
    tile_async64(g_Wch, sb + F2_BH, tid);
    tile_async64(g_Wcl, sb + F2_BL, tid);
    CP_COMMIT();
    CP_WAIT0();
    __syncthreads();

    int rw = wid * 16, r0 = lane >> 2, q = (lane & 3) * 2;
    float acc[8][4];
#pragma unroll
    for (int g = 0; g < 8; g++)
#pragma unroll
        for (int i = 0; i < 4; i++) acc[g][i] = 0.f;

    uint32_t aoff = (uint32_t)((rw + (lane & 15)) * LDB + (lane >> 4) * 16);
    uint32_t boff = (uint32_t)(((lane & 7) + ((lane >> 4) << 3)) * LDB + ((lane >> 3) & 1) * 16);
    uint32_t a_hi = sb + F2_AH, a_lo = sb + F2_AL;
    uint32_t b_hi = sb + F2_BH, b_lo = sb + F2_BL;
    float* uvb = g_uv + (size_t)(b << 11) * (2 * CO);

#pragma unroll 1
    for (int t = 0; t < 8; t++) {
#pragma unroll
        for (int ks = 0; ks < 8; ks++) {
            uint32_t kb = ks * 32;
            uint32_t ah[4], al[4];
            ldsm4(ah, a_hi + aoff + kb);
            ldsm4(al, a_lo + aoff + kb);
#pragma unroll
            for (int g = 0; g < 4; g++) {
                uint32_t bo = boff + g * (16 * LDB) + kb;
                uint32_t bhx[4], blx[4];
                ldsm4(bhx, b_hi + bo);
                ldsm4(blx, b_lo + bo);
                mma16816(acc[2 * g],     ah, bhx[0], bhx[1]);
                mma16816(acc[2 * g],     ah, blx[0], blx[1]);
                mma16816(acc[2 * g],     al, bhx[0], bhx[1]);
                mma16816(acc[2 * g + 1], ah, bhx[2], bhx[3]);
                mma16816(acc[2 * g + 1], ah, blx[2], blx[3]);
                mma16816(acc[2 * g + 1], al, bhx[2], bhx[3]);
            }
        }
        __syncthreads();
        if (t < 7) {
            tile_async64(g_Wch + (size_t)(t + 1) * 64 * Cc, b_hi, tid);
            tile_async64(g_Wcl + (size_t)(t + 1) * 64 * Cc, b_lo, tid);
            CP_COMMIT();
        }

        int j0 = t * 64;
#pragma unroll
        for (int g = 0; g < 8; g++) {
            int jj = j0 + g * 8 + q;
            int nn = n0 + rw + r0;
            *(float2*)&uvb[(size_t)nn * (2 * CO) + jj] =
                make_float2(acc[g][0], acc[g][1]);
            *(float2*)&uvb[(size_t)(nn + 8) * (2 * CO) + jj] =
                make_float2(acc[g][2], acc[g][3]);
            acc[g][0] = acc[g][1] = acc[g][2] = acc[g][3] = 0.f;
        }
        if (t < 7) {
            CP_WAIT0();
            __syncthreads();
        }
    }
}

// ---------------- gather: y = u + v[knn]; stats + selected extremum -------------
#define NT 32
__global__ __launch_bounds__(256) void k_gather() {
    int blk = blockIdx.x;
    int b = blk >> 6;
    int n0 = (blk & 63) * NT;
    int o = threadIdx.x;
    const float* uvb = g_uv + (size_t)b * Nn * (2 * CO);
    int gpos = g_gpos[o];

    __shared__ int sidx[NT * KK];
    for (int i = threadIdx.x; i < NT * KK; i += 256) {
        int nn = i / KK, jj = i % KK;
        sidx[i] = g_knn[((b << 11) + n0 + nn) * KK + jj];
    }
    __syncthreads();

    float s = 0.f, s2 = 0.f;
#pragma unroll 1
    for (int nn = 0; nn < NT; nn++) {
        int n = n0 + nn;
        float uo = uvb[(size_t)n * (2 * CO) + o];
        float mx = -BIGF, mn = BIGF;
#pragma unroll
        for (int j = 0; j < KK; j++) {
            int m = sidx[nn * KK + j];
            float y = uo + uvb[(size_t)m * (2 * CO) + CO + o];
            s += y;
            s2 = fmaf(y, y, s2);
            mx = fmaxf(mx, y);
            mn = fminf(mn, y);
        }
        g_ysel[((size_t)(b << 11) + n) * CO + o] = gpos ? mx : mn;
    }
    int bkt = (blk & (NB - 1)) * CO + o;
    atomicAdd(&g_sum[bkt], (double)s);
    atomicAdd(&g_sumsq[bkt], (double)s2);
}

// ---------------- finalize BN stats ---------------------------------------------
__global__ void k_final(const float* __restrict__ gamma, const float* __restrict__ beta) {
    int o = threadIdx.x;
    double sum = 0.0, sumsq = 0.0;
#pragma unroll
    for (int k = 0; k < NB; k++) { sum += g_sum[k * CO + o]; sumsq += g_sumsq[k * CO + o]; }
    double mean = sum / CNT;
    double var = sumsq / CNT - mean * mean;
    double inv = 1.0 / sqrt(var + 1e-5);
    float sc = (float)((double)gamma[o] * inv);
    g_scale[o] = sc;
    g_shift[o] = beta[o] - (float)(mean * (double)gamma[o] * inv);
}

// ---------------- output: affine + relu + transpose ------------------------------
__global__ void k_out(float* __restrict__ out) {
    __shared__ float tile[32][33];
    int b = blockIdx.z, o0 = blockIdx.y * 32, n0 = blockIdx.x * 32;
    int tx = threadIdx.x, ty = threadIdx.y;

    for (int i = ty; i < 32; i += 8) {
        int n = n0 + i;
        int o = o0 + tx;
        float sc = g_scale[o];
        float v = g_ysel[((size_t)(b << 11) + n) * CO + o];
        float r = fmaf(sc, v, g_shift[o]);
        tile[i][tx] = fmaxf(r, 0.f);
    }
    __syncthreads();
    for (int i = ty; i < 32; i += 8) {
        int o = o0 + i;
        int n = n0 + tx;
        out[((size_t)b * CO + o) * Nn + n] = tile[tx][i];
    }
}

// ---------------- launch ----------------------------------------------------------
extern "C" void kernel_launch(void* const* d_in, const int* in_sizes, int n_in,
                              void* d_out, int out_size) {
    const float* x     = (const float*)d_in[0];
    const float* W     = (const float*)d_in[1];
    const float* gamma = (const float*)d_in[2];
    const float* beta  = (const float*)d_in[3];
    float* out = (float*)d_out;

    static cudaStream_t s2 = nullptr;
    static cudaEvent_t ev1 = nullptr, ev2 = nullptr;
    static int tried = 0;
    if (!tried) {
        tried = 1;
        if (cudaStreamCreateWithFlags(&s2, cudaStreamNonBlocking) != cudaSuccess) s2 = nullptr;
        if (s2) {
            if (cudaEventCreateWithFlags(&ev1, cudaEventDisableTiming) != cudaSuccess ||
                cudaEventCreateWithFlags(&ev2, cudaEventDisableTiming) != cudaSuccess) {
                s2 = nullptr;
            }
        }
    }

    cudaFuncSetAttribute(k_distknn, cudaFuncAttributeMaxDynamicSharedMemorySize, F2_DYN);
    cudaFuncSetAttribute(k_uv_mma,  cudaFuncAttributeMaxDynamicSharedMemorySize, F2_DYN);

    k_prep<<<256, 256>>>(W, gamma);
    k_split<<<dim3(Nn / 32, Bb), dim3(32, 8)>>>(x);

    if (s2) {
        // fork: uv runs concurrently with distknn + fix (it only needs split/prep outputs)
        cudaEventRecord(ev1, 0);
        cudaStreamWaitEvent(s2, ev1, 0);
        k_uv_mma<<<dim3(16, Bb), 256, F2_DYN, s2>>>();
        cudaEventRecord(ev2, s2);
        k_distknn<<<dim3(16, Bb), 256, F2_DYN>>>();
        k_fix<<<256, 512>>>();
        cudaStreamWaitEvent(0, ev2, 0);   // join before gather
    } else {
        k_distknn<<<dim3(16, Bb), 256, F2_DYN>>>();
        k_fix<<<256, 512>>>();
        k_uv_mma<<<dim3(16, Bb), 256, F2_DYN>>>();
    }

    k_gather<<<Bb * (Nn / NT), 256>>>();
    k_final<<<1, 256>>>(gamma, beta);
    k_out<<<dim3(Nn / 32, CO / 32, Bb), dim3(32, 8)>>>(out);
}

// round 17
// speedup vs baseline: 1.5755x; 1.0527x over previous
#include <cuda_runtime.h>
#include <cuda_bf16.h>
#include <cstdint>

#define Bb 16
#define Cc 128
#define Nn 2048
#define CO 256
#define KK 20
#define KL 12
#define NB 8
#define CNT ((double)(Bb) * (double)(Nn) * (double)(KK))
#define BIGF 1e30f

// ---------------- scratch -----------------------------------------------------
__device__ float          g_sq[Bb * Nn];
__device__ int            g_knn[Bb * Nn * KK];
__device__ __nv_bfloat16  g_xh[(size_t)Bb * Nn * Cc];          // x transposed [b][n][c], hi
__device__ __nv_bfloat16  g_xl[(size_t)Bb * Nn * Cc];          // lo
__device__ __nv_bfloat16  g_Wch[(size_t)2 * CO * Cc];          // Wc [j][c] hi (j<256: W1-W2, else W2)
__device__ __nv_bfloat16  g_Wcl[(size_t)2 * CO * Cc];          // lo
__device__ float          g_uv[(size_t)Bb * Nn * 2 * CO];      // [b][n][0..255]=u, [256..511]=v
__device__ float          g_ysel[(size_t)Bb * Nn * CO];        // selected extremum per (b,n,o)
__device__ int            g_gpos[CO];                          // gamma[o] >= 0
__device__ double         g_sum[NB * CO];
__device__ double         g_sumsq[NB * CO];
__device__ float          g_scale[CO];
__device__ float          g_shift[CO];
__device__ int            g_nfb;
__device__ int            g_fbrow[Bb * Nn];

// ---------------- helpers -----------------------------------------------------
__device__ __forceinline__ uint32_t smem_u32(const void* p) {
    uint32_t a;
    asm("{ .reg .u64 t; cvta.to.shared.u64 t, %1; cvt.u32.u64 %0, t; }" : "=r"(a) : "l"(p));
    return a;
}
__device__ __forceinline__ void ldsm4(uint32_t* r, uint32_t addr) {
    asm volatile("ldmatrix.sync.aligned.m8n8.x4.shared.b16 {%0,%1,%2,%3}, [%4];"
        : "=r"(r[0]), "=r"(r[1]), "=r"(r[2]), "=r"(r[3]) : "r"(addr));
}
__device__ __forceinline__ void mma16816(float* d, const uint32_t* a, uint32_t b0, uint32_t b1) {
    asm volatile("mma.sync.aligned.m16n8k16.row.col.f32.bf16.bf16.f32 "
        "{%0,%1,%2,%3}, {%4,%5,%6,%7}, {%8,%9}, {%0,%1,%2,%3};"
        : "+f"(d[0]), "+f"(d[1]), "+f"(d[2]), "+f"(d[3])
        : "r"(a[0]), "r"(a[1]), "r"(a[2]), "r"(a[3]), "r"(b0), "r"(b1));
}
#define CP16(dst, src) asm volatile("cp.async.cg.shared.global [%0], [%1], 16;" :: "r"(dst), "l"(src))
#define CP_COMMIT()    asm volatile("cp.async.commit_group;" ::: "memory")
#define CP_WAIT0()     asm volatile("cp.async.wait_group 0;" ::: "memory")

// padded smem tile: rows x 128 bf16, row stride 272 bytes (conflict-free ldmatrix)
#define LDB   272
#define TILEB (128 * LDB)          // 34816
#define TILEB64 (64 * LDB)         // 17408

// ---- shared 2-CTA smem layout (distknn + uv) ----
#define F2_AH 0
#define F2_AL TILEB
#define F2_BH (2 * TILEB)                 // 69632
#define F2_BL (2 * TILEB + TILEB64)       // 87040
#define F2_SQ (2 * TILEB + 2 * TILEB64)   // 104448
#define F2_DYN (F2_SQ + 8192)             // 112640

__device__ __forceinline__ void tile_async(const __nv_bfloat16* __restrict__ src,
                                           uint32_t smbase, int tid) {
#pragma unroll
    for (int it = 0; it < 8; it++) {
        int idx = it * 256 + tid;
        int row = idx >> 4, seg = idx & 15;
        CP16(smbase + row * LDB + seg * 16, src + (size_t)row * 128 + seg * 8);
    }
}
__device__ __forceinline__ void tile_async64(const __nv_bfloat16* __restrict__ src,
                                             uint32_t smbase, int tid) {
#pragma unroll
    for (int it = 0; it < 4; it++) {
        int idx = it * 256 + tid;          // 1024 = 64 rows x 16 segs
        int row = idx >> 4, seg = idx & 15;
        CP16(smbase + row * LDB + seg * 16, src + (size_t)row * 128 + seg * 8);
    }
}

// key = (monotone-uint(dist) << 32) | index: lexicographic (dist, idx)
__device__ __forceinline__ uint64_t pd_key(float d, int m) {
    uint32_t b = __float_as_uint(d);
    b ^= ((uint32_t)((int32_t)b >> 31)) | 0x80000000u;
    return ((uint64_t)b << 32) | (uint32_t)m;
}

// paired insert: insert (da,ia),(db,ib) into sorted KL-list in ONE chain pass.
// Values > T are skippable (row-20th <= T proven by quad bound); keep == T.
__device__ __forceinline__ void insert2(float (&bd)[KL], int (&bi)[KL],
                                        float da, int ia, float db, int ib, float T) {
    {
        bool sw = db < da;
        float td = sw ? db : da;  int ti = sw ? ib : ia;
        db = sw ? da : db;        ib = sw ? ia : ib;
        da = td;                  ia = ti;
    }
    if (da < bd[KL - 1] && da <= T) {
#pragma unroll
        for (int i = 0; i < KL; i++) {
            bool lt = da < bd[i];
            float sv = lt ? da : bd[i];
            int   si = lt ? ia : bi[i];
            float c1 = lt ? bd[i] : da;       // displaced candidate
            int   ci = lt ? bi[i] : ia;
            bd[i] = sv; bi[i] = si;
            bool sw = db < c1;                // keep carried pair ordered
            da = sw ? db : c1;  ia = sw ? ib : ci;
            db = sw ? c1 : db;  ib = sw ? ci : ib;
        }
    }
}

// merge one row's 4 per-thread sorted lists (quad of lanes) -> top-20 to g_knn
__device__ __forceinline__ int quad_merge(float (&bd)[KL], int (&bi)[KL],
                                          int lane, int nglob) {
    uint64_t cur = pd_key(bd[0], bi[0]);
    int p = 0;
#pragma unroll 1
    for (int s = 0; s < KK; s++) {
        uint64_t v = cur;
        uint64_t o2 = __shfl_down_sync(0xffffffffu, v, 2, 4); v = o2 < v ? o2 : v;
        uint64_t o1 = __shfl_down_sync(0xffffffffu, v, 1, 4); v = o1 < v ? o1 : v;
        v = __shfl_sync(0xffffffffu, v, 0, 4);
        if ((lane & 3) == 0) g_knn[nglob * KK + s] = (int)(uint32_t)v;
        if (cur == v) {
            p++;
#pragma unroll
            for (int i = 0; i < KL - 1; i++) { bd[i] = bd[i + 1]; bi[i] = bi[i + 1]; }
            bd[KL - 1] = BIGF; bi[KL - 1] = 0x7fffffff;
            cur = pd_key(bd[0], bi[0]);
        }
    }
    return p >= KL ? 1 : 0;
}

// ---------------- prep: weights (folded + split) + zero accumulators ----------
__global__ void k_prep(const float* __restrict__ W, const float* __restrict__ gamma) {
    int tid = blockIdx.x * blockDim.x + threadIdx.x;     // 65536
    int j = tid >> 7, c = tid & 127;
    float w;
    if (j < CO) w = W[j * (2 * Cc) + c] - W[j * (2 * Cc) + Cc + c];
    else        w = W[(j - CO) * (2 * Cc) + Cc + c];
    __nv_bfloat16 hi = __float2bfloat16(w);
    g_Wch[tid] = hi;
    g_Wcl[tid] = __float2bfloat16(w - __bfloat162float(hi));
    if (tid < NB * CO) { g_sum[tid] = 0.0; g_sumsq[tid] = 0.0; }
    if (tid < CO) g_gpos[tid] = (gamma[tid] >= 0.f) ? 1 : 0;
    if (tid == 0) g_nfb = 0;
}

// ---------------- transpose x -> [b][n][c] bf16 hi/lo + fused squared norms -----
__global__ void k_split(const float* __restrict__ x) {
    __shared__ float t[32][33];
    __shared__ float sqa[32];
    int b = blockIdx.y, n0 = blockIdx.x * 32;
    int tx = threadIdx.x, ty = threadIdx.y;
    if (ty == 0) sqa[tx] = 0.f;

#pragma unroll 1
    for (int c0 = 0; c0 < Cc; c0 += 32) {
        const float* xb = x + ((size_t)b * Cc + c0) * Nn + n0;
        __syncthreads();
        for (int i = ty; i < 32; i += 8)
            t[i][tx] = xb[(size_t)i * Nn + tx];
        __syncthreads();
        for (int i = ty; i < 32; i += 8) {
            float v = t[tx][i];
            __nv_bfloat16 hi = __float2bfloat16(v);
            float lo = v - __bfloat162float(hi);
            size_t o = ((size_t)b * Nn + n0 + i) * Cc + c0 + tx;
            g_xh[o] = hi;
            g_xl[o] = __float2bfloat16(lo);
            float ssq = v * v;
#pragma unroll
            for (int off = 16; off; off >>= 1)
                ssq += __shfl_down_sync(0xffffffffu, ssq, off);
            if (tx == 0) sqa[i] += ssq;
        }
    }
    __syncthreads();
    if (ty == 0) g_sq[(b << 11) + n0 + tx] = sqa[tx];
}

// ---------------- fused distance GEMM + top-k (2 CTAs/SM, 64-row B tiles) -------
__global__ __launch_bounds__(256, 2) void k_distknn() {
    extern __shared__ char sm[];
    uint32_t sb = smem_u32(sm);
    int tid = threadIdx.x, wid = tid >> 5, lane = tid & 31;
    int strip = blockIdx.x, b = blockIdx.y;
    int n0 = strip * 128;
    const __nv_bfloat16* xh = g_xh + ((size_t)b << 11) * Cc;
    const __nv_bfloat16* xl = g_xl + ((size_t)b << 11) * Cc;
    float* s_sqm = (float*)(sm + F2_SQ);

    {
        const float4* src = (const float4*)(g_sq + (b << 11));
        float4* dst = (float4*)s_sqm;
        for (int i = tid; i < 512; i += 256) dst[i] = src[i];
    }
    tile_async(xh + (size_t)n0 * Cc, sb + F2_AH, tid);
    tile_async(xl + (size_t)n0 * Cc, sb + F2_AL, tid);
    tile_async64(xh, sb + F2_BH, tid);
    tile_async64(xl, sb + F2_BL, tid);
    CP_COMMIT();
    CP_WAIT0();
    __syncthreads();

    int rw = wid * 16, r0 = lane >> 2, q = (lane & 3) * 2;
    float acc[8][4];
#pragma unroll
    for (int g = 0; g < 8; g++)
#pragma unroll
        for (int i = 0; i < 4; i++) acc[g][i] = 0.f;

    float bd0[KL], bd1[KL];
    int   bi0[KL], bi1[KL];
#pragma unroll
    for (int i = 0; i < KL; i++) { bd0[i] = BIGF; bd1[i] = BIGF; bi0[i] = 0x7fffffff; bi1[i] = 0x7fffffff; }
    float T0 = BIGF, T1 = BIGF;

    float sn0 = s_sqm[n0 + rw + r0];
    float sn1 = s_sqm[n0 + rw + r0 + 8];
    uint32_t aoff = (uint32_t)((rw + (lane & 15)) * LDB + (lane >> 4) * 16);
    uint32_t boff = (uint32_t)(((lane & 7) + ((lane >> 4) << 3)) * LDB + ((lane >> 3) & 1) * 16);
    uint32_t a_hi = sb + F2_AH, a_lo = sb + F2_AL;
    uint32_t b_hi = sb + F2_BH, b_lo = sb + F2_BL;

#pragma unroll 1
    for (int t = 0; t < 32; t++) {
#pragma unroll
        for (int ks = 0; ks < 8; ks++) {
            uint32_t kb = ks * 32;
            uint32_t ah[4], al[4];
            ldsm4(ah, a_hi + aoff + kb);
            ldsm4(al, a_lo + aoff + kb);
#pragma unroll
            for (int g = 0; g < 4; g++) {
                uint32_t bo = boff + g * (16 * LDB) + kb;
                uint32_t bhx[4], blx[4];
                ldsm4(bhx, b_hi + bo);
                ldsm4(blx, b_lo + bo);
                mma16816(acc[2 * g],     ah, bhx[0], bhx[1]);
                mma16816(acc[2 * g],     ah, blx[0], blx[1]);
                mma16816(acc[2 * g],     al, bhx[0], bhx[1]);
                mma16816(acc[2 * g + 1], ah, bhx[2], bhx[3]);
                mma16816(acc[2 * g + 1], ah, blx[2], blx[3]);
                mma16816(acc[2 * g + 1], al, bhx[2], bhx[3]);
            }
        }
        __syncthreads();                    // all warps done reading B tile t
        if (t < 31) {                       // overwrite B with tile t+1 (async)
            tile_async64(xh + (size_t)(t + 1) * 64 * Cc, b_hi, tid);
            tile_async64(xl + (size_t)(t + 1) * 64 * Cc, b_lo, tid);
            CP_COMMIT();
        }

        // epilogue (overlaps the async loads): d = sqn + sqm - 2*acc; inserts
        int m0 = t * 64;
#pragma unroll
        for (int g = 0; g < 8; g++) {
            int mm = m0 + g * 8 + q;
            float sm0v = s_sqm[mm], sm1v = s_sqm[mm + 1];
            float d00 = fmaf(-2.f, acc[g][0], sn0 + sm0v);
            float d01 = fmaf(-2.f, acc[g][1], sn0 + sm1v);
            float d10 = fmaf(-2.f, acc[g][2], sn1 + sm0v);
            float d11 = fmaf(-2.f, acc[g][3], sn1 + sm1v);
            insert2(bd0, bi0, d00, mm, d01, mm + 1, T0);
            insert2(bd1, bi1, d10, mm, d11, mm + 1, T1);
            acc[g][0] = acc[g][1] = acc[g][2] = acc[g][3] = 0.f;
        }
        // quad threshold: T = max over quad of bd[4]; >=20 union values <= T
        {
            float t0 = bd0[4];
            t0 = fmaxf(t0, __shfl_xor_sync(0xffffffffu, t0, 1, 4));
            t0 = fmaxf(t0, __shfl_xor_sync(0xffffffffu, t0, 2, 4));
            T0 = t0;
            float t1 = bd1[4];
            t1 = fmaxf(t1, __shfl_xor_sync(0xffffffffu, t1, 1, 4));
            t1 = fmaxf(t1, __shfl_xor_sync(0xffffffffu, t1, 2, 4));
            T1 = t1;
        }
        if (t < 31) {
            CP_WAIT0();
            __syncthreads();
        }
    }

    // merge quads -> g_knn; flag exhausted rows for exact redo
    int nbase = (b << 11) + n0 + rw;
    int bad0 = quad_merge(bd0, bi0, lane, nbase + r0);
    int bad1 = quad_merge(bd1, bi1, lane, nbase + r0 + 8);
    unsigned bm0 = __ballot_sync(0xffffffffu, bad0 != 0);
    unsigned bm1 = __ballot_sync(0xffffffffu, bad1 != 0);
    if ((lane & 3) == 0) {
        if ((bm0 >> lane) & 0xFu) { int s = atomicAdd(&g_nfb, 1); g_fbrow[s] = nbase + r0; }
        if ((bm1 >> lane) & 0xFu) { int s = atomicAdd(&g_nfb, 1); g_fbrow[s] = nbase + r0 + 8; }
    }
}

// ---------------- cleanup: exact fp32 top-20 for flagged rows -------------------
// 512 threads: 16 warps on dots; scan split over warps 0-3; warp 0 final merge.
__global__ __launch_bounds__(512) void k_fix() {
    __shared__ float xn[Cc];
    __shared__ float sd[Nn];
    __shared__ uint64_t s_cand[4 * KK];
    int nfb = g_nfb;
    int wid = threadIdx.x >> 5, lane = threadIdx.x & 31;
    int msub = lane >> 3, cl = lane & 7;
    for (int i = blockIdx.x; i < nfb; i += gridDim.x) {
        int rowid = g_fbrow[i];
        int b = rowid >> 11, n = rowid & (Nn - 1);
        const __nv_bfloat16* xh = g_xh + ((size_t)b << 11) * Cc;
        const __nv_bfloat16* xl = g_xl + ((size_t)b << 11) * Cc;
        if (threadIdx.x < Cc)
            xn[threadIdx.x] = __bfloat162float(xh[(size_t)n * Cc + threadIdx.x])
                            + __bfloat162float(xl[(size_t)n * Cc + threadIdx.x]);
        __syncthreads();
        float sqn = g_sq[(b << 11) + n];
#pragma unroll 4
        for (int m0 = wid * 4; m0 < Nn; m0 += 64) {
            int m = m0 + msub;
            const uint4* rh = (const uint4*)(xh + (size_t)m * Cc);
            const uint4* rl = (const uint4*)(xl + (size_t)m * Cc);
            uint4 H0 = rh[cl * 2], H1 = rh[cl * 2 + 1];
            uint4 L0 = rl[cl * 2], L1 = rl[cl * 2 + 1];
            const __nv_bfloat162* h0 = (const __nv_bfloat162*)&H0;
            const __nv_bfloat162* h1 = (const __nv_bfloat162*)&H1;
            const __nv_bfloat162* l0 = (const __nv_bfloat162*)&L0;
            const __nv_bfloat162* l1 = (const __nv_bfloat162*)&L1;
            int c0 = cl * 16;
            float dot = 0.f;
#pragma unroll
            for (int k = 0; k < 4; k++) {
                dot = fmaf(xn[c0 + 2 * k],     __bfloat162float(h0[k].x) + __bfloat162float(l0[k].x), dot);
                dot = fmaf(xn[c0 + 2 * k + 1], __bfloat162float(h0[k].y) + __bfloat162float(l0[k].y), dot);
            }
#pragma unroll
            for (int k = 0; k < 4; k++) {
                dot = fmaf(xn[c0 + 8 + 2 * k],     __bfloat162float(h1[k].x) + __bfloat162float(l1[k].x), dot);
                dot = fmaf(xn[c0 + 8 + 2 * k + 1], __bfloat162float(h1[k].y) + __bfloat162float(l1[k].y), dot);
            }
            dot += __shfl_down_sync(0xffffffffu, dot, 1, 8);
            dot += __shfl_down_sync(0xffffffffu, dot, 2, 8);
            dot += __shfl_down_sync(0xffffffffu, dot, 4, 8);
            if (cl == 0)
                sd[m] = fmaf(-2.f, dot, sqn + g_sq[(b << 11) + m]);
        }
        __syncthreads();
        if (wid < 4) {
            uint64_t lst[16];
#pragma unroll
            for (int ii = 0; ii < 16; ii++) lst[ii] = ~0ull;
#pragma unroll 1
            for (int t = 0; t < 16; t++) {
                int m = wid * 512 + t * 32 + lane;
                uint64_t key = pd_key(sd[m], m);
#pragma unroll
                for (int ii = 0; ii < 16; ii++) {
                    uint64_t bv = lst[ii];
                    uint64_t lo = (key < bv) ? key : bv;
                    key          = (key < bv) ? bv : key;
                    lst[ii] = lo;
                }
            }
            uint64_t cur = lst[0];
#pragma unroll 1
            for (int s = 0; s < KK; s++) {
                uint64_t v = cur;
#pragma unroll
                for (int off = 16; off; off >>= 1) {
                    uint64_t ov = __shfl_down_sync(0xffffffffu, v, off);
                    v = (ov < v) ? ov : v;
                }
                v = __shfl_sync(0xffffffffu, v, 0);
                if (lane == 0) s_cand[wid * KK + s] = v;
                if (cur == v) {
#pragma unroll
                    for (int ii = 0; ii < 15; ii++) lst[ii] = lst[ii + 1];
                    lst[15] = ~0ull;
                    cur = lst[0];
                }
            }
        }
        __syncthreads();
        if (wid == 0) {
            uint64_t a = s_cand[lane];
            uint64_t bb = (lane + 32 < 4 * KK) ? s_cand[lane + 32] : ~0ull;
            uint64_t c = (lane + 64 < 4 * KK) ? s_cand[lane + 64] : ~0ull;
            uint64_t t;
            if (bb < a) { t = a; a = bb; bb = t; }
            if (c < bb) { t = bb; bb = c; c = t; }
            if (bb < a) { t = a; a = bb; bb = t; }
            uint64_t cur = a;
#pragma unroll 1
            for (int s = 0; s < KK; s++) {
                uint64_t v = cur;
#pragma unroll
                for (int off = 16; off; off >>= 1) {
                    uint64_t ov = __shfl_down_sync(0xffffffffu, v, off);
                    v = (ov < v) ? ov : v;
                }
                v = __shfl_sync(0xffffffffu, v, 0);
                if (lane == 0) g_knn[((b << 11) + n) * KK + s] = (int)(uint32_t)v;
                if (cur == v) { a = bb; bb = c; c = ~0ull; cur = a; }
            }
        }
        __syncthreads();
    }
}

// ---------------- uv GEMM (2-CTA skeleton): uv[b][n][j] = x[n,:].Wc[j,:] --------
__global__ __launch_bounds__(256, 2) void k_uv_mma() {
    extern __shared__ char sm[];
    uint32_t sb = smem_u32(sm);
    int tid = threadIdx.x, wid = tid >> 5, lane = tid & 31;
    int strip = blockIdx.x, b = blockIdx.y;
    int n0 = strip * 128;
    const __nv_bfloat16* xh = g_xh + ((size_t)b << 11) * Cc;
    const __nv_bfloat16* xl = g_xl + ((size_t)b << 11) * Cc;

    tile_async(xh + (size_t)n0 * Cc, sb + F2_AH, tid);
    tile_async(xl + (size_t)n0 * Cc, sb + F2_AL, tid);
    tile_async64(g_Wch, sb + F2_BH, tid);
    tile_async64(g_Wcl, sb + F2_BL, tid);
    CP_COMMIT();
    CP_WAIT0();
    __syncthreads();

    int rw = wid * 16, r0 = lane >> 2, q = (lane & 3) * 2;
    float acc[8][4];
#pragma unroll
    for (int g = 0; g < 8; g++)
#pragma unroll
        for (int i = 0; i < 4; i++) acc[g][i] = 0.f;

    uint32_t aoff = (uint32_t)((rw + (lane & 15)) * LDB + (lane >> 4) * 16);
    uint32_t boff = (uint32_t)(((lane & 7) + ((lane >> 4) << 3)) * LDB + ((lane >> 3) & 1) * 16);
    uint32_t a_hi = sb + F2_AH, a_lo = sb + F2_AL;
    uint32_t b_hi = sb + F2_BH, b_lo = sb + F2_BL;
    float* uvb = g_uv + (size_t)(b << 11) * (2 * CO);

#pragma unroll 1
    for (int t = 0; t < 8; t++) {
#pragma unroll
        for (int ks = 0; ks < 8; ks++) {
            uint32_t kb = ks * 32;
            uint32_t ah[4], al[4];
            ldsm4(ah, a_hi + aoff + kb);
            ldsm4(al, a_lo + aoff + kb);
#pragma unroll
            for (int g = 0; g < 4; g++) {
                uint32_t bo = boff + g * (16 * LDB) + kb;
                uint32_t bhx[4], blx[4];
                ldsm4(bhx, b_hi + bo);
                ldsm4(blx, b_lo + bo);
                mma16816(acc[2 * g],     ah, bhx[0], bhx[1]);
                mma16816(acc[2 * g],     ah, blx[0], blx[1]);
                mma16816(acc[2 * g],     al, bhx[0], bhx[1]);
                mma16816(acc[2 * g + 1], ah, bhx[2], bhx[3]);
                mma16816(acc[2 * g + 1], ah, blx[2], blx[3]);
                mma16816(acc[2 * g + 1], al, bhx[2], bhx[3]);
            }
        }
        __syncthreads();
        if (t < 7) {
            tile_async64(g_Wch + (size_t)(t + 1) * 64 * Cc, b_hi, tid);
            tile_async64(g_Wcl + (size_t)(t + 1) * 64 * Cc, b_lo, tid);
            CP_COMMIT();
        }

        int j0 = t * 64;
#pragma unroll
        for (int g = 0; g < 8; g++) {
            int jj = j0 + g * 8 + q;
            int nn = n0 + rw + r0;
            *(float2*)&uvb[(size_t)nn * (2 * CO) + jj] =
                make_float2(acc[g][0], acc[g][1]);
            *(float2*)&uvb[(size_t)(nn + 8) * (2 * CO) + jj] =
                make_float2(acc[g][2], acc[g][3]);
            acc[g][0] = acc[g][1] = acc[g][2] = acc[g][3] = 0.f;
        }
        if (t < 7) {
            CP_WAIT0();
            __syncthreads();
        }
    }
}

// ---------------- gather (float4): y = u + v[knn]; stats + selected extremum ----
#define NT 32
__global__ __launch_bounds__(256) void k_gather() {
    int blk = blockIdx.x;                  // Bb * (Nn/NT) = 1024 blocks
    int b = blk >> 6;
    int n0 = (blk & 63) * NT;
    int tid = threadIdx.x;
    int ty = tid >> 6;                     // 0..3 (n subgroup)
    int ox = tid & 63;                     // channel group: o = ox*4 .. ox*4+3
    const float* uvb = g_uv + (size_t)b * Nn * (2 * CO);
    int gp0 = g_gpos[ox * 4], gp1 = g_gpos[ox * 4 + 1];
    int gp2 = g_gpos[ox * 4 + 2], gp3 = g_gpos[ox * 4 + 3];

    __shared__ int sidx[NT * KK];
    for (int i = tid; i < NT * KK; i += 256)
        sidx[i] = g_knn[((b << 11) + n0) * KK + i];
    __syncthreads();

    float4 s = make_float4(0.f, 0.f, 0.f, 0.f);
    float4 s2 = make_float4(0.f, 0.f, 0.f, 0.f);
#pragma unroll 1
    for (int nn = ty; nn < NT; nn += 4) {
        int n = n0 + nn;
        float4 uo = *(const float4*)&uvb[(size_t)n * (2 * CO) + ox * 4];
        float4 mx = make_float4(-BIGF, -BIGF, -BIGF, -BIGF);
        float4 mn = make_float4(BIGF, BIGF, BIGF, BIGF);
#pragma unroll
        for (int j = 0; j < KK; j++) {
            int m = sidx[nn * KK + j];
            float4 v = *(const float4*)&uvb[(size_t)m * (2 * CO) + CO + ox * 4];
            float y0 = uo.x + v.x, y1 = uo.y + v.y, y2 = uo.z + v.z, y3 = uo.w + v.w;
            s.x += y0; s.y += y1; s.z += y2; s.w += y3;
            s2.x = fmaf(y0, y0, s2.x); s2.y = fmaf(y1, y1, s2.y);
            s2.z = fmaf(y2, y2, s2.z); s2.w = fmaf(y3, y3, s2.w);
            mx.x = fmaxf(mx.x, y0); mx.y = fmaxf(mx.y, y1);
            mx.z = fmaxf(mx.z, y2); mx.w = fmaxf(mx.w, y3);
            mn.x = fminf(mn.x, y0); mn.y = fminf(mn.y, y1);
            mn.z = fminf(mn.z, y2); mn.w = fminf(mn.w, y3);
        }
        float4 sel;
        sel.x = gp0 ? mx.x : mn.x;
        sel.y = gp1 ? mx.y : mn.y;
        sel.z = gp2 ? mx.z : mn.z;
        sel.w = gp3 ? mx.w : mn.w;
        *(float4*)&g_ysel[((size_t)(b << 11) + n) * CO + ox * 4] = sel;
    }
    int bkt = (blk & (NB - 1)) * CO + ox * 4;
    atomicAdd(&g_sum[bkt],     (double)s.x);
    atomicAdd(&g_sum[bkt + 1], (double)s.y);
    atomicAdd(&g_sum[bkt + 2], (double)s.z);
    atomicAdd(&g_sum[bkt + 3], (double)s.w);
    atomicAdd(&g_sumsq[bkt],     (double)s2.x);
    atomicAdd(&g_sumsq[bkt + 1], (double)s2.y);
    atomicAdd(&g_sumsq[bkt + 2], (double)s2.z);
    atomicAdd(&g_sumsq[bkt + 3], (double)s2.w);
}

// ---------------- finalize BN stats ---------------------------------------------
__global__ void k_final(const float* __restrict__ gamma, const float* __restrict__ beta) {
    int o = threadIdx.x;
    double sum = 0.0, sumsq = 0.0;
#pragma unroll
    for (int k = 0; k < NB; k++) { sum += g_sum[k * CO + o]; sumsq += g_sumsq[k * CO + o]; }
    double mean = sum / CNT;
    double var = sumsq / CNT - mean * mean;
    double inv = 1.0 / sqrt(var + 1e-5);
    float sc = (float)((double)gamma[o] * inv);
    g_scale[o] = sc;
    g_shift[o] = beta[o] - (float)(mean * (double)gamma[o] * inv);
}

// ---------------- output: affine + relu + transpose ------------------------------
__global__ void k_out(float* __restrict__ out) {
    __shared__ float tile[32][33];
    int b = blockIdx.z, o0 = blockIdx.y * 32, n0 = blockIdx.x * 32;
    int tx = threadIdx.x, ty = threadIdx.y;

    for (int i = ty; i < 32; i += 8) {
        int n = n0 + i;
        int o = o0 + tx;
        float sc = g_scale[o];
        float v = g_ysel[((size_t)(b << 11) + n) * CO + o];
        float r = fmaf(sc, v, g_shift[o]);
        tile[i][tx] = fmaxf(r, 0.f);
    }
    __syncthreads();
    for (int i = ty; i < 32; i += 8) {
        int o = o0 + i;
        int n = n0 + tx;
        out[((size_t)b * CO + o) * Nn + n] = tile[tx][i];
    }
}

// ---------------- launch ----------------------------------------------------------
extern "C" void kernel_launch(void* const* d_in, const int* in_sizes, int n_in,
                              void* d_out, int out_size) {
    const float* x     = (const float*)d_in[0];
    const float* W     = (const float*)d_in[1];
    const float* gamma = (const float*)d_in[2];
    const float* beta  = (const float*)d_in[3];
    float* out = (float*)d_out;

    static cudaStream_t s2 = nullptr;
    static cudaEvent_t ev1 = nullptr, ev2 = nullptr;
    static int tried = 0;
    if (!tried) {
        tried = 1;
        if (cudaStreamCreateWithFlags(&s2, cudaStreamNonBlocking) != cudaSuccess) s2 = nullptr;
        if (s2) {
            if (cudaEventCreateWithFlags(&ev1, cudaEventDisableTiming) != cudaSuccess ||
                cudaEventCreateWithFlags(&ev2, cudaEventDisableTiming) != cudaSuccess) {
                s2 = nullptr;
            }
        }
    }

    cudaFuncSetAttribute(k_distknn, cudaFuncAttributeMaxDynamicSharedMemorySize, F2_DYN);
    cudaFuncSetAttribute(k_uv_mma,  cudaFuncAttributeMaxDynamicSharedMemorySize, F2_DYN);

    k_prep<<<256, 256>>>(W, gamma);
    k_split<<<dim3(Nn / 32, Bb), dim3(32, 8)>>>(x);

    if (s2) {
        cudaEventRecord(ev1, 0);
        cudaStreamWaitEvent(s2, ev1, 0);
        k_uv_mma<<<dim3(16, Bb), 256, F2_DYN, s2>>>();
        cudaEventRecord(ev2, s2);
        k_distknn<<<dim3(16, Bb), 256, F2_DYN>>>();
        k_fix<<<256, 512>>>();
        cudaStreamWaitEvent(0, ev2, 0);
    } else {
        k_distknn<<<dim3(16, Bb), 256, F2_DYN>>>();
        k_fix<<<256, 512>>>();
        k_uv_mma<<<dim3(16, Bb), 256, F2_DYN>>>();
    }

    k_gather<<<Bb * (Nn / NT), 256>>>();
    k_final<<<1, 256>>>(gamma, beta);
    k_out<<<dim3(Nn / 32, CO / 32, Bb), dim3(32, 8)>>>(out);
}